// round 7
// baseline (speedup 1.0000x reference)
#include <cuda_runtime.h>
#include <cuda_bf16.h>
#include <cuda_fp16.h>
#include <cstdint>

#define NN 50000
#define NE 800000
#define NET (NN + NE)

// ---------------- scratch (static device globals; no allocation) -------------
__device__ float g_h1[NN * 256];      // layer1 pre-attention features fp32
__device__ float g_asrc1[NN * 8];
__device__ float g_adst1[NN * 8];
__device__ float g_h2[NN * 64];
__device__ float g_asrc2[NN];
__device__ float g_adst2[NN];
__device__ float g_expw1[NET * 8];
__device__ float g_expw2[NET];
__device__ int   g_deg[NN];
__device__ int   g_rowptr[NN + 1];
__device__ int   g_pos[NN];
__device__ int   g_ssrc[NET];
__device__ int   g_sdst[NET];
__device__ int   g_is64;

// half/bf16 operands
__device__ unsigned short g_h1h[NN * 256];      // fp16 copy of h1 for gather
__device__ unsigned short g_xhi[NN * 128];
__device__ unsigned short g_xlo[NN * 128];
__device__ unsigned short g_b1catT[256 * 384];  // [n][3K]: hi|hi|lo, K=128
__device__ unsigned short g_h2hi[NN * 256];
__device__ unsigned short g_h2lo[NN * 256];
__device__ unsigned short g_b2catT[64 * 768];   // [n][3K], K=256

__device__ __forceinline__ unsigned short f2bf(float x) {
    __nv_bfloat16 b = __float2bfloat16_rn(x);
    return *(unsigned short*)&b;
}
__device__ __forceinline__ float bf2f(unsigned short u) {
    unsigned int v = ((unsigned int)u) << 16;
    return __uint_as_float(v);
}
__device__ __forceinline__ unsigned short f2h(float x) {
    __half h = __float2half_rn(x);
    return *(unsigned short*)&h;
}
__device__ __forceinline__ float h2f(unsigned short u) {
    __half h = *(__half*)&u;
    return __half2float(h);
}

__device__ __forceinline__ int load_idx(const void* ei, long long pos, int is64) {
    if (is64) return (int)((const long long*)ei)[pos];
    return ((const int*)ei)[pos];
}

// ---------------- zero + dtype detect -----------------------------------------
__global__ void k_zero_detect(const int* __restrict__ w, int n) {
    int i = blockIdx.x * blockDim.x + threadIdx.x;
    if (i < n) g_deg[i] = 0;
    if (blockIdx.x == 0 && threadIdx.x == 0) {
        int all0 = 1;
        for (int j = 1; j < 200; j += 2)
            if (w[j] != 0) { all0 = 0; break; }
        g_is64 = all0;
    }
}

// ---------------- conversions --------------------------------------------------
__global__ void k_conv_x(const float* __restrict__ x, int nf4) {
    int i = blockIdx.x * blockDim.x + threadIdx.x;
    if (i >= nf4) return;
    float4 v = ((const float4*)x)[i];
    ushort4 hi, lo;
    hi.x = f2bf(v.x); lo.x = f2bf(v.x - bf2f(hi.x));
    hi.y = f2bf(v.y); lo.y = f2bf(v.y - bf2f(hi.y));
    hi.z = f2bf(v.z); lo.z = f2bf(v.z - bf2f(hi.z));
    hi.w = f2bf(v.w); lo.w = f2bf(v.w - bf2f(hi.w));
    ((ushort4*)g_xhi)[i] = hi;
    ((ushort4*)g_xlo)[i] = lo;
}

// W1 [128][256] -> b1catT[n][384]; W2 [256][64] -> b2catT[n][768]
__global__ void k_conv_w(const float* __restrict__ W1, const float* __restrict__ W2) {
    int i = blockIdx.x * blockDim.x + threadIdx.x;
    if (i < 32768) {
        int k = i >> 8, nn = i & 255;
        float w = W1[i];
        unsigned short hi = f2bf(w);
        unsigned short lo = f2bf(w - bf2f(hi));
        unsigned short* r = &g_b1catT[nn * 384];
        r[k] = hi; r[128 + k] = hi; r[256 + k] = lo;
    } else if (i < 32768 + 16384) {
        int j = i - 32768;
        int k = j >> 6, nn = j & 63;
        float w = W2[j];
        unsigned short hi = f2bf(w);
        unsigned short lo = f2bf(w - bf2f(hi));
        unsigned short* r = &g_b2catT[nn * 768];
        r[k] = hi; r[256 + k] = hi; r[512 + k] = lo;
    }
}

// ---------------- bf16 split tensor-core GEMM ---------------------------------
__device__ __forceinline__ void mma16816(float* d, const uint32_t* a, const uint32_t* b) {
    asm volatile(
        "mma.sync.aligned.m16n8k16.row.col.f32.bf16.bf16.f32 "
        "{%0,%1,%2,%3}, {%4,%5,%6,%7}, {%8,%9}, {%0,%1,%2,%3};"
        : "+f"(d[0]), "+f"(d[1]), "+f"(d[2]), "+f"(d[3])
        : "r"(a[0]), "r"(a[1]), "r"(a[2]), "r"(a[3]), "r"(b[0]), "r"(b[1]));
}

__global__ void __launch_bounds__(256) k_gemm_bf16(
    const unsigned short* __restrict__ Ahi, const unsigned short* __restrict__ Alo,
    const unsigned short* __restrict__ BcatT, float* __restrict__ C,
    unsigned short* __restrict__ Ch,          // optional fp16 copy of C
    int M, int Nc, int Kp)
{
    __shared__ unsigned short As[128][40];
    __shared__ unsigned short Bs[64][40];
    const int t = threadIdx.x;
    const int wid = t >> 5, lane = t & 31;
    const int gid = lane >> 2, tig = lane & 3;
    const int wm = wid & 3, wn = wid >> 2;
    const int m0 = blockIdx.y * 128, n0 = blockIdx.x * 64;
    const int cpp = Kp >> 5;
    const int nch = 3 * cpp;
    const int K3 = 3 * Kp;

    float acc[2][4][4];
#pragma unroll
    for (int a = 0; a < 2; a++)
#pragma unroll
        for (int b = 0; b < 4; b++)
#pragma unroll
            for (int c = 0; c < 4; c++) acc[a][b][c] = 0.f;

    const int segA = t & 3, rowA = t >> 2;
    const int nB = t >> 2, ksegB = t & 3;

    for (int cc = 0; cc < nch; cc++) {
        int phase = cc / cpp;
        int kloc = (cc - phase * cpp) * 32;
        const unsigned short* Ap = (phase == 1) ? Alo : Ahi;
        __syncthreads();
#pragma unroll
        for (int half = 0; half < 2; half++) {
            int r = rowA + half * 64;
            int m = m0 + r;
            uint4 v = make_uint4(0u, 0u, 0u, 0u);
            if (m < M) v = *(const uint4*)(Ap + (size_t)m * Kp + kloc + segA * 8);
            *(uint4*)&As[r][segA * 8] = v;
        }
        {
            uint4 v = *(const uint4*)(BcatT + (size_t)(n0 + nB) * K3 + cc * 32 + ksegB * 8);
            *(uint4*)&Bs[nB][ksegB * 8] = v;
        }
        __syncthreads();
#pragma unroll
        for (int ks = 0; ks < 32; ks += 16) {
            uint32_t af[2][4];
#pragma unroll
            for (int mt = 0; mt < 2; mt++) {
                int rb = wm * 32 + mt * 16 + gid;
                af[mt][0] = *(const uint32_t*)&As[rb][ks + tig * 2];
                af[mt][1] = *(const uint32_t*)&As[rb + 8][ks + tig * 2];
                af[mt][2] = *(const uint32_t*)&As[rb][ks + tig * 2 + 8];
                af[mt][3] = *(const uint32_t*)&As[rb + 8][ks + tig * 2 + 8];
            }
            uint32_t bfr[4][2];
#pragma unroll
            for (int nt = 0; nt < 4; nt++) {
                int nb = wn * 32 + nt * 8 + gid;
                bfr[nt][0] = *(const uint32_t*)&Bs[nb][ks + tig * 2];
                bfr[nt][1] = *(const uint32_t*)&Bs[nb][ks + tig * 2 + 8];
            }
#pragma unroll
            for (int mt = 0; mt < 2; mt++)
#pragma unroll
                for (int nt = 0; nt < 4; nt++)
                    mma16816(acc[mt][nt], af[mt], bfr[nt]);
        }
    }
#pragma unroll
    for (int mt = 0; mt < 2; mt++) {
#pragma unroll
        for (int nt = 0; nt < 4; nt++) {
            int row = m0 + wm * 32 + mt * 16 + gid;
            int col = n0 + wn * 32 + nt * 8 + tig * 2;
            if (row < M) {
                *(float2*)&C[(size_t)row * Nc + col] = make_float2(acc[mt][nt][0], acc[mt][nt][1]);
                if (Ch) {
                    uint32_t pk = ((uint32_t)f2h(acc[mt][nt][1]) << 16) | f2h(acc[mt][nt][0]);
                    *(uint32_t*)&Ch[(size_t)row * Nc + col] = pk;
                }
            }
            if (row + 8 < M) {
                *(float2*)&C[(size_t)(row + 8) * Nc + col] = make_float2(acc[mt][nt][2], acc[mt][nt][3]);
                if (Ch) {
                    uint32_t pk = ((uint32_t)f2h(acc[mt][nt][3]) << 16) | f2h(acc[mt][nt][2]);
                    *(uint32_t*)&Ch[(size_t)(row + 8) * Nc + col] = pk;
                }
            }
        }
    }
}

// ---------------- layer1 attention logits: warp per node ----------------------
__global__ void __launch_bounds__(256) k_att1(const float* __restrict__ att_src,
                                              const float* __restrict__ att_dst, int n)
{
    int warp = (blockIdx.x * blockDim.x + threadIdx.x) >> 5;
    int lane = threadIdx.x & 31;
    if (warp >= n) return;
    float wsrc[8], wdst[8];
#pragma unroll
    for (int h = 0; h < 8; h++) {
        wsrc[h] = att_src[h * 32 + lane];
        wdst[h] = att_dst[h * 32 + lane];
    }
    const float* hp = &g_h1[warp * 256];
    float sa = 0.f, sd = 0.f;
#pragma unroll
    for (int h = 0; h < 8; h++) {
        float v = hp[h * 32 + lane];
        float p1 = v * wsrc[h];
        float p2 = v * wdst[h];
#pragma unroll
        for (int o = 16; o; o >>= 1) {
            p1 += __shfl_xor_sync(0xffffffffu, p1, o);
            p2 += __shfl_xor_sync(0xffffffffu, p2, o);
        }
        if (lane == h) { sa = p1; sd = p2; }
    }
    if (lane < 8) {
        g_asrc1[warp * 8 + lane] = sa;
        g_adst1[warp * 8 + lane] = sd;
    }
}

// ---------------- CSR build ---------------------------------------------------
__global__ void k_count(const void* __restrict__ ei, int e, int n) {
    int i = blockIdx.x * blockDim.x + threadIdx.x;
    if (i >= e + n) return;
    int is64 = g_is64;
    int d = (i < e) ? load_idx(ei, (long long)e + i, is64) : (i - e);
    atomicAdd(&g_deg[d], 1);
}

__global__ void __launch_bounds__(1024) k_scan(int n) {
    const int CH = 49;
    int t = threadIdx.x;
    int base = t * CH;
    int s = 0;
    for (int i = 0; i < CH; i++) { int idx = base + i; if (idx < n) s += g_deg[idx]; }
    int lane = t & 31, wid = t >> 5;
    int v = s;
#pragma unroll
    for (int o = 1; o < 32; o <<= 1) {
        int u = __shfl_up_sync(0xffffffffu, v, o);
        if (lane >= o) v += u;
    }
    __shared__ int ws[32];
    if (lane == 31) ws[wid] = v;
    __syncthreads();
    if (wid == 0) {
        int w = ws[lane];
#pragma unroll
        for (int o = 1; o < 32; o <<= 1) {
            int u = __shfl_up_sync(0xffffffffu, w, o);
            if (lane >= o) w += u;
        }
        ws[lane] = w;
    }
    __syncthreads();
    int excl = v - s + (wid > 0 ? ws[wid - 1] : 0);
    int run = excl;
    for (int i = 0; i < CH; i++) {
        int idx = base + i;
        if (idx < n) { g_rowptr[idx] = run; g_pos[idx] = run; run += g_deg[idx]; }
    }
    if (t == 1023) g_rowptr[n] = excl;
}

// ---------------- scatter + layer1 softmax numerators (fused) -----------------
__global__ void k_scatter_exp1(const void* __restrict__ ei, int e, int n) {
    int i = blockIdx.x * blockDim.x + threadIdx.x;
    if (i >= e + n) return;
    int is64 = g_is64;
    int s, d;
    if (i < e) { s = load_idx(ei, i, is64); d = load_idx(ei, (long long)e + i, is64); }
    else       { s = i - e;                 d = i - e; }
    int p = atomicAdd(&g_pos[d], 1);
    g_ssrc[p] = s;
    g_sdst[p] = d;
    const float4* AS = (const float4*)g_asrc1;
    const float4* AD = (const float4*)g_adst1;
    float4 a0 = AS[s * 2], a1 = AS[s * 2 + 1];
    float4 d0 = AD[d * 2], d1 = AD[d * 2 + 1];
    float4 r0, r1;
    float e0;
    e0 = a0.x + d0.x; e0 = e0 > 0.f ? e0 : 0.2f * e0; r0.x = __expf(e0);
    e0 = a0.y + d0.y; e0 = e0 > 0.f ? e0 : 0.2f * e0; r0.y = __expf(e0);
    e0 = a0.z + d0.z; e0 = e0 > 0.f ? e0 : 0.2f * e0; r0.z = __expf(e0);
    e0 = a0.w + d0.w; e0 = e0 > 0.f ? e0 : 0.2f * e0; r0.w = __expf(e0);
    e0 = a1.x + d1.x; e0 = e0 > 0.f ? e0 : 0.2f * e0; r1.x = __expf(e0);
    e0 = a1.y + d1.y; e0 = e0 > 0.f ? e0 : 0.2f * e0; r1.y = __expf(e0);
    e0 = a1.z + d1.z; e0 = e0 > 0.f ? e0 : 0.2f * e0; r1.z = __expf(e0);
    e0 = a1.w + d1.w; e0 = e0 > 0.f ? e0 : 0.2f * e0; r1.w = __expf(e0);
    float4* EX = (float4*)g_expw1;
    EX[p * 2] = r0; EX[p * 2 + 1] = r1;
}

// ---------------- layer1 aggregation (fp16 gather) + bias + ELU -> bf16 split --
__global__ void __launch_bounds__(256) k_agg1(const float* __restrict__ bias1) {
    int t = threadIdx.x;
    int u = t & 63;
    int d = blockIdx.x * 4 + (t >> 6);
    int h = u >> 3;
    int r0 = g_rowptr[d], r1 = g_rowptr[d + 1];
    const ushort4* Hh = (const ushort4*)g_h1h;
    float4 acc = make_float4(0.f, 0.f, 0.f, 0.f);
    float wsum = 0.f;
    int p = r0;
    for (; p + 2 <= r1; p += 2) {
        int s0 = g_ssrc[p],     s1 = g_ssrc[p + 1];
        float w0 = g_expw1[p * 8 + h], w1 = g_expw1[(p + 1) * 8 + h];
        ushort4 v0 = Hh[s0 * 64 + u];
        ushort4 v1 = Hh[s1 * 64 + u];
        acc.x += w0 * h2f(v0.x) + w1 * h2f(v1.x);
        acc.y += w0 * h2f(v0.y) + w1 * h2f(v1.y);
        acc.z += w0 * h2f(v0.z) + w1 * h2f(v1.z);
        acc.w += w0 * h2f(v0.w) + w1 * h2f(v1.w);
        wsum += w0 + w1;
    }
    if (p < r1) {
        int s0 = g_ssrc[p];
        float w0 = g_expw1[p * 8 + h];
        ushort4 v0 = Hh[s0 * 64 + u];
        acc.x += w0 * h2f(v0.x); acc.y += w0 * h2f(v0.y);
        acc.z += w0 * h2f(v0.z); acc.w += w0 * h2f(v0.w);
        wsum += w0;
    }
    float sinv = 1.f / (wsum + 1e-16f);
    float4 b = ((const float4*)bias1)[u];
    float4 o;
    o.x = acc.x * sinv + b.x; o.x = o.x > 0.f ? o.x : expm1f(o.x);
    o.y = acc.y * sinv + b.y; o.y = o.y > 0.f ? o.y : expm1f(o.y);
    o.z = acc.z * sinv + b.z; o.z = o.z > 0.f ? o.z : expm1f(o.z);
    o.w = acc.w * sinv + b.w; o.w = o.w > 0.f ? o.w : expm1f(o.w);
    ushort4 hi, lo;
    hi.x = f2bf(o.x); lo.x = f2bf(o.x - bf2f(hi.x));
    hi.y = f2bf(o.y); lo.y = f2bf(o.y - bf2f(hi.y));
    hi.z = f2bf(o.z); lo.z = f2bf(o.z - bf2f(hi.z));
    hi.w = f2bf(o.w); lo.w = f2bf(o.w - bf2f(hi.w));
    ((ushort4*)g_h2hi)[d * 64 + u] = hi;
    ((ushort4*)g_h2lo)[d * 64 + u] = lo;
}

// ---------------- layer2 attention logits (warp per node) ---------------------
__global__ void k_att2(const float* __restrict__ as2,
                       const float* __restrict__ ad2, int n)
{
    int w = (blockIdx.x * blockDim.x + threadIdx.x) >> 5;
    int lane = threadIdx.x & 31;
    if (w >= n) return;
    float v0 = g_h2[w * 64 + lane], v1 = g_h2[w * 64 + 32 + lane];
    float sa = v0 * as2[lane] + v1 * as2[32 + lane];
    float sd = v0 * ad2[lane] + v1 * ad2[32 + lane];
#pragma unroll
    for (int o = 16; o; o >>= 1) {
        sa += __shfl_xor_sync(0xffffffffu, sa, o);
        sd += __shfl_xor_sync(0xffffffffu, sd, o);
    }
    if (lane == 0) { g_asrc2[w] = sa; g_adst2[w] = sd; }
}

__global__ void k_exp2(int et) {
    int p = blockIdx.x * blockDim.x + threadIdx.x;
    if (p >= et) return;
    int s = g_ssrc[p], d = g_sdst[p];
    float ev = g_asrc2[s] + g_adst2[d];
    ev = ev > 0.f ? ev : 0.2f * ev;
    g_expw2[p] = __expf(ev);
}

// ---------------- layer2 aggregation + bias -> output -------------------------
__global__ void __launch_bounds__(256) k_agg2(const float* __restrict__ bias2,
                                              float* __restrict__ out)
{
    int t = threadIdx.x;
    int u = t & 15;
    int d = blockIdx.x * 16 + (t >> 4);
    int r0 = g_rowptr[d], r1 = g_rowptr[d + 1];
    const float4* H = (const float4*)g_h2;
    float4 acc = make_float4(0.f, 0.f, 0.f, 0.f);
    float wsum = 0.f;
    int p = r0;
    for (; p + 2 <= r1; p += 2) {
        int s0 = g_ssrc[p], s1 = g_ssrc[p + 1];
        float w0 = g_expw2[p], w1 = g_expw2[p + 1];
        float4 v0 = H[s0 * 16 + u];
        float4 v1 = H[s1 * 16 + u];
        acc.x += w0 * v0.x + w1 * v1.x;
        acc.y += w0 * v0.y + w1 * v1.y;
        acc.z += w0 * v0.z + w1 * v1.z;
        acc.w += w0 * v0.w + w1 * v1.w;
        wsum += w0 + w1;
    }
    if (p < r1) {
        int s0 = g_ssrc[p];
        float w0 = g_expw2[p];
        float4 v0 = H[s0 * 16 + u];
        acc.x += w0 * v0.x; acc.y += w0 * v0.y;
        acc.z += w0 * v0.z; acc.w += w0 * v0.w;
        wsum += w0;
    }
    float sinv = 1.f / (wsum + 1e-16f);
    float4 b = ((const float4*)bias2)[u];
    float4 o;
    o.x = acc.x * sinv + b.x;
    o.y = acc.y * sinv + b.y;
    o.z = acc.z * sinv + b.z;
    o.w = acc.w * sinv + b.w;
    ((float4*)out)[d * 16 + u] = o;
}

// ------------------------------------------------------------------------------
extern "C" void kernel_launch(void* const* d_in, const int* in_sizes, int n_in,
                              void* d_out, int out_size)
{
    const float* x   = (const float*)d_in[0];
    const void*  ei  = d_in[1];
    const float* W1  = (const float*)d_in[3];
    const float* as1 = (const float*)d_in[4];
    const float* ad1 = (const float*)d_in[5];
    const float* b1  = (const float*)d_in[6];
    const float* W2  = (const float*)d_in[7];
    const float* as2 = (const float*)d_in[8];
    const float* ad2 = (const float*)d_in[9];
    const float* b2  = (const float*)d_in[10];
    float* out = (float*)d_out;

    const int n  = in_sizes[0] / 128;   // 50000
    const int e  = in_sizes[1] / 2;     // 800000
    const int et = e + n;

    float *h1, *h2;
    unsigned short *h1h, *xhi, *xlo, *b1catT, *h2hi, *h2lo, *b2catT;
    cudaGetSymbolAddress((void**)&h1,     g_h1);
    cudaGetSymbolAddress((void**)&h2,     g_h2);
    cudaGetSymbolAddress((void**)&h1h,    g_h1h);
    cudaGetSymbolAddress((void**)&xhi,    g_xhi);
    cudaGetSymbolAddress((void**)&xlo,    g_xlo);
    cudaGetSymbolAddress((void**)&b1catT, g_b1catT);
    cudaGetSymbolAddress((void**)&h2hi,   g_h2hi);
    cudaGetSymbolAddress((void**)&h2lo,   g_h2lo);
    cudaGetSymbolAddress((void**)&b2catT, g_b2catT);

    k_zero_detect<<<(n + 255) / 256, 256>>>((const int*)ei, n);

    int nf4 = n * 32;
    k_conv_x<<<(nf4 + 255) / 256, 256>>>(x, nf4);
    k_conv_w<<<(49152 + 255) / 256, 256>>>(W1, W2);

    // layer1 GEMM: h1 = x @ W1 (fp32 + fp16 copy)
    k_gemm_bf16<<<dim3(4, (n + 127) / 128), 256>>>(xhi, xlo, b1catT, h1, h1h, n, 256, 128);

    k_att1<<<(n * 32 + 255) / 256, 256>>>(as1, ad1, n);

    // CSR build + fused layer1 softmax numerators
    k_count<<<(et + 255) / 256, 256>>>(ei, e, n);
    k_scan<<<1, 1024>>>(n);
    k_scatter_exp1<<<(et + 255) / 256, 256>>>(ei, e, n);

    k_agg1<<<(n + 3) / 4, 256>>>(b1);

    // layer2 GEMM: h2 = elu_out @ W2
    k_gemm_bf16<<<dim3(1, (n + 127) / 128), 256>>>(h2hi, h2lo, b2catT, h2, (unsigned short*)nullptr, n, 64, 256);

    k_att2<<<(n * 32 + 255) / 256, 256>>>(as2, ad2, n);
    k_exp2<<<(et + 255) / 256, 256>>>(et);
    k_agg2<<<(n + 15) / 16, 256>>>(b2, out);
}

// round 8
// speedup vs baseline: 1.5199x; 1.5199x over previous
#include <cuda_runtime.h>
#include <cuda_bf16.h>
#include <cuda_fp16.h>
#include <cstdint>

#define NN 50000
#define NE 800000
#define NET (NN + NE)

// ---------------- scratch (static device globals; no allocation) -------------
__device__ float g_h1[NN * 256];
__device__ float g_asrc1[NN * 8];
__device__ float g_adst1[NN * 8];
__device__ float g_h2[NN * 64];
__device__ float g_asrc2[NN];
__device__ float g_adst2[NN];
__device__ float g_expw1[NET * 8];
__device__ float g_expw2[NET];
__device__ int   g_deg[NN];
__device__ int   g_rowptr[NN + 1];
__device__ int   g_pos[NN];
__device__ int   g_ssrc[NET];
__device__ int   g_sdst[NET];
__device__ int   g_is64;

// half/bf16 operands
__device__ unsigned short g_h1h[NN * 256];      // fp16 copy of h1 for gather
__device__ unsigned short g_xhi[NN * 128];
__device__ unsigned short g_xlo[NN * 128];
__device__ unsigned short g_b1catT[256 * 384];  // [n][3K]: hi|hi|lo, K=128
__device__ unsigned short g_h2hi[NN * 256];
__device__ unsigned short g_h2lo[NN * 256];
__device__ unsigned short g_b2catT[64 * 768];   // [n][3K], K=256

__device__ __forceinline__ unsigned short f2bf(float x) {
    __nv_bfloat16 b = __float2bfloat16_rn(x);
    return *(unsigned short*)&b;
}
__device__ __forceinline__ float bf2f(unsigned short u) {
    unsigned int v = ((unsigned int)u) << 16;
    return __uint_as_float(v);
}
__device__ __forceinline__ unsigned short f2h(float x) {
    __half h = __float2half_rn(x);
    return *(unsigned short*)&h;
}
__device__ __forceinline__ float h2f(unsigned short u) {
    __half h = *(__half*)&u;
    return __half2float(h);
}

__device__ __forceinline__ int load_idx(const void* ei, long long pos, int is64) {
    if (is64) return (int)((const long long*)ei)[pos];
    return ((const int*)ei)[pos];
}

// ---------------- zero + dtype detect -----------------------------------------
__global__ void k_zero_detect(const int* __restrict__ w, int n) {
    int i = blockIdx.x * blockDim.x + threadIdx.x;
    if (i < n) g_deg[i] = 0;
    if (blockIdx.x == 0 && threadIdx.x == 0) {
        int all0 = 1;
        for (int j = 1; j < 200; j += 2)
            if (w[j] != 0) { all0 = 0; break; }
        g_is64 = all0;
    }
}

// ---------------- conversions --------------------------------------------------
__global__ void k_conv_x(const float* __restrict__ x, int nf4) {
    int i = blockIdx.x * blockDim.x + threadIdx.x;
    if (i >= nf4) return;
    float4 v = ((const float4*)x)[i];
    ushort4 hi, lo;
    hi.x = f2bf(v.x); lo.x = f2bf(v.x - bf2f(hi.x));
    hi.y = f2bf(v.y); lo.y = f2bf(v.y - bf2f(hi.y));
    hi.z = f2bf(v.z); lo.z = f2bf(v.z - bf2f(hi.z));
    hi.w = f2bf(v.w); lo.w = f2bf(v.w - bf2f(hi.w));
    ((ushort4*)g_xhi)[i] = hi;
    ((ushort4*)g_xlo)[i] = lo;
}

__global__ void k_conv_w(const float* __restrict__ W1, const float* __restrict__ W2) {
    int i = blockIdx.x * blockDim.x + threadIdx.x;
    if (i < 32768) {
        int k = i >> 8, nn = i & 255;
        float w = W1[i];
        unsigned short hi = f2bf(w);
        unsigned short lo = f2bf(w - bf2f(hi));
        unsigned short* r = &g_b1catT[nn * 384];
        r[k] = hi; r[128 + k] = hi; r[256 + k] = lo;
    } else if (i < 32768 + 16384) {
        int j = i - 32768;
        int k = j >> 6, nn = j & 63;
        float w = W2[j];
        unsigned short hi = f2bf(w);
        unsigned short lo = f2bf(w - bf2f(hi));
        unsigned short* r = &g_b2catT[nn * 768];
        r[k] = hi; r[256 + k] = hi; r[512 + k] = lo;
    }
}

// ---------------- bf16 split tensor-core GEMM (ldmatrix fragments) ------------
__device__ __forceinline__ void mma16816(float* d, const uint32_t* a, const uint32_t* b) {
    asm volatile(
        "mma.sync.aligned.m16n8k16.row.col.f32.bf16.bf16.f32 "
        "{%0,%1,%2,%3}, {%4,%5,%6,%7}, {%8,%9}, {%0,%1,%2,%3};"
        : "+f"(d[0]), "+f"(d[1]), "+f"(d[2]), "+f"(d[3])
        : "r"(a[0]), "r"(a[1]), "r"(a[2]), "r"(a[3]), "r"(b[0]), "r"(b[1]));
}

__device__ __forceinline__ void ldsm_x4(uint32_t& r0, uint32_t& r1, uint32_t& r2, uint32_t& r3, uint32_t addr) {
    asm volatile("ldmatrix.sync.aligned.m8n8.x4.shared.b16 {%0,%1,%2,%3}, [%4];"
                 : "=r"(r0), "=r"(r1), "=r"(r2), "=r"(r3) : "r"(addr));
}

__global__ void __launch_bounds__(256) k_gemm_bf16(
    const unsigned short* __restrict__ Ahi, const unsigned short* __restrict__ Alo,
    const unsigned short* __restrict__ BcatT, float* __restrict__ C,
    unsigned short* __restrict__ Ch, int M, int Nc, int Kp)
{
    __shared__ unsigned short As[128][40];   // 80B row stride: LDSM phase hits 32 banks
    __shared__ unsigned short Bs[64][40];
    const int t = threadIdx.x;
    const int wid = t >> 5, lane = t & 31;
    const int gid = lane >> 2, tig = lane & 3;
    const int wm = wid & 3, wn = wid >> 2;
    const int m0 = blockIdx.y * 128, n0 = blockIdx.x * 64;
    const int cpp = Kp >> 5;
    const int nch = 3 * cpp;
    const int K3 = 3 * Kp;

    const int lr = lane & 7, lg = lane >> 3;
    const uint32_t sA = (uint32_t)__cvta_generic_to_shared(&As[0][0]);
    const uint32_t sB = (uint32_t)__cvta_generic_to_shared(&Bs[0][0]);

    float acc[2][4][4];
#pragma unroll
    for (int a = 0; a < 2; a++)
#pragma unroll
        for (int b = 0; b < 4; b++)
#pragma unroll
            for (int c = 0; c < 4; c++) acc[a][b][c] = 0.f;

    const int segA = t & 3, rowA = t >> 2;
    const int nB = t >> 2, ksegB = t & 3;

    for (int cc = 0; cc < nch; cc++) {
        int phase = cc / cpp;
        int kloc = (cc - phase * cpp) * 32;
        const unsigned short* Ap = (phase == 1) ? Alo : Ahi;
        __syncthreads();
#pragma unroll
        for (int half = 0; half < 2; half++) {
            int r = rowA + half * 64;
            int m = m0 + r;
            uint4 v = make_uint4(0u, 0u, 0u, 0u);
            if (m < M) v = *(const uint4*)(Ap + (size_t)m * Kp + kloc + segA * 8);
            *(uint4*)&As[r][segA * 8] = v;
        }
        {
            uint4 v = *(const uint4*)(BcatT + (size_t)(n0 + nB) * K3 + cc * 32 + ksegB * 8);
            *(uint4*)&Bs[nB][ksegB * 8] = v;
        }
        __syncthreads();
#pragma unroll
        for (int ks = 0; ks < 32; ks += 16) {
            uint32_t af[2][4];
#pragma unroll
            for (int mt = 0; mt < 2; mt++) {
                // M0: rows rb+lr k=ks | M1: rows rb+8+lr k=ks | M2: rows rb+lr k=ks+8 | M3: rows rb+8+lr k=ks+8
                int row = wm * 32 + mt * 16 + (lg & 1) * 8 + lr;
                int col = ks + (lg >> 1) * 8;
                ldsm_x4(af[mt][0], af[mt][1], af[mt][2], af[mt][3],
                        sA + (uint32_t)(row * 40 + col) * 2u);
            }
            uint32_t bfr[4][2];
#pragma unroll
            for (int p2 = 0; p2 < 2; p2++) {
                // M0: n rows nt(2p2) k=ks | M1: same n, k=ks+8 | M2: nt(2p2+1) k=ks | M3: nt(2p2+1) k=ks+8
                int row = wn * 32 + p2 * 16 + (lg >> 1) * 8 + lr;
                int col = ks + (lg & 1) * 8;
                ldsm_x4(bfr[p2 * 2][0], bfr[p2 * 2][1], bfr[p2 * 2 + 1][0], bfr[p2 * 2 + 1][1],
                        sB + (uint32_t)(row * 40 + col) * 2u);
            }
#pragma unroll
            for (int mt = 0; mt < 2; mt++)
#pragma unroll
                for (int nt = 0; nt < 4; nt++)
                    mma16816(acc[mt][nt], af[mt], bfr[nt]);
        }
    }
#pragma unroll
    for (int mt = 0; mt < 2; mt++) {
#pragma unroll
        for (int nt = 0; nt < 4; nt++) {
            int row = m0 + wm * 32 + mt * 16 + gid;
            int col = n0 + wn * 32 + nt * 8 + tig * 2;
            if (row < M) {
                *(float2*)&C[(size_t)row * Nc + col] = make_float2(acc[mt][nt][0], acc[mt][nt][1]);
                if (Ch) {
                    uint32_t pk = ((uint32_t)f2h(acc[mt][nt][1]) << 16) | f2h(acc[mt][nt][0]);
                    *(uint32_t*)&Ch[(size_t)row * Nc + col] = pk;
                }
            }
            if (row + 8 < M) {
                *(float2*)&C[(size_t)(row + 8) * Nc + col] = make_float2(acc[mt][nt][2], acc[mt][nt][3]);
                if (Ch) {
                    uint32_t pk = ((uint32_t)f2h(acc[mt][nt][3]) << 16) | f2h(acc[mt][nt][2]);
                    *(uint32_t*)&Ch[(size_t)(row + 8) * Nc + col] = pk;
                }
            }
        }
    }
}

// ---------------- layer1 attention logits: warp per node ----------------------
__global__ void __launch_bounds__(256) k_att1(const float* __restrict__ att_src,
                                              const float* __restrict__ att_dst, int n)
{
    int warp = (blockIdx.x * blockDim.x + threadIdx.x) >> 5;
    int lane = threadIdx.x & 31;
    if (warp >= n) return;
    float wsrc[8], wdst[8];
#pragma unroll
    for (int h = 0; h < 8; h++) {
        wsrc[h] = att_src[h * 32 + lane];
        wdst[h] = att_dst[h * 32 + lane];
    }
    const float* hp = &g_h1[warp * 256];
    float sa = 0.f, sd = 0.f;
#pragma unroll
    for (int h = 0; h < 8; h++) {
        float v = hp[h * 32 + lane];
        float p1 = v * wsrc[h];
        float p2 = v * wdst[h];
#pragma unroll
        for (int o = 16; o; o >>= 1) {
            p1 += __shfl_xor_sync(0xffffffffu, p1, o);
            p2 += __shfl_xor_sync(0xffffffffu, p2, o);
        }
        if (lane == h) { sa = p1; sd = p2; }
    }
    if (lane < 8) {
        g_asrc1[warp * 8 + lane] = sa;
        g_adst1[warp * 8 + lane] = sd;
    }
}

// ---------------- CSR build ---------------------------------------------------
__global__ void k_count(const void* __restrict__ ei, int e, int n) {
    int i = blockIdx.x * blockDim.x + threadIdx.x;
    if (i >= e + n) return;
    int is64 = g_is64;
    int d = (i < e) ? load_idx(ei, (long long)e + i, is64) : (i - e);
    atomicAdd(&g_deg[d], 1);
}

__global__ void __launch_bounds__(1024) k_scan(int n) {
    const int CH = 49;
    int t = threadIdx.x;
    int base = t * CH;
    int s = 0;
    for (int i = 0; i < CH; i++) { int idx = base + i; if (idx < n) s += g_deg[idx]; }
    int lane = t & 31, wid = t >> 5;
    int v = s;
#pragma unroll
    for (int o = 1; o < 32; o <<= 1) {
        int u = __shfl_up_sync(0xffffffffu, v, o);
        if (lane >= o) v += u;
    }
    __shared__ int ws[32];
    if (lane == 31) ws[wid] = v;
    __syncthreads();
    if (wid == 0) {
        int w = ws[lane];
#pragma unroll
        for (int o = 1; o < 32; o <<= 1) {
            int u = __shfl_up_sync(0xffffffffu, w, o);
            if (lane >= o) w += u;
        }
        ws[lane] = w;
    }
    __syncthreads();
    int excl = v - s + (wid > 0 ? ws[wid - 1] : 0);
    int run = excl;
    for (int i = 0; i < CH; i++) {
        int idx = base + i;
        if (idx < n) { g_rowptr[idx] = run; g_pos[idx] = run; run += g_deg[idx]; }
    }
    if (t == 1023) g_rowptr[n] = excl;
}

__global__ void k_scatter(const void* __restrict__ ei, int e, int n) {
    int i = blockIdx.x * blockDim.x + threadIdx.x;
    if (i >= e + n) return;
    int is64 = g_is64;
    int s, d;
    if (i < e) { s = load_idx(ei, i, is64); d = load_idx(ei, (long long)e + i, is64); }
    else       { s = i - e;                 d = i - e; }
    int p = atomicAdd(&g_pos[d], 1);
    g_ssrc[p] = s;
    g_sdst[p] = d;
}

// ---------------- layer1 softmax numerators (sequential p, coalesced writes) --
__global__ void k_exp1(int et) {
    int p = blockIdx.x * blockDim.x + threadIdx.x;
    if (p >= et) return;
    int s = g_ssrc[p], d = g_sdst[p];
    const float4* AS = (const float4*)g_asrc1;
    const float4* AD = (const float4*)g_adst1;
    float4 a0 = AS[s * 2], a1 = AS[s * 2 + 1];
    float4 d0 = AD[d * 2], d1 = AD[d * 2 + 1];
    float4 r0, r1;
    float e0;
    e0 = a0.x + d0.x; e0 = e0 > 0.f ? e0 : 0.2f * e0; r0.x = __expf(e0);
    e0 = a0.y + d0.y; e0 = e0 > 0.f ? e0 : 0.2f * e0; r0.y = __expf(e0);
    e0 = a0.z + d0.z; e0 = e0 > 0.f ? e0 : 0.2f * e0; r0.z = __expf(e0);
    e0 = a0.w + d0.w; e0 = e0 > 0.f ? e0 : 0.2f * e0; r0.w = __expf(e0);
    e0 = a1.x + d1.x; e0 = e0 > 0.f ? e0 : 0.2f * e0; r1.x = __expf(e0);
    e0 = a1.y + d1.y; e0 = e0 > 0.f ? e0 : 0.2f * e0; r1.y = __expf(e0);
    e0 = a1.z + d1.z; e0 = e0 > 0.f ? e0 : 0.2f * e0; r1.z = __expf(e0);
    e0 = a1.w + d1.w; e0 = e0 > 0.f ? e0 : 0.2f * e0; r1.w = __expf(e0);
    float4* EX = (float4*)g_expw1;
    EX[p * 2] = r0; EX[p * 2 + 1] = r1;
}

// ---------------- layer1 aggregation (fp16 gather) + bias + ELU -> bf16 split --
__global__ void __launch_bounds__(256) k_agg1(const float* __restrict__ bias1) {
    int t = threadIdx.x;
    int u = t & 63;
    int d = blockIdx.x * 4 + (t >> 6);
    int h = u >> 3;
    int r0 = g_rowptr[d], r1 = g_rowptr[d + 1];
    const ushort4* Hh = (const ushort4*)g_h1h;
    float4 acc = make_float4(0.f, 0.f, 0.f, 0.f);
    float wsum = 0.f;
    int p = r0;
    for (; p + 2 <= r1; p += 2) {
        int s0 = g_ssrc[p],     s1 = g_ssrc[p + 1];
        float w0 = g_expw1[p * 8 + h], w1 = g_expw1[(p + 1) * 8 + h];
        ushort4 v0 = Hh[s0 * 64 + u];
        ushort4 v1 = Hh[s1 * 64 + u];
        acc.x += w0 * h2f(v0.x) + w1 * h2f(v1.x);
        acc.y += w0 * h2f(v0.y) + w1 * h2f(v1.y);
        acc.z += w0 * h2f(v0.z) + w1 * h2f(v1.z);
        acc.w += w0 * h2f(v0.w) + w1 * h2f(v1.w);
        wsum += w0 + w1;
    }
    if (p < r1) {
        int s0 = g_ssrc[p];
        float w0 = g_expw1[p * 8 + h];
        ushort4 v0 = Hh[s0 * 64 + u];
        acc.x += w0 * h2f(v0.x); acc.y += w0 * h2f(v0.y);
        acc.z += w0 * h2f(v0.z); acc.w += w0 * h2f(v0.w);
        wsum += w0;
    }
    float sinv = 1.f / (wsum + 1e-16f);
    float4 b = ((const float4*)bias1)[u];
    float4 o;
    o.x = acc.x * sinv + b.x; o.x = o.x > 0.f ? o.x : expm1f(o.x);
    o.y = acc.y * sinv + b.y; o.y = o.y > 0.f ? o.y : expm1f(o.y);
    o.z = acc.z * sinv + b.z; o.z = o.z > 0.f ? o.z : expm1f(o.z);
    o.w = acc.w * sinv + b.w; o.w = o.w > 0.f ? o.w : expm1f(o.w);
    ushort4 hi, lo;
    hi.x = f2bf(o.x); lo.x = f2bf(o.x - bf2f(hi.x));
    hi.y = f2bf(o.y); lo.y = f2bf(o.y - bf2f(hi.y));
    hi.z = f2bf(o.z); lo.z = f2bf(o.z - bf2f(hi.z));
    hi.w = f2bf(o.w); lo.w = f2bf(o.w - bf2f(hi.w));
    ((ushort4*)g_h2hi)[d * 64 + u] = hi;
    ((ushort4*)g_h2lo)[d * 64 + u] = lo;
}

// ---------------- layer2 attention logits (warp per node) ---------------------
__global__ void k_att2(const float* __restrict__ as2,
                       const float* __restrict__ ad2, int n)
{
    int w = (blockIdx.x * blockDim.x + threadIdx.x) >> 5;
    int lane = threadIdx.x & 31;
    if (w >= n) return;
    float v0 = g_h2[w * 64 + lane], v1 = g_h2[w * 64 + 32 + lane];
    float sa = v0 * as2[lane] + v1 * as2[32 + lane];
    float sd = v0 * ad2[lane] + v1 * ad2[32 + lane];
#pragma unroll
    for (int o = 16; o; o >>= 1) {
        sa += __shfl_xor_sync(0xffffffffu, sa, o);
        sd += __shfl_xor_sync(0xffffffffu, sd, o);
    }
    if (lane == 0) { g_asrc2[w] = sa; g_adst2[w] = sd; }
}

__global__ void k_exp2(int et) {
    int p = blockIdx.x * blockDim.x + threadIdx.x;
    if (p >= et) return;
    int s = g_ssrc[p], d = g_sdst[p];
    float ev = g_asrc2[s] + g_adst2[d];
    ev = ev > 0.f ? ev : 0.2f * ev;
    g_expw2[p] = __expf(ev);
}

// ---------------- layer2 aggregation + bias -> output -------------------------
__global__ void __launch_bounds__(256) k_agg2(const float* __restrict__ bias2,
                                              float* __restrict__ out)
{
    int t = threadIdx.x;
    int u = t & 15;
    int d = blockIdx.x * 16 + (t >> 4);
    int r0 = g_rowptr[d], r1 = g_rowptr[d + 1];
    const float4* H = (const float4*)g_h2;
    float4 acc = make_float4(0.f, 0.f, 0.f, 0.f);
    float wsum = 0.f;
    int p = r0;
    for (; p + 2 <= r1; p += 2) {
        int s0 = g_ssrc[p], s1 = g_ssrc[p + 1];
        float w0 = g_expw2[p], w1 = g_expw2[p + 1];
        float4 v0 = H[s0 * 16 + u];
        float4 v1 = H[s1 * 16 + u];
        acc.x += w0 * v0.x + w1 * v1.x;
        acc.y += w0 * v0.y + w1 * v1.y;
        acc.z += w0 * v0.z + w1 * v1.z;
        acc.w += w0 * v0.w + w1 * v1.w;
        wsum += w0 + w1;
    }
    if (p < r1) {
        int s0 = g_ssrc[p];
        float w0 = g_expw2[p];
        float4 v0 = H[s0 * 16 + u];
        acc.x += w0 * v0.x; acc.y += w0 * v0.y;
        acc.z += w0 * v0.z; acc.w += w0 * v0.w;
        wsum += w0;
    }
    float sinv = 1.f / (wsum + 1e-16f);
    float4 b = ((const float4*)bias2)[u];
    float4 o;
    o.x = acc.x * sinv + b.x;
    o.y = acc.y * sinv + b.y;
    o.z = acc.z * sinv + b.z;
    o.w = acc.w * sinv + b.w;
    ((float4*)out)[d * 16 + u] = o;
}

// ------------------------------------------------------------------------------
extern "C" void kernel_launch(void* const* d_in, const int* in_sizes, int n_in,
                              void* d_out, int out_size)
{
    const float* x   = (const float*)d_in[0];
    const void*  ei  = d_in[1];
    const float* W1  = (const float*)d_in[3];
    const float* as1 = (const float*)d_in[4];
    const float* ad1 = (const float*)d_in[5];
    const float* b1  = (const float*)d_in[6];
    const float* W2  = (const float*)d_in[7];
    const float* as2 = (const float*)d_in[8];
    const float* ad2 = (const float*)d_in[9];
    const float* b2  = (const float*)d_in[10];
    float* out = (float*)d_out;

    const int n  = in_sizes[0] / 128;   // 50000
    const int e  = in_sizes[1] / 2;     // 800000
    const int et = e + n;

    float *h1, *h2;
    unsigned short *h1h, *xhi, *xlo, *b1catT, *h2hi, *h2lo, *b2catT;
    cudaGetSymbolAddress((void**)&h1,     g_h1);
    cudaGetSymbolAddress((void**)&h2,     g_h2);
    cudaGetSymbolAddress((void**)&h1h,    g_h1h);
    cudaGetSymbolAddress((void**)&xhi,    g_xhi);
    cudaGetSymbolAddress((void**)&xlo,    g_xlo);
    cudaGetSymbolAddress((void**)&b1catT, g_b1catT);
    cudaGetSymbolAddress((void**)&h2hi,   g_h2hi);
    cudaGetSymbolAddress((void**)&h2lo,   g_h2lo);
    cudaGetSymbolAddress((void**)&b2catT, g_b2catT);

    k_zero_detect<<<(n + 255) / 256, 256>>>((const int*)ei, n);

    int nf4 = n * 32;
    k_conv_x<<<(nf4 + 255) / 256, 256>>>(x, nf4);
    k_conv_w<<<(49152 + 255) / 256, 256>>>(W1, W2);

    // layer1 GEMM: h1 = x @ W1 (fp32 + fp16 copy)
    k_gemm_bf16<<<dim3(4, (n + 127) / 128), 256>>>(xhi, xlo, b1catT, h1, h1h, n, 256, 128);

    k_att1<<<(n * 32 + 255) / 256, 256>>>(as1, ad1, n);

    // CSR build
    k_count<<<(et + 255) / 256, 256>>>(ei, e, n);
    k_scan<<<1, 1024>>>(n);
    k_scatter<<<(et + 255) / 256, 256>>>(ei, e, n);

    // layer1 softmax numerators + aggregation
    k_exp1<<<(et + 255) / 256, 256>>>(et);
    k_agg1<<<(n + 3) / 4, 256>>>(b1);

    // layer2 GEMM: h2 = elu_out @ W2
    k_gemm_bf16<<<dim3(1, (n + 127) / 128), 256>>>(h2hi, h2lo, b2catT, h2, (unsigned short*)nullptr, n, 64, 256);

    k_att2<<<(n * 32 + 255) / 256, 256>>>(as2, ad2, n);
    k_exp2<<<(et + 255) / 256, 256>>>(et);
    k_agg2<<<(n + 15) / 16, 256>>>(b2, out);
}

// round 9
// speedup vs baseline: 1.6377x; 1.0775x over previous
#include <cuda_runtime.h>
#include <cuda_bf16.h>
#include <cuda_fp16.h>
#include <cstdint>

#define NN 50000
#define NE 800000
#define NET (NN + NE)

// ---------------- scratch (static device globals; no allocation) -------------
__device__ float g_h1[NN * 256];
__device__ float g_asrc1[NN * 8];
__device__ float g_adst1[NN * 8];
__device__ float g_h2[NN * 64];
__device__ float g_asrc2[NN];
__device__ float g_adst2[NN];
__device__ float g_expw1[NET * 8];
__device__ float g_expw2[NET];
__device__ int   g_deg[NN];
__device__ int   g_rowptr[NN + 1];
__device__ int   g_pos[NN];
__device__ int   g_ssrc[NET];
__device__ int   g_sdst[NET];
__device__ int   g_is64;

// half/bf16 operands
__device__ unsigned short g_h1h[NN * 256];      // fp16 copy of h1 for gather
__device__ unsigned short g_xhi[NN * 128];
__device__ unsigned short g_xlo[NN * 128];
__device__ unsigned short g_b1catT[256 * 384];  // [n][3K]: hi|hi|lo, K=128
__device__ unsigned short g_h2hi[NN * 256];
__device__ unsigned short g_h2lo[NN * 256];
__device__ unsigned short g_b2catT[64 * 768];   // [n][3K], K=256

__device__ __forceinline__ unsigned short f2bf(float x) {
    __nv_bfloat16 b = __float2bfloat16_rn(x);
    return *(unsigned short*)&b;
}
__device__ __forceinline__ float bf2f(unsigned short u) {
    unsigned int v = ((unsigned int)u) << 16;
    return __uint_as_float(v);
}
__device__ __forceinline__ unsigned short f2h(float x) {
    __half h = __float2half_rn(x);
    return *(unsigned short*)&h;
}
__device__ __forceinline__ float h2f(unsigned short u) {
    __half h = *(__half*)&u;
    return __half2float(h);
}

__device__ __forceinline__ int load_idx(const void* ei, long long pos, int is64) {
    if (is64) return (int)((const long long*)ei)[pos];
    return ((const int*)ei)[pos];
}

// ---------------- fused prep: zero, detect, conv_x, conv_w --------------------
__global__ void k_prep(const int* __restrict__ w, const float* __restrict__ x,
                       const float* __restrict__ W1, const float* __restrict__ W2,
                       int n, int nf4)
{
    int i = blockIdx.x * blockDim.x + threadIdx.x;
    if (i == 0) {
        int all0 = 1;
        for (int j = 1; j < 200; j += 2)
            if (w[j] != 0) { all0 = 0; break; }
        g_is64 = all0;
    }
    if (i < n) g_deg[i] = 0;
    if (i < nf4) {
        float4 v = ((const float4*)x)[i];
        ushort4 hi, lo;
        hi.x = f2bf(v.x); lo.x = f2bf(v.x - bf2f(hi.x));
        hi.y = f2bf(v.y); lo.y = f2bf(v.y - bf2f(hi.y));
        hi.z = f2bf(v.z); lo.z = f2bf(v.z - bf2f(hi.z));
        hi.w = f2bf(v.w); lo.w = f2bf(v.w - bf2f(hi.w));
        ((ushort4*)g_xhi)[i] = hi;
        ((ushort4*)g_xlo)[i] = lo;
    }
    if (i < 32768) {
        int k = i >> 8, nn = i & 255;
        float wv = W1[i];
        unsigned short hi = f2bf(wv);
        unsigned short lo = f2bf(wv - bf2f(hi));
        unsigned short* r = &g_b1catT[nn * 384];
        r[k] = hi; r[128 + k] = hi; r[256 + k] = lo;
    } else if (i < 32768 + 16384) {
        int j = i - 32768;
        int k = j >> 6, nn = j & 63;
        float wv = W2[j];
        unsigned short hi = f2bf(wv);
        unsigned short lo = f2bf(wv - bf2f(hi));
        unsigned short* r = &g_b2catT[nn * 768];
        r[k] = hi; r[256 + k] = hi; r[512 + k] = lo;
    }
}

// ---------------- bf16 split tensor-core GEMM (cp.async double buffer) --------
__device__ __forceinline__ void mma16816(float* d, const uint32_t* a, const uint32_t* b) {
    asm volatile(
        "mma.sync.aligned.m16n8k16.row.col.f32.bf16.bf16.f32 "
        "{%0,%1,%2,%3}, {%4,%5,%6,%7}, {%8,%9}, {%0,%1,%2,%3};"
        : "+f"(d[0]), "+f"(d[1]), "+f"(d[2]), "+f"(d[3])
        : "r"(a[0]), "r"(a[1]), "r"(a[2]), "r"(a[3]), "r"(b[0]), "r"(b[1]));
}

__device__ __forceinline__ void ldsm_x4(uint32_t& r0, uint32_t& r1, uint32_t& r2, uint32_t& r3, uint32_t addr) {
    asm volatile("ldmatrix.sync.aligned.m8n8.x4.shared.b16 {%0,%1,%2,%3}, [%4];"
                 : "=r"(r0), "=r"(r1), "=r"(r2), "=r"(r3) : "r"(addr));
}

__device__ __forceinline__ void cpa16(uint32_t dst, const void* src, int srcsz) {
    asm volatile("cp.async.cg.shared.global [%0], [%1], 16, %2;"
                 :: "r"(dst), "l"(src), "r"(srcsz));
}

__global__ void __launch_bounds__(256) k_gemm_bf16(
    const unsigned short* __restrict__ Ahi, const unsigned short* __restrict__ Alo,
    const unsigned short* __restrict__ BcatT, float* __restrict__ C,
    unsigned short* __restrict__ Ch, int M, int Nc, int Kp)
{
    __shared__ unsigned short As[2][128][40];
    __shared__ unsigned short Bs[2][64][40];
    const int t = threadIdx.x;
    const int wid = t >> 5, lane = t & 31;
    const int gid = lane >> 2, tig = lane & 3;
    const int wm = wid & 3, wn = wid >> 2;
    const int m0 = blockIdx.y * 128, n0 = blockIdx.x * 64;
    const int cpp = Kp >> 5;
    const int nch = 3 * cpp;
    const int K3 = 3 * Kp;

    const int lr = lane & 7, lg = lane >> 3;
    const int segA = t & 3, rowA = t >> 2;
    const int nB = t >> 2, ksegB = t & 3;

    float acc[2][4][4];
#pragma unroll
    for (int a = 0; a < 2; a++)
#pragma unroll
        for (int b = 0; b < 4; b++)
#pragma unroll
            for (int c = 0; c < 4; c++) acc[a][b][c] = 0.f;

    // issue async fill of chunk cc into buffer st
    auto issue = [&](int cc, int st) {
        int phase = cc / cpp;
        int kloc = (cc - phase * cpp) * 32;
        const unsigned short* Ap = (phase == 1) ? Alo : Ahi;
#pragma unroll
        for (int half = 0; half < 2; half++) {
            int r = rowA + half * 64;
            int m = m0 + r;
            uint32_t d = (uint32_t)__cvta_generic_to_shared(&As[st][r][segA * 8]);
            cpa16(d, Ap + (size_t)m * Kp + kloc + segA * 8, (m < M) ? 16 : 0);
        }
        {
            uint32_t d = (uint32_t)__cvta_generic_to_shared(&Bs[st][nB][ksegB * 8]);
            cpa16(d, BcatT + (size_t)(n0 + nB) * K3 + cc * 32 + ksegB * 8, 16);
        }
        asm volatile("cp.async.commit_group;");
    };

    issue(0, 0);
    for (int cc = 0; cc < nch; cc++) {
        int st = cc & 1;
        if (cc + 1 < nch) {
            issue(cc + 1, st ^ 1);
            asm volatile("cp.async.wait_group 1;");
        } else {
            asm volatile("cp.async.wait_group 0;");
        }
        __syncthreads();
        const uint32_t sA = (uint32_t)__cvta_generic_to_shared(&As[st][0][0]);
        const uint32_t sB = (uint32_t)__cvta_generic_to_shared(&Bs[st][0][0]);
#pragma unroll
        for (int ks = 0; ks < 32; ks += 16) {
            uint32_t af[2][4];
#pragma unroll
            for (int mt = 0; mt < 2; mt++) {
                int row = wm * 32 + mt * 16 + (lg & 1) * 8 + lr;
                int col = ks + (lg >> 1) * 8;
                ldsm_x4(af[mt][0], af[mt][1], af[mt][2], af[mt][3],
                        sA + (uint32_t)(row * 40 + col) * 2u);
            }
            uint32_t bfr[4][2];
#pragma unroll
            for (int p2 = 0; p2 < 2; p2++) {
                int row = wn * 32 + p2 * 16 + (lg >> 1) * 8 + lr;
                int col = ks + (lg & 1) * 8;
                ldsm_x4(bfr[p2 * 2][0], bfr[p2 * 2][1], bfr[p2 * 2 + 1][0], bfr[p2 * 2 + 1][1],
                        sB + (uint32_t)(row * 40 + col) * 2u);
            }
#pragma unroll
            for (int mt = 0; mt < 2; mt++)
#pragma unroll
                for (int nt = 0; nt < 4; nt++)
                    mma16816(acc[mt][nt], af[mt], bfr[nt]);
        }
        __syncthreads();
    }
#pragma unroll
    for (int mt = 0; mt < 2; mt++) {
#pragma unroll
        for (int nt = 0; nt < 4; nt++) {
            int row = m0 + wm * 32 + mt * 16 + gid;
            int col = n0 + wn * 32 + nt * 8 + tig * 2;
            if (row < M) {
                *(float2*)&C[(size_t)row * Nc + col] = make_float2(acc[mt][nt][0], acc[mt][nt][1]);
                if (Ch) {
                    uint32_t pk = ((uint32_t)f2h(acc[mt][nt][1]) << 16) | f2h(acc[mt][nt][0]);
                    *(uint32_t*)&Ch[(size_t)row * Nc + col] = pk;
                }
            }
            if (row + 8 < M) {
                *(float2*)&C[(size_t)(row + 8) * Nc + col] = make_float2(acc[mt][nt][2], acc[mt][nt][3]);
                if (Ch) {
                    uint32_t pk = ((uint32_t)f2h(acc[mt][nt][3]) << 16) | f2h(acc[mt][nt][2]);
                    *(uint32_t*)&Ch[(size_t)(row + 8) * Nc + col] = pk;
                }
            }
        }
    }
}

// ---------------- layer1 attention logits: warp per node ----------------------
__global__ void __launch_bounds__(256) k_att1(const float* __restrict__ att_src,
                                              const float* __restrict__ att_dst, int n)
{
    int warp = (blockIdx.x * blockDim.x + threadIdx.x) >> 5;
    int lane = threadIdx.x & 31;
    if (warp >= n) return;
    float wsrc[8], wdst[8];
#pragma unroll
    for (int h = 0; h < 8; h++) {
        wsrc[h] = att_src[h * 32 + lane];
        wdst[h] = att_dst[h * 32 + lane];
    }
    const float* hp = &g_h1[warp * 256];
    float sa = 0.f, sd = 0.f;
#pragma unroll
    for (int h = 0; h < 8; h++) {
        float v = hp[h * 32 + lane];
        float p1 = v * wsrc[h];
        float p2 = v * wdst[h];
#pragma unroll
        for (int o = 16; o; o >>= 1) {
            p1 += __shfl_xor_sync(0xffffffffu, p1, o);
            p2 += __shfl_xor_sync(0xffffffffu, p2, o);
        }
        if (lane == h) { sa = p1; sd = p2; }
    }
    if (lane < 8) {
        g_asrc1[warp * 8 + lane] = sa;
        g_adst1[warp * 8 + lane] = sd;
    }
}

// ---------------- CSR build ---------------------------------------------------
__global__ void k_count(const void* __restrict__ ei, int e, int n) {
    int i = blockIdx.x * blockDim.x + threadIdx.x;
    if (i >= e + n) return;
    int is64 = g_is64;
    int d = (i < e) ? load_idx(ei, (long long)e + i, is64) : (i - e);
    atomicAdd(&g_deg[d], 1);
}

__global__ void __launch_bounds__(1024) k_scan(int n) {
    const int CH = 49;
    int t = threadIdx.x;
    int base = t * CH;
    int s = 0;
    for (int i = 0; i < CH; i++) { int idx = base + i; if (idx < n) s += g_deg[idx]; }
    int lane = t & 31, wid = t >> 5;
    int v = s;
#pragma unroll
    for (int o = 1; o < 32; o <<= 1) {
        int u = __shfl_up_sync(0xffffffffu, v, o);
        if (lane >= o) v += u;
    }
    __shared__ int ws[32];
    if (lane == 31) ws[wid] = v;
    __syncthreads();
    if (wid == 0) {
        int w = ws[lane];
#pragma unroll
        for (int o = 1; o < 32; o <<= 1) {
            int u = __shfl_up_sync(0xffffffffu, w, o);
            if (lane >= o) w += u;
        }
        ws[lane] = w;
    }
    __syncthreads();
    int excl = v - s + (wid > 0 ? ws[wid - 1] : 0);
    int run = excl;
    for (int i = 0; i < CH; i++) {
        int idx = base + i;
        if (idx < n) { g_rowptr[idx] = run; g_pos[idx] = run; run += g_deg[idx]; }
    }
    if (t == 1023) g_rowptr[n] = excl;
}

__global__ void k_scatter(const void* __restrict__ ei, int e, int n) {
    int i = blockIdx.x * blockDim.x + threadIdx.x;
    if (i >= e + n) return;
    int is64 = g_is64;
    int s, d;
    if (i < e) { s = load_idx(ei, i, is64); d = load_idx(ei, (long long)e + i, is64); }
    else       { s = i - e;                 d = i - e; }
    int p = atomicAdd(&g_pos[d], 1);
    g_ssrc[p] = s;
    g_sdst[p] = d;
}

// ---------------- layer1 softmax numerators -----------------------------------
__global__ void k_exp1(int et) {
    int p = blockIdx.x * blockDim.x + threadIdx.x;
    if (p >= et) return;
    int s = g_ssrc[p], d = g_sdst[p];
    const float4* AS = (const float4*)g_asrc1;
    const float4* AD = (const float4*)g_adst1;
    float4 a0 = AS[s * 2], a1 = AS[s * 2 + 1];
    float4 d0 = AD[d * 2], d1 = AD[d * 2 + 1];
    float4 r0, r1;
    float e0;
    e0 = a0.x + d0.x; e0 = e0 > 0.f ? e0 : 0.2f * e0; r0.x = __expf(e0);
    e0 = a0.y + d0.y; e0 = e0 > 0.f ? e0 : 0.2f * e0; r0.y = __expf(e0);
    e0 = a0.z + d0.z; e0 = e0 > 0.f ? e0 : 0.2f * e0; r0.z = __expf(e0);
    e0 = a0.w + d0.w; e0 = e0 > 0.f ? e0 : 0.2f * e0; r0.w = __expf(e0);
    e0 = a1.x + d1.x; e0 = e0 > 0.f ? e0 : 0.2f * e0; r1.x = __expf(e0);
    e0 = a1.y + d1.y; e0 = e0 > 0.f ? e0 : 0.2f * e0; r1.y = __expf(e0);
    e0 = a1.z + d1.z; e0 = e0 > 0.f ? e0 : 0.2f * e0; r1.z = __expf(e0);
    e0 = a1.w + d1.w; e0 = e0 > 0.f ? e0 : 0.2f * e0; r1.w = __expf(e0);
    float4* EX = (float4*)g_expw1;
    EX[p * 2] = r0; EX[p * 2 + 1] = r1;
}

// ---------------- layer1 aggregation (fp16 gather) + bias + ELU -> bf16 split --
__global__ void __launch_bounds__(256) k_agg1(const float* __restrict__ bias1) {
    int t = threadIdx.x;
    int u = t & 63;
    int d = blockIdx.x * 4 + (t >> 6);
    int h = u >> 3;
    int r0 = g_rowptr[d], r1 = g_rowptr[d + 1];
    const ushort4* Hh = (const ushort4*)g_h1h;
    float4 acc = make_float4(0.f, 0.f, 0.f, 0.f);
    float wsum = 0.f;
    int p = r0;
    for (; p + 2 <= r1; p += 2) {
        int s0 = g_ssrc[p],     s1 = g_ssrc[p + 1];
        float w0 = g_expw1[p * 8 + h], w1 = g_expw1[(p + 1) * 8 + h];
        ushort4 v0 = Hh[s0 * 64 + u];
        ushort4 v1 = Hh[s1 * 64 + u];
        acc.x += w0 * h2f(v0.x) + w1 * h2f(v1.x);
        acc.y += w0 * h2f(v0.y) + w1 * h2f(v1.y);
        acc.z += w0 * h2f(v0.z) + w1 * h2f(v1.z);
        acc.w += w0 * h2f(v0.w) + w1 * h2f(v1.w);
        wsum += w0 + w1;
    }
    if (p < r1) {
        int s0 = g_ssrc[p];
        float w0 = g_expw1[p * 8 + h];
        ushort4 v0 = Hh[s0 * 64 + u];
        acc.x += w0 * h2f(v0.x); acc.y += w0 * h2f(v0.y);
        acc.z += w0 * h2f(v0.z); acc.w += w0 * h2f(v0.w);
        wsum += w0;
    }
    float sinv = 1.f / (wsum + 1e-16f);
    float4 b = ((const float4*)bias1)[u];
    float4 o;
    o.x = acc.x * sinv + b.x; o.x = o.x > 0.f ? o.x : expm1f(o.x);
    o.y = acc.y * sinv + b.y; o.y = o.y > 0.f ? o.y : expm1f(o.y);
    o.z = acc.z * sinv + b.z; o.z = o.z > 0.f ? o.z : expm1f(o.z);
    o.w = acc.w * sinv + b.w; o.w = o.w > 0.f ? o.w : expm1f(o.w);
    ushort4 hi, lo;
    hi.x = f2bf(o.x); lo.x = f2bf(o.x - bf2f(hi.x));
    hi.y = f2bf(o.y); lo.y = f2bf(o.y - bf2f(hi.y));
    hi.z = f2bf(o.z); lo.z = f2bf(o.z - bf2f(hi.z));
    hi.w = f2bf(o.w); lo.w = f2bf(o.w - bf2f(hi.w));
    ((ushort4*)g_h2hi)[d * 64 + u] = hi;
    ((ushort4*)g_h2lo)[d * 64 + u] = lo;
}

// ---------------- layer2 attention logits (warp per node) ---------------------
__global__ void k_att2(const float* __restrict__ as2,
                       const float* __restrict__ ad2, int n)
{
    int w = (blockIdx.x * blockDim.x + threadIdx.x) >> 5;
    int lane = threadIdx.x & 31;
    if (w >= n) return;
    float v0 = g_h2[w * 64 + lane], v1 = g_h2[w * 64 + 32 + lane];
    float sa = v0 * as2[lane] + v1 * as2[32 + lane];
    float sd = v0 * ad2[lane] + v1 * ad2[32 + lane];
#pragma unroll
    for (int o = 16; o; o >>= 1) {
        sa += __shfl_xor_sync(0xffffffffu, sa, o);
        sd += __shfl_xor_sync(0xffffffffu, sd, o);
    }
    if (lane == 0) { g_asrc2[w] = sa; g_adst2[w] = sd; }
}

__global__ void k_exp2(int et) {
    int p = blockIdx.x * blockDim.x + threadIdx.x;
    if (p >= et) return;
    int s = g_ssrc[p], d = g_sdst[p];
    float ev = g_asrc2[s] + g_adst2[d];
    ev = ev > 0.f ? ev : 0.2f * ev;
    g_expw2[p] = __expf(ev);
}

// ---------------- layer2 aggregation + bias -> output -------------------------
__global__ void __launch_bounds__(256) k_agg2(const float* __restrict__ bias2,
                                              float* __restrict__ out)
{
    int t = threadIdx.x;
    int u = t & 15;
    int d = blockIdx.x * 16 + (t >> 4);
    int r0 = g_rowptr[d], r1 = g_rowptr[d + 1];
    const float4* H = (const float4*)g_h2;
    float4 acc = make_float4(0.f, 0.f, 0.f, 0.f);
    float wsum = 0.f;
    int p = r0;
    for (; p + 2 <= r1; p += 2) {
        int s0 = g_ssrc[p], s1 = g_ssrc[p + 1];
        float w0 = g_expw2[p], w1 = g_expw2[p + 1];
        float4 v0 = H[s0 * 16 + u];
        float4 v1 = H[s1 * 16 + u];
        acc.x += w0 * v0.x + w1 * v1.x;
        acc.y += w0 * v0.y + w1 * v1.y;
        acc.z += w0 * v0.z + w1 * v1.z;
        acc.w += w0 * v0.w + w1 * v1.w;
        wsum += w0 + w1;
    }
    if (p < r1) {
        int s0 = g_ssrc[p];
        float w0 = g_expw2[p];
        float4 v0 = H[s0 * 16 + u];
        acc.x += w0 * v0.x; acc.y += w0 * v0.y;
        acc.z += w0 * v0.z; acc.w += w0 * v0.w;
        wsum += w0;
    }
    float sinv = 1.f / (wsum + 1e-16f);
    float4 b = ((const float4*)bias2)[u];
    float4 o;
    o.x = acc.x * sinv + b.x;
    o.y = acc.y * sinv + b.y;
    o.z = acc.z * sinv + b.z;
    o.w = acc.w * sinv + b.w;
    ((float4*)out)[d * 16 + u] = o;
}

// ------------------------------------------------------------------------------
extern "C" void kernel_launch(void* const* d_in, const int* in_sizes, int n_in,
                              void* d_out, int out_size)
{
    const float* x   = (const float*)d_in[0];
    const void*  ei  = d_in[1];
    const float* W1  = (const float*)d_in[3];
    const float* as1 = (const float*)d_in[4];
    const float* ad1 = (const float*)d_in[5];
    const float* b1  = (const float*)d_in[6];
    const float* W2  = (const float*)d_in[7];
    const float* as2 = (const float*)d_in[8];
    const float* ad2 = (const float*)d_in[9];
    const float* b2  = (const float*)d_in[10];
    float* out = (float*)d_out;

    const int n  = in_sizes[0] / 128;   // 50000
    const int e  = in_sizes[1] / 2;     // 800000
    const int et = e + n;

    float *h1, *h2;
    unsigned short *h1h, *xhi, *xlo, *b1catT, *h2hi, *h2lo, *b2catT;
    cudaGetSymbolAddress((void**)&h1,     g_h1);
    cudaGetSymbolAddress((void**)&h2,     g_h2);
    cudaGetSymbolAddress((void**)&h1h,    g_h1h);
    cudaGetSymbolAddress((void**)&xhi,    g_xhi);
    cudaGetSymbolAddress((void**)&xlo,    g_xlo);
    cudaGetSymbolAddress((void**)&b1catT, g_b1catT);
    cudaGetSymbolAddress((void**)&h2hi,   g_h2hi);
    cudaGetSymbolAddress((void**)&h2lo,   g_h2lo);
    cudaGetSymbolAddress((void**)&b2catT, g_b2catT);

    int nf4 = n * 32;
    k_prep<<<(nf4 + 255) / 256, 256>>>((const int*)ei, x, W1, W2, n, nf4);

    // layer1 GEMM: h1 = x @ W1 (fp32 + fp16 copy)
    k_gemm_bf16<<<dim3(4, (n + 127) / 128), 256>>>(xhi, xlo, b1catT, h1, h1h, n, 256, 128);

    k_att1<<<(n * 32 + 255) / 256, 256>>>(as1, ad1, n);

    // CSR build
    k_count<<<(et + 255) / 256, 256>>>(ei, e, n);
    k_scan<<<1, 1024>>>(n);
    k_scatter<<<(et + 255) / 256, 256>>>(ei, e, n);

    // layer1 softmax numerators + aggregation
    k_exp1<<<(et + 255) / 256, 256>>>(et);
    k_agg1<<<(n + 3) / 4, 256>>>(b1);

    // layer2 GEMM: h2 = elu_out @ W2
    k_gemm_bf16<<<dim3(1, (n + 127) / 128), 256>>>(h2hi, h2lo, b2catT, h2, (unsigned short*)nullptr, n, 64, 256);

    k_att2<<<(n * 32 + 255) / 256, 256>>>(as2, ad2, n);
    k_exp2<<<(et + 255) / 256, 256>>>(et);
    k_agg2<<<(n + 15) / 16, 256>>>(b2, out);
}

// round 11
// speedup vs baseline: 1.8250x; 1.1143x over previous
#include <cuda_runtime.h>
#include <cuda_bf16.h>
#include <cuda_fp16.h>
#include <cstdint>

#define NN 50000
#define NE 800000
#define NET (NN + NE)

// ---------------- scratch (static device globals; no allocation) -------------
__device__ float g_asrc1[NN * 8];
__device__ float g_adst1[NN * 8];
__device__ float g_h2[NN * 64];
__device__ float g_asrc2[NN];
__device__ float g_adst2[NN];
__device__ int   g_deg[NN];
__device__ int   g_rowptr[NN + 1];
__device__ int   g_pos[NN];
__device__ int   g_ssrc[NET];
__device__ int   g_is64;

// half/bf16 operands
__device__ unsigned short g_h1h[NN * 256];      // fp16 h1 (only h1 representation kept)
__device__ unsigned short g_xhi[NN * 128];
__device__ unsigned short g_xlo[NN * 128];
__device__ unsigned short g_b1catT[256 * 384];  // [n][3K]: hi|hi|lo, K=128
__device__ unsigned short g_h2hi[NN * 256];
__device__ unsigned short g_h2lo[NN * 256];
__device__ unsigned short g_b2catT[64 * 768];   // [n][3K], K=256

__device__ __forceinline__ unsigned short f2bf(float x) {
    __nv_bfloat16 b = __float2bfloat16_rn(x);
    return *(unsigned short*)&b;
}
__device__ __forceinline__ float bf2f(unsigned short u) {
    unsigned int v = ((unsigned int)u) << 16;
    return __uint_as_float(v);
}
__device__ __forceinline__ unsigned short f2h(float x) {
    __half h = __float2half_rn(x);
    return *(unsigned short*)&h;
}
__device__ __forceinline__ float h2f(unsigned short u) {
    __half h = *(__half*)&u;
    return __half2float(h);
}

__device__ __forceinline__ int load_idx(const void* ei, long long pos, int is64) {
    if (is64) return (int)((const long long*)ei)[pos];
    return ((const int*)ei)[pos];
}

// ---------------- fused prep: zero, detect, conv_x, conv_w --------------------
__global__ void k_prep(const int* __restrict__ w, const float* __restrict__ x,
                       const float* __restrict__ W1, const float* __restrict__ W2,
                       int n, int nf4)
{
    int i = blockIdx.x * blockDim.x + threadIdx.x;
    if (i == 0) {
        int all0 = 1;
        for (int j = 1; j < 200; j += 2)
            if (w[j] != 0) { all0 = 0; break; }
        g_is64 = all0;
    }
    if (i < n) g_deg[i] = 0;
    if (i < nf4) {
        float4 v = ((const float4*)x)[i];
        ushort4 hi, lo;
        hi.x = f2bf(v.x); lo.x = f2bf(v.x - bf2f(hi.x));
        hi.y = f2bf(v.y); lo.y = f2bf(v.y - bf2f(hi.y));
        hi.z = f2bf(v.z); lo.z = f2bf(v.z - bf2f(hi.z));
        hi.w = f2bf(v.w); lo.w = f2bf(v.w - bf2f(hi.w));
        ((ushort4*)g_xhi)[i] = hi;
        ((ushort4*)g_xlo)[i] = lo;
    }
    if (i < 32768) {
        int k = i >> 8, nn = i & 255;
        float wv = W1[i];
        unsigned short hi = f2bf(wv);
        unsigned short lo = f2bf(wv - bf2f(hi));
        unsigned short* r = &g_b1catT[nn * 384];
        r[k] = hi; r[128 + k] = hi; r[256 + k] = lo;
    } else if (i < 32768 + 16384) {
        int j = i - 32768;
        int k = j >> 6, nn = j & 63;
        float wv = W2[j];
        unsigned short hi = f2bf(wv);
        unsigned short lo = f2bf(wv - bf2f(hi));
        unsigned short* r = &g_b2catT[nn * 768];
        r[k] = hi; r[256 + k] = hi; r[512 + k] = lo;
    }
}

// ---------------- bf16 split tensor-core GEMM (cp.async, optional att epi) ----
__device__ __forceinline__ void mma16816(float* d, const uint32_t* a, const uint32_t* b) {
    asm volatile(
        "mma.sync.aligned.m16n8k16.row.col.f32.bf16.bf16.f32 "
        "{%0,%1,%2,%3}, {%4,%5,%6,%7}, {%8,%9}, {%0,%1,%2,%3};"
        : "+f"(d[0]), "+f"(d[1]), "+f"(d[2]), "+f"(d[3])
        : "r"(a[0]), "r"(a[1]), "r"(a[2]), "r"(a[3]), "r"(b[0]), "r"(b[1]));
}

__device__ __forceinline__ void ldsm_x4(uint32_t& r0, uint32_t& r1, uint32_t& r2, uint32_t& r3, uint32_t addr) {
    asm volatile("ldmatrix.sync.aligned.m8n8.x4.shared.b16 {%0,%1,%2,%3}, [%4];"
                 : "=r"(r0), "=r"(r1), "=r"(r2), "=r"(r3) : "r"(addr));
}

__device__ __forceinline__ void cpa16(uint32_t dst, const void* src, int srcsz) {
    asm volatile("cp.async.cg.shared.global [%0], [%1], 16, %2;"
                 :: "r"(dst), "l"(src), "r"(srcsz));
}

// If att_src != nullptr (layer 1): skip fp32 C store, store fp16 Ch, and compute
// per-(row,head) attention logits into asrc_o/adst_o. Each warp owns one head.
__global__ void __launch_bounds__(256) k_gemm_bf16(
    const unsigned short* __restrict__ Ahi, const unsigned short* __restrict__ Alo,
    const unsigned short* __restrict__ BcatT, float* __restrict__ C,
    unsigned short* __restrict__ Ch,
    const float* __restrict__ att_src, const float* __restrict__ att_dst,
    float* __restrict__ asrc_o, float* __restrict__ adst_o,
    int M, int Nc, int Kp)
{
    __shared__ unsigned short As[2][128][40];
    __shared__ unsigned short Bs[2][64][40];
    const int t = threadIdx.x;
    const int wid = t >> 5, lane = t & 31;
    const int gid = lane >> 2, tig = lane & 3;
    const int wm = wid & 3, wn = wid >> 2;
    const int m0 = blockIdx.y * 128, n0 = blockIdx.x * 64;
    const int cpp = Kp >> 5;
    const int nch = 3 * cpp;
    const int K3 = 3 * Kp;

    const int lr = lane & 7, lg = lane >> 3;
    const int segA = t & 3, rowA = t >> 2;
    const int nB = t >> 2, ksegB = t & 3;

    float acc[2][4][4];
#pragma unroll
    for (int a = 0; a < 2; a++)
#pragma unroll
        for (int b = 0; b < 4; b++)
#pragma unroll
            for (int c = 0; c < 4; c++) acc[a][b][c] = 0.f;

    auto issue = [&](int cc, int st) {
        int phase = cc / cpp;
        int kloc = (cc - phase * cpp) * 32;
        const unsigned short* Ap = (phase == 1) ? Alo : Ahi;
#pragma unroll
        for (int half = 0; half < 2; half++) {
            int r = rowA + half * 64;
            int m = m0 + r;
            uint32_t d = (uint32_t)__cvta_generic_to_shared(&As[st][r][segA * 8]);
            cpa16(d, Ap + (size_t)m * Kp + kloc + segA * 8, (m < M) ? 16 : 0);
        }
        {
            uint32_t d = (uint32_t)__cvta_generic_to_shared(&Bs[st][nB][ksegB * 8]);
            cpa16(d, BcatT + (size_t)(n0 + nB) * K3 + cc * 32 + ksegB * 8, 16);
        }
        asm volatile("cp.async.commit_group;");
    };

    issue(0, 0);
    for (int cc = 0; cc < nch; cc++) {
        int st = cc & 1;
        if (cc + 1 < nch) {
            issue(cc + 1, st ^ 1);
            asm volatile("cp.async.wait_group 1;");
        } else {
            asm volatile("cp.async.wait_group 0;");
        }
        __syncthreads();
        const uint32_t sA = (uint32_t)__cvta_generic_to_shared(&As[st][0][0]);
        const uint32_t sB = (uint32_t)__cvta_generic_to_shared(&Bs[st][0][0]);
#pragma unroll
        for (int ks = 0; ks < 32; ks += 16) {
            uint32_t af[2][4];
#pragma unroll
            for (int mt = 0; mt < 2; mt++) {
                int row = wm * 32 + mt * 16 + (lg & 1) * 8 + lr;
                int col = ks + (lg >> 1) * 8;
                ldsm_x4(af[mt][0], af[mt][1], af[mt][2], af[mt][3],
                        sA + (uint32_t)(row * 40 + col) * 2u);
            }
            uint32_t bfr[4][2];
#pragma unroll
            for (int p2 = 0; p2 < 2; p2++) {
                int row = wn * 32 + p2 * 16 + (lg >> 1) * 8 + lr;
                int col = ks + (lg & 1) * 8;
                ldsm_x4(bfr[p2 * 2][0], bfr[p2 * 2][1], bfr[p2 * 2 + 1][0], bfr[p2 * 2 + 1][1],
                        sB + (uint32_t)(row * 40 + col) * 2u);
            }
#pragma unroll
            for (int mt = 0; mt < 2; mt++)
#pragma unroll
                for (int nt = 0; nt < 4; nt++)
                    mma16816(acc[mt][nt], af[mt], bfr[nt]);
        }
        __syncthreads();
    }

    if (att_src) {
        // layer1 epilogue: fp16 store + fused attention logits (warp = 1 head)
        const int h = blockIdx.x * 2 + wn;
        float wsv[4][2], wdv[4][2];
#pragma unroll
        for (int nt = 0; nt < 4; nt++) {
            int c = nt * 8 + tig * 2;
            wsv[nt][0] = att_src[h * 32 + c];     wsv[nt][1] = att_src[h * 32 + c + 1];
            wdv[nt][0] = att_dst[h * 32 + c];     wdv[nt][1] = att_dst[h * 32 + c + 1];
        }
#pragma unroll
        for (int mt = 0; mt < 2; mt++) {
            float ps_lo = 0.f, ps_hi = 0.f, pd_lo = 0.f, pd_hi = 0.f;
#pragma unroll
            for (int nt = 0; nt < 4; nt++) {
                ps_lo += acc[mt][nt][0] * wsv[nt][0] + acc[mt][nt][1] * wsv[nt][1];
                ps_hi += acc[mt][nt][2] * wsv[nt][0] + acc[mt][nt][3] * wsv[nt][1];
                pd_lo += acc[mt][nt][0] * wdv[nt][0] + acc[mt][nt][1] * wdv[nt][1];
                pd_hi += acc[mt][nt][2] * wdv[nt][0] + acc[mt][nt][3] * wdv[nt][1];
            }
#pragma unroll
            for (int o = 1; o <= 2; o <<= 1) {
                ps_lo += __shfl_xor_sync(0xffffffffu, ps_lo, o);
                ps_hi += __shfl_xor_sync(0xffffffffu, ps_hi, o);
                pd_lo += __shfl_xor_sync(0xffffffffu, pd_lo, o);
                pd_hi += __shfl_xor_sync(0xffffffffu, pd_hi, o);
            }
            int row = m0 + wm * 32 + mt * 16 + gid;
            if (tig == 0) {
                if (row < M)     { asrc_o[row * 8 + h] = ps_lo; adst_o[row * 8 + h] = pd_lo; }
                if (row + 8 < M) { asrc_o[(row + 8) * 8 + h] = ps_hi; adst_o[(row + 8) * 8 + h] = pd_hi; }
            }
#pragma unroll
            for (int nt = 0; nt < 4; nt++) {
                int col = n0 + wn * 32 + nt * 8 + tig * 2;
                if (row < M) {
                    uint32_t pk = ((uint32_t)f2h(acc[mt][nt][1]) << 16) | f2h(acc[mt][nt][0]);
                    *(uint32_t*)&Ch[(size_t)row * Nc + col] = pk;
                }
                if (row + 8 < M) {
                    uint32_t pk = ((uint32_t)f2h(acc[mt][nt][3]) << 16) | f2h(acc[mt][nt][2]);
                    *(uint32_t*)&Ch[(size_t)(row + 8) * Nc + col] = pk;
                }
            }
        }
    } else {
#pragma unroll
        for (int mt = 0; mt < 2; mt++) {
#pragma unroll
            for (int nt = 0; nt < 4; nt++) {
                int row = m0 + wm * 32 + mt * 16 + gid;
                int col = n0 + wn * 32 + nt * 8 + tig * 2;
                if (row < M)
                    *(float2*)&C[(size_t)row * Nc + col] = make_float2(acc[mt][nt][0], acc[mt][nt][1]);
                if (row + 8 < M)
                    *(float2*)&C[(size_t)(row + 8) * Nc + col] = make_float2(acc[mt][nt][2], acc[mt][nt][3]);
            }
        }
    }
}

// ---------------- CSR build ---------------------------------------------------
__global__ void k_count(const void* __restrict__ ei, int e, int n) {
    int i = blockIdx.x * blockDim.x + threadIdx.x;
    if (i >= e + n) return;
    int is64 = g_is64;
    int d = (i < e) ? load_idx(ei, (long long)e + i, is64) : (i - e);
    atomicAdd(&g_deg[d], 1);
}

__global__ void __launch_bounds__(1024) k_scan(int n) {
    const int CH = 49;
    int t = threadIdx.x;
    int base = t * CH;
    int s = 0;
    for (int i = 0; i < CH; i++) { int idx = base + i; if (idx < n) s += g_deg[idx]; }
    int lane = t & 31, wid = t >> 5;
    int v = s;
#pragma unroll
    for (int o = 1; o < 32; o <<= 1) {
        int u = __shfl_up_sync(0xffffffffu, v, o);
        if (lane >= o) v += u;
    }
    __shared__ int ws[32];
    if (lane == 31) ws[wid] = v;
    __syncthreads();
    if (wid == 0) {
        int w = ws[lane];
#pragma unroll
        for (int o = 1; o < 32; o <<= 1) {
            int u = __shfl_up_sync(0xffffffffu, w, o);
            if (lane >= o) w += u;
        }
        ws[lane] = w;
    }
    __syncthreads();
    int excl = v - s + (wid > 0 ? ws[wid - 1] : 0);
    int run = excl;
    for (int i = 0; i < CH; i++) {
        int idx = base + i;
        if (idx < n) { g_rowptr[idx] = run; g_pos[idx] = run; run += g_deg[idx]; }
    }
    if (t == 1023) g_rowptr[n] = excl;
}

__global__ void k_scatter(const void* __restrict__ ei, int e, int n) {
    int i = blockIdx.x * blockDim.x + threadIdx.x;
    if (i >= e + n) return;
    int is64 = g_is64;
    int s, d;
    if (i < e) { s = load_idx(ei, i, is64); d = load_idx(ei, (long long)e + i, is64); }
    else       { s = i - e;                 d = i - e; }
    int p = atomicAdd(&g_pos[d], 1);
    g_ssrc[p] = s;
}

// ---------------- layer1 agg: fused exp + gather + bias + ELU -> bf16 split ---
__global__ void __launch_bounds__(256) k_agg1(const float* __restrict__ bias1) {
    int t = threadIdx.x;
    int u = t & 63;
    int d = blockIdx.x * 4 + (t >> 6);
    int h = u >> 3;
    int r0 = g_rowptr[d], r1 = g_rowptr[d + 1];
    float ad = g_adst1[d * 8 + h];
    const ushort4* Hh = (const ushort4*)g_h1h;
    float4 acc = make_float4(0.f, 0.f, 0.f, 0.f);
    float wsum = 0.f;
    int p = r0;
    for (; p + 2 <= r1; p += 2) {
        int s0 = g_ssrc[p], s1 = g_ssrc[p + 1];
        float e0 = g_asrc1[s0 * 8 + h] + ad;
        float e1 = g_asrc1[s1 * 8 + h] + ad;
        e0 = e0 > 0.f ? e0 : 0.2f * e0;
        e1 = e1 > 0.f ? e1 : 0.2f * e1;
        float w0 = __expf(e0), w1 = __expf(e1);
        ushort4 v0 = Hh[s0 * 64 + u];
        ushort4 v1 = Hh[s1 * 64 + u];
        acc.x += w0 * h2f(v0.x) + w1 * h2f(v1.x);
        acc.y += w0 * h2f(v0.y) + w1 * h2f(v1.y);
        acc.z += w0 * h2f(v0.z) + w1 * h2f(v1.z);
        acc.w += w0 * h2f(v0.w) + w1 * h2f(v1.w);
        wsum += w0 + w1;
    }
    if (p < r1) {
        int s0 = g_ssrc[p];
        float e0 = g_asrc1[s0 * 8 + h] + ad;
        e0 = e0 > 0.f ? e0 : 0.2f * e0;
        float w0 = __expf(e0);
        ushort4 v0 = Hh[s0 * 64 + u];
        acc.x += w0 * h2f(v0.x); acc.y += w0 * h2f(v0.y);
        acc.z += w0 * h2f(v0.z); acc.w += w0 * h2f(v0.w);
        wsum += w0;
    }
    float sinv = 1.f / (wsum + 1e-16f);
    float4 b = ((const float4*)bias1)[u];
    float4 o;
    o.x = acc.x * sinv + b.x; o.x = o.x > 0.f ? o.x : expm1f(o.x);
    o.y = acc.y * sinv + b.y; o.y = o.y > 0.f ? o.y : expm1f(o.y);
    o.z = acc.z * sinv + b.z; o.z = o.z > 0.f ? o.z : expm1f(o.z);
    o.w = acc.w * sinv + b.w; o.w = o.w > 0.f ? o.w : expm1f(o.w);
    ushort4 hi, lo;
    hi.x = f2bf(o.x); lo.x = f2bf(o.x - bf2f(hi.x));
    hi.y = f2bf(o.y); lo.y = f2bf(o.y - bf2f(hi.y));
    hi.z = f2bf(o.z); lo.z = f2bf(o.z - bf2f(hi.z));
    hi.w = f2bf(o.w); lo.w = f2bf(o.w - bf2f(hi.w));
    ((ushort4*)g_h2hi)[d * 64 + u] = hi;
    ((ushort4*)g_h2lo)[d * 64 + u] = lo;
}

// ---------------- layer2 attention logits (warp per node) ---------------------
__global__ void k_att2(const float* __restrict__ as2,
                       const float* __restrict__ ad2, int n)
{
    int w = (blockIdx.x * blockDim.x + threadIdx.x) >> 5;
    int lane = threadIdx.x & 31;
    if (w >= n) return;
    float v0 = g_h2[w * 64 + lane], v1 = g_h2[w * 64 + 32 + lane];
    float sa = v0 * as2[lane] + v1 * as2[32 + lane];
    float sd = v0 * ad2[lane] + v1 * ad2[32 + lane];
#pragma unroll
    for (int o = 16; o; o >>= 1) {
        sa += __shfl_xor_sync(0xffffffffu, sa, o);
        sd += __shfl_xor_sync(0xffffffffu, sd, o);
    }
    if (lane == 0) { g_asrc2[w] = sa; g_adst2[w] = sd; }
}

// ---------------- layer2 agg: fused exp + gather + bias -> output -------------
__global__ void __launch_bounds__(256) k_agg2(const float* __restrict__ bias2,
                                              float* __restrict__ out)
{
    int t = threadIdx.x;
    int u = t & 15;
    int d = blockIdx.x * 16 + (t >> 4);
    int r0 = g_rowptr[d], r1 = g_rowptr[d + 1];
    float ad = g_adst2[d];
    const float4* H = (const float4*)g_h2;
    float4 acc = make_float4(0.f, 0.f, 0.f, 0.f);
    float wsum = 0.f;
    int p = r0;
    for (; p + 2 <= r1; p += 2) {
        int s0 = g_ssrc[p], s1 = g_ssrc[p + 1];
        float e0 = g_asrc2[s0] + ad, e1 = g_asrc2[s1] + ad;
        e0 = e0 > 0.f ? e0 : 0.2f * e0;
        e1 = e1 > 0.f ? e1 : 0.2f * e1;
        float w0 = __expf(e0), w1 = __expf(e1);
        float4 v0 = H[s0 * 16 + u];
        float4 v1 = H[s1 * 16 + u];
        acc.x += w0 * v0.x + w1 * v1.x;
        acc.y += w0 * v0.y + w1 * v1.y;
        acc.z += w0 * v0.z + w1 * v1.z;
        acc.w += w0 * v0.w + w1 * v1.w;
        wsum += w0 + w1;
    }
    if (p < r1) {
        int s0 = g_ssrc[p];
        float e0 = g_asrc2[s0] + ad;
        e0 = e0 > 0.f ? e0 : 0.2f * e0;
        float w0 = __expf(e0);
        float4 v0 = H[s0 * 16 + u];
        acc.x += w0 * v0.x; acc.y += w0 * v0.y;
        acc.z += w0 * v0.z; acc.w += w0 * v0.w;
        wsum += w0;
    }
    float sinv = 1.f / (wsum + 1e-16f);
    float4 b = ((const float4*)bias2)[u];
    float4 o;
    o.x = acc.x * sinv + b.x;
    o.y = acc.y * sinv + b.y;
    o.z = acc.z * sinv + b.z;
    o.w = acc.w * sinv + b.w;
    ((float4*)out)[d * 16 + u] = o;
}

// ------------------------------------------------------------------------------
extern "C" void kernel_launch(void* const* d_in, const int* in_sizes, int n_in,
                              void* d_out, int out_size)
{
    const float* x   = (const float*)d_in[0];
    const void*  ei  = d_in[1];
    const float* W1  = (const float*)d_in[3];
    const float* as1 = (const float*)d_in[4];
    const float* ad1 = (const float*)d_in[5];
    const float* b1  = (const float*)d_in[6];
    const float* W2  = (const float*)d_in[7];
    const float* as2 = (const float*)d_in[8];
    const float* ad2 = (const float*)d_in[9];
    const float* b2  = (const float*)d_in[10];
    float* out = (float*)d_out;

    const int n  = in_sizes[0] / 128;   // 50000
    const int e  = in_sizes[1] / 2;     // 800000
    const int et = e + n;

    float *h2, *asrc1, *adst1;
    unsigned short *h1h, *xhi, *xlo, *b1catT, *h2hi, *h2lo, *b2catT;
    cudaGetSymbolAddress((void**)&h2,     g_h2);
    cudaGetSymbolAddress((void**)&asrc1,  g_asrc1);
    cudaGetSymbolAddress((void**)&adst1,  g_adst1);
    cudaGetSymbolAddress((void**)&h1h,    g_h1h);
    cudaGetSymbolAddress((void**)&xhi,    g_xhi);
    cudaGetSymbolAddress((void**)&xlo,    g_xlo);
    cudaGetSymbolAddress((void**)&b1catT, g_b1catT);
    cudaGetSymbolAddress((void**)&h2hi,   g_h2hi);
    cudaGetSymbolAddress((void**)&h2lo,   g_h2lo);
    cudaGetSymbolAddress((void**)&b2catT, g_b2catT);

    int nf4 = n * 32;
    k_prep<<<(nf4 + 255) / 256, 256>>>((const int*)ei, x, W1, W2, n, nf4);

    // layer1 GEMM + fused att1 logits (fp16 h1 output only)
    k_gemm_bf16<<<dim3(4, (n + 127) / 128), 256>>>(
        xhi, xlo, b1catT, (float*)nullptr, h1h, as1, ad1, asrc1, adst1, n, 256, 128);

    // CSR build
    k_count<<<(et + 255) / 256, 256>>>(ei, e, n);
    k_scan<<<1, 1024>>>(n);
    k_scatter<<<(et + 255) / 256, 256>>>(ei, e, n);

    // layer1 aggregation (fused softmax)
    k_agg1<<<(n + 3) / 4, 256>>>(b1);

    // layer2 GEMM: h2 = elu_out @ W2 (fp32 output)
    k_gemm_bf16<<<dim3(1, (n + 127) / 128), 256>>>(
        h2hi, h2lo, b2catT, h2, (unsigned short*)nullptr,
        (const float*)nullptr, (const float*)nullptr, (float*)nullptr, (float*)nullptr,
        n, 64, 256);

    k_att2<<<(n * 32 + 255) / 256, 256>>>(as2, ad2, n);
    k_agg2<<<(n + 15) / 16, 256>>>(b2, out);
}

// round 12
// speedup vs baseline: 2.4050x; 1.3178x over previous
#include <cuda_runtime.h>
#include <cuda_bf16.h>
#include <cuda_fp16.h>
#include <cstdint>

#define NN 50000
#define NE 800000
#define NET (NN + NE)
#define SCAN_B 256

// ---------------- scratch (static device globals; no allocation) -------------
__device__ float g_asrc1[NN * 8];
__device__ float g_adst1[NN * 8];
__device__ float g_h2[NN * 64];
__device__ float g_asrc2[NN];
__device__ float g_adst2[NN];
__device__ int   g_deg[NN];
__device__ int   g_rowptr[NN + 1];
__device__ int   g_pos[NN];
__device__ int   g_ssrc[NET];
__device__ int   g_bsum[SCAN_B];
__device__ int   g_boff[SCAN_B];
__device__ int   g_is64;

// half/bf16 operands
__device__ unsigned short g_h1h[NN * 256];      // fp16 h1 (only h1 representation kept)
__device__ unsigned short g_xhi[NN * 128];
__device__ unsigned short g_xlo[NN * 128];
__device__ unsigned short g_b1catT[256 * 384];  // [n][3K]: hi|hi|lo, K=128
__device__ unsigned short g_h2hi[NN * 256];
__device__ unsigned short g_h2lo[NN * 256];
__device__ unsigned short g_b2catT[64 * 768];   // [n][3K], K=256

__device__ __forceinline__ unsigned short f2bf(float x) {
    __nv_bfloat16 b = __float2bfloat16_rn(x);
    return *(unsigned short*)&b;
}
__device__ __forceinline__ float bf2f(unsigned short u) {
    unsigned int v = ((unsigned int)u) << 16;
    return __uint_as_float(v);
}
__device__ __forceinline__ unsigned short f2h(float x) {
    __half h = __float2half_rn(x);
    return *(unsigned short*)&h;
}
__device__ __forceinline__ float h2f(unsigned short u) {
    __half h = *(__half*)&u;
    return __half2float(h);
}

__device__ __forceinline__ int load_idx(const void* ei, long long pos, int is64) {
    if (is64) return (int)((const long long*)ei)[pos];
    return ((const int*)ei)[pos];
}

// ---------------- fused prep: zero, detect, conv_x, conv_w --------------------
__global__ void k_prep(const int* __restrict__ w, const float* __restrict__ x,
                       const float* __restrict__ W1, const float* __restrict__ W2,
                       int n, int nf4)
{
    int i = blockIdx.x * blockDim.x + threadIdx.x;
    if (i == 0) {
        int all0 = 1;
        for (int j = 1; j < 200; j += 2)
            if (w[j] != 0) { all0 = 0; break; }
        g_is64 = all0;
    }
    if (i < n) g_deg[i] = 0;
    if (i < nf4) {
        float4 v = ((const float4*)x)[i];
        ushort4 hi, lo;
        hi.x = f2bf(v.x); lo.x = f2bf(v.x - bf2f(hi.x));
        hi.y = f2bf(v.y); lo.y = f2bf(v.y - bf2f(hi.y));
        hi.z = f2bf(v.z); lo.z = f2bf(v.z - bf2f(hi.z));
        hi.w = f2bf(v.w); lo.w = f2bf(v.w - bf2f(hi.w));
        ((ushort4*)g_xhi)[i] = hi;
        ((ushort4*)g_xlo)[i] = lo;
    }
    if (i < 32768) {
        int k = i >> 8, nn = i & 255;
        float wv = W1[i];
        unsigned short hi = f2bf(wv);
        unsigned short lo = f2bf(wv - bf2f(hi));
        unsigned short* r = &g_b1catT[nn * 384];
        r[k] = hi; r[128 + k] = hi; r[256 + k] = lo;
    } else if (i < 32768 + 16384) {
        int j = i - 32768;
        int k = j >> 6, nn = j & 63;
        float wv = W2[j];
        unsigned short hi = f2bf(wv);
        unsigned short lo = f2bf(wv - bf2f(hi));
        unsigned short* r = &g_b2catT[nn * 768];
        r[k] = hi; r[256 + k] = hi; r[512 + k] = lo;
    }
}

// ---------------- bf16 split tensor-core GEMM (cp.async, optional att epi) ----
__device__ __forceinline__ void mma16816(float* d, const uint32_t* a, const uint32_t* b) {
    asm volatile(
        "mma.sync.aligned.m16n8k16.row.col.f32.bf16.bf16.f32 "
        "{%0,%1,%2,%3}, {%4,%5,%6,%7}, {%8,%9}, {%0,%1,%2,%3};"
        : "+f"(d[0]), "+f"(d[1]), "+f"(d[2]), "+f"(d[3])
        : "r"(a[0]), "r"(a[1]), "r"(a[2]), "r"(a[3]), "r"(b[0]), "r"(b[1]));
}

__device__ __forceinline__ void ldsm_x4(uint32_t& r0, uint32_t& r1, uint32_t& r2, uint32_t& r3, uint32_t addr) {
    asm volatile("ldmatrix.sync.aligned.m8n8.x4.shared.b16 {%0,%1,%2,%3}, [%4];"
                 : "=r"(r0), "=r"(r1), "=r"(r2), "=r"(r3) : "r"(addr));
}

__device__ __forceinline__ void cpa16(uint32_t dst, const void* src, int srcsz) {
    asm volatile("cp.async.cg.shared.global [%0], [%1], 16, %2;"
                 :: "r"(dst), "l"(src), "r"(srcsz));
}

// If att_src != nullptr (layer 1): skip fp32 C store, store fp16 Ch, and compute
// per-(row,head) attention logits into asrc_o/adst_o. Each warp owns one head.
__global__ void __launch_bounds__(256) k_gemm_bf16(
    const unsigned short* __restrict__ Ahi, const unsigned short* __restrict__ Alo,
    const unsigned short* __restrict__ BcatT, float* __restrict__ C,
    unsigned short* __restrict__ Ch,
    const float* __restrict__ att_src, const float* __restrict__ att_dst,
    float* __restrict__ asrc_o, float* __restrict__ adst_o,
    int M, int Nc, int Kp)
{
    __shared__ unsigned short As[2][128][40];
    __shared__ unsigned short Bs[2][64][40];
    const int t = threadIdx.x;
    const int wid = t >> 5, lane = t & 31;
    const int gid = lane >> 2, tig = lane & 3;
    const int wm = wid & 3, wn = wid >> 2;
    const int m0 = blockIdx.y * 128, n0 = blockIdx.x * 64;
    const int cpp = Kp >> 5;
    const int nch = 3 * cpp;
    const int K3 = 3 * Kp;

    const int lr = lane & 7, lg = lane >> 3;
    const int segA = t & 3, rowA = t >> 2;
    const int nB = t >> 2, ksegB = t & 3;

    float acc[2][4][4];
#pragma unroll
    for (int a = 0; a < 2; a++)
#pragma unroll
        for (int b = 0; b < 4; b++)
#pragma unroll
            for (int c = 0; c < 4; c++) acc[a][b][c] = 0.f;

    auto issue = [&](int cc, int st) {
        int phase = cc / cpp;
        int kloc = (cc - phase * cpp) * 32;
        const unsigned short* Ap = (phase == 1) ? Alo : Ahi;
#pragma unroll
        for (int half = 0; half < 2; half++) {
            int r = rowA + half * 64;
            int m = m0 + r;
            uint32_t d = (uint32_t)__cvta_generic_to_shared(&As[st][r][segA * 8]);
            cpa16(d, Ap + (size_t)m * Kp + kloc + segA * 8, (m < M) ? 16 : 0);
        }
        {
            uint32_t d = (uint32_t)__cvta_generic_to_shared(&Bs[st][nB][ksegB * 8]);
            cpa16(d, BcatT + (size_t)(n0 + nB) * K3 + cc * 32 + ksegB * 8, 16);
        }
        asm volatile("cp.async.commit_group;");
    };

    issue(0, 0);
    for (int cc = 0; cc < nch; cc++) {
        int st = cc & 1;
        if (cc + 1 < nch) {
            issue(cc + 1, st ^ 1);
            asm volatile("cp.async.wait_group 1;");
        } else {
            asm volatile("cp.async.wait_group 0;");
        }
        __syncthreads();
        const uint32_t sA = (uint32_t)__cvta_generic_to_shared(&As[st][0][0]);
        const uint32_t sB = (uint32_t)__cvta_generic_to_shared(&Bs[st][0][0]);
#pragma unroll
        for (int ks = 0; ks < 32; ks += 16) {
            uint32_t af[2][4];
#pragma unroll
            for (int mt = 0; mt < 2; mt++) {
                int row = wm * 32 + mt * 16 + (lg & 1) * 8 + lr;
                int col = ks + (lg >> 1) * 8;
                ldsm_x4(af[mt][0], af[mt][1], af[mt][2], af[mt][3],
                        sA + (uint32_t)(row * 40 + col) * 2u);
            }
            uint32_t bfr[4][2];
#pragma unroll
            for (int p2 = 0; p2 < 2; p2++) {
                int row = wn * 32 + p2 * 16 + (lg >> 1) * 8 + lr;
                int col = ks + (lg & 1) * 8;
                ldsm_x4(bfr[p2 * 2][0], bfr[p2 * 2][1], bfr[p2 * 2 + 1][0], bfr[p2 * 2 + 1][1],
                        sB + (uint32_t)(row * 40 + col) * 2u);
            }
#pragma unroll
            for (int mt = 0; mt < 2; mt++)
#pragma unroll
                for (int nt = 0; nt < 4; nt++)
                    mma16816(acc[mt][nt], af[mt], bfr[nt]);
        }
        __syncthreads();
    }

    if (att_src) {
        // layer1 epilogue: fp16 store + fused attention logits (warp = 1 head)
        const int h = blockIdx.x * 2 + wn;
        float wsv[4][2], wdv[4][2];
#pragma unroll
        for (int nt = 0; nt < 4; nt++) {
            int c = nt * 8 + tig * 2;
            wsv[nt][0] = att_src[h * 32 + c];     wsv[nt][1] = att_src[h * 32 + c + 1];
            wdv[nt][0] = att_dst[h * 32 + c];     wdv[nt][1] = att_dst[h * 32 + c + 1];
        }
#pragma unroll
        for (int mt = 0; mt < 2; mt++) {
            float ps_lo = 0.f, ps_hi = 0.f, pd_lo = 0.f, pd_hi = 0.f;
#pragma unroll
            for (int nt = 0; nt < 4; nt++) {
                ps_lo += acc[mt][nt][0] * wsv[nt][0] + acc[mt][nt][1] * wsv[nt][1];
                ps_hi += acc[mt][nt][2] * wsv[nt][0] + acc[mt][nt][3] * wsv[nt][1];
                pd_lo += acc[mt][nt][0] * wdv[nt][0] + acc[mt][nt][1] * wdv[nt][1];
                pd_hi += acc[mt][nt][2] * wdv[nt][0] + acc[mt][nt][3] * wdv[nt][1];
            }
#pragma unroll
            for (int o = 1; o <= 2; o <<= 1) {
                ps_lo += __shfl_xor_sync(0xffffffffu, ps_lo, o);
                ps_hi += __shfl_xor_sync(0xffffffffu, ps_hi, o);
                pd_lo += __shfl_xor_sync(0xffffffffu, pd_lo, o);
                pd_hi += __shfl_xor_sync(0xffffffffu, pd_hi, o);
            }
            int row = m0 + wm * 32 + mt * 16 + gid;
            if (tig == 0) {
                if (row < M)     { asrc_o[row * 8 + h] = ps_lo; adst_o[row * 8 + h] = pd_lo; }
                if (row + 8 < M) { asrc_o[(row + 8) * 8 + h] = ps_hi; adst_o[(row + 8) * 8 + h] = pd_hi; }
            }
#pragma unroll
            for (int nt = 0; nt < 4; nt++) {
                int col = n0 + wn * 32 + nt * 8 + tig * 2;
                if (row < M) {
                    uint32_t pk = ((uint32_t)f2h(acc[mt][nt][1]) << 16) | f2h(acc[mt][nt][0]);
                    *(uint32_t*)&Ch[(size_t)row * Nc + col] = pk;
                }
                if (row + 8 < M) {
                    uint32_t pk = ((uint32_t)f2h(acc[mt][nt][3]) << 16) | f2h(acc[mt][nt][2]);
                    *(uint32_t*)&Ch[(size_t)(row + 8) * Nc + col] = pk;
                }
            }
        }
    } else {
#pragma unroll
        for (int mt = 0; mt < 2; mt++) {
#pragma unroll
            for (int nt = 0; nt < 4; nt++) {
                int row = m0 + wm * 32 + mt * 16 + gid;
                int col = n0 + wn * 32 + nt * 8 + tig * 2;
                if (row < M)
                    *(float2*)&C[(size_t)row * Nc + col] = make_float2(acc[mt][nt][0], acc[mt][nt][1]);
                if (row + 8 < M)
                    *(float2*)&C[(size_t)(row + 8) * Nc + col] = make_float2(acc[mt][nt][2], acc[mt][nt][3]);
            }
        }
    }
}

// ---------------- CSR build ---------------------------------------------------
__global__ void k_count(const void* __restrict__ ei, int e, int n) {
    int i = blockIdx.x * blockDim.x + threadIdx.x;
    if (i >= e + n) return;
    int is64 = g_is64;
    int d = (i < e) ? load_idx(ei, (long long)e + i, is64) : (i - e);
    atomicAdd(&g_deg[d], 1);
}

// full-chip 3-phase exclusive scan of g_deg -> g_rowptr/g_pos
__device__ __forceinline__ int block_incl_scan(int v, int t) {
    __shared__ int ws[8];
    int lane = t & 31, wid = t >> 5;
    int incl = v;
#pragma unroll
    for (int o = 1; o < 32; o <<= 1) {
        int u = __shfl_up_sync(0xffffffffu, incl, o);
        if (lane >= o) incl += u;
    }
    if (lane == 31) ws[wid] = incl;
    __syncthreads();
    if (wid == 0) {
        int w = (lane < 8) ? ws[lane] : 0;
#pragma unroll
        for (int o = 1; o < 8; o <<= 1) {
            int u = __shfl_up_sync(0xffffffffu, w, o);
            if (lane >= o) w += u;
        }
        if (lane < 8) ws[lane] = w;
    }
    __syncthreads();
    return incl + (wid > 0 ? ws[wid - 1] : 0);
}

__global__ void __launch_bounds__(SCAN_B) k_scan_a(int n) {
    int t = threadIdx.x;
    int i = blockIdx.x * SCAN_B + t;
    int v = (i < n) ? g_deg[i] : 0;
    int incl = block_incl_scan(v, t);
    if (i < n) g_rowptr[i] = incl - v;      // block-local exclusive
    if (t == SCAN_B - 1) g_bsum[blockIdx.x] = incl;
}

__global__ void __launch_bounds__(SCAN_B) k_scan_b(int nb, int n) {
    int t = threadIdx.x;
    int v = (t < nb) ? g_bsum[t] : 0;
    int incl = block_incl_scan(v, t);
    if (t < nb) g_boff[t] = incl - v;       // exclusive block offsets
    if (t == SCAN_B - 1) g_rowptr[n] = incl;
}

__global__ void __launch_bounds__(SCAN_B) k_scan_c(int n) {
    int i = blockIdx.x * SCAN_B + threadIdx.x;
    if (i < n) {
        int r = g_rowptr[i] + g_boff[blockIdx.x];
        g_rowptr[i] = r;
        g_pos[i] = r;
    }
}

__global__ void k_scatter(const void* __restrict__ ei, int e, int n) {
    int i = blockIdx.x * blockDim.x + threadIdx.x;
    if (i >= e + n) return;
    int is64 = g_is64;
    int s, d;
    if (i < e) { s = load_idx(ei, i, is64); d = load_idx(ei, (long long)e + i, is64); }
    else       { s = i - e;                 d = i - e; }
    int p = atomicAdd(&g_pos[d], 1);
    g_ssrc[p] = s;
}

// ---------------- layer1 agg: fused exp + gather + bias + ELU -> bf16 split ---
__global__ void __launch_bounds__(256) k_agg1(const float* __restrict__ bias1) {
    int t = threadIdx.x;
    int u = t & 63;
    int d = blockIdx.x * 4 + (t >> 6);
    int h = u >> 3;
    int r0 = g_rowptr[d], r1 = g_rowptr[d + 1];
    float ad = g_adst1[d * 8 + h];
    const ushort4* Hh = (const ushort4*)g_h1h;
    float4 acc = make_float4(0.f, 0.f, 0.f, 0.f);
    float wsum = 0.f;
    int p = r0;
    for (; p + 2 <= r1; p += 2) {
        int s0 = g_ssrc[p], s1 = g_ssrc[p + 1];
        float e0 = g_asrc1[s0 * 8 + h] + ad;
        float e1 = g_asrc1[s1 * 8 + h] + ad;
        e0 = e0 > 0.f ? e0 : 0.2f * e0;
        e1 = e1 > 0.f ? e1 : 0.2f * e1;
        float w0 = __expf(e0), w1 = __expf(e1);
        ushort4 v0 = Hh[s0 * 64 + u];
        ushort4 v1 = Hh[s1 * 64 + u];
        acc.x += w0 * h2f(v0.x) + w1 * h2f(v1.x);
        acc.y += w0 * h2f(v0.y) + w1 * h2f(v1.y);
        acc.z += w0 * h2f(v0.z) + w1 * h2f(v1.z);
        acc.w += w0 * h2f(v0.w) + w1 * h2f(v1.w);
        wsum += w0 + w1;
    }
    if (p < r1) {
        int s0 = g_ssrc[p];
        float e0 = g_asrc1[s0 * 8 + h] + ad;
        e0 = e0 > 0.f ? e0 : 0.2f * e0;
        float w0 = __expf(e0);
        ushort4 v0 = Hh[s0 * 64 + u];
        acc.x += w0 * h2f(v0.x); acc.y += w0 * h2f(v0.y);
        acc.z += w0 * h2f(v0.z); acc.w += w0 * h2f(v0.w);
        wsum += w0;
    }
    float sinv = 1.f / (wsum + 1e-16f);
    float4 b = ((const float4*)bias1)[u];
    float4 o;
    o.x = acc.x * sinv + b.x; o.x = o.x > 0.f ? o.x : expm1f(o.x);
    o.y = acc.y * sinv + b.y; o.y = o.y > 0.f ? o.y : expm1f(o.y);
    o.z = acc.z * sinv + b.z; o.z = o.z > 0.f ? o.z : expm1f(o.z);
    o.w = acc.w * sinv + b.w; o.w = o.w > 0.f ? o.w : expm1f(o.w);
    ushort4 hi, lo;
    hi.x = f2bf(o.x); lo.x = f2bf(o.x - bf2f(hi.x));
    hi.y = f2bf(o.y); lo.y = f2bf(o.y - bf2f(hi.y));
    hi.z = f2bf(o.z); lo.z = f2bf(o.z - bf2f(hi.z));
    hi.w = f2bf(o.w); lo.w = f2bf(o.w - bf2f(hi.w));
    ((ushort4*)g_h2hi)[d * 64 + u] = hi;
    ((ushort4*)g_h2lo)[d * 64 + u] = lo;
}

// ---------------- layer2 attention logits (warp per node) ---------------------
__global__ void k_att2(const float* __restrict__ as2,
                       const float* __restrict__ ad2, int n)
{
    int w = (blockIdx.x * blockDim.x + threadIdx.x) >> 5;
    int lane = threadIdx.x & 31;
    if (w >= n) return;
    float v0 = g_h2[w * 64 + lane], v1 = g_h2[w * 64 + 32 + lane];
    float sa = v0 * as2[lane] + v1 * as2[32 + lane];
    float sd = v0 * ad2[lane] + v1 * ad2[32 + lane];
#pragma unroll
    for (int o = 16; o; o >>= 1) {
        sa += __shfl_xor_sync(0xffffffffu, sa, o);
        sd += __shfl_xor_sync(0xffffffffu, sd, o);
    }
    if (lane == 0) { g_asrc2[w] = sa; g_adst2[w] = sd; }
}

// ---------------- layer2 agg: fused exp + gather + bias -> output -------------
__global__ void __launch_bounds__(256) k_agg2(const float* __restrict__ bias2,
                                              float* __restrict__ out)
{
    int t = threadIdx.x;
    int u = t & 15;
    int d = blockIdx.x * 16 + (t >> 4);
    int r0 = g_rowptr[d], r1 = g_rowptr[d + 1];
    float ad = g_adst2[d];
    const float4* H = (const float4*)g_h2;
    float4 acc = make_float4(0.f, 0.f, 0.f, 0.f);
    float wsum = 0.f;
    int p = r0;
    for (; p + 2 <= r1; p += 2) {
        int s0 = g_ssrc[p], s1 = g_ssrc[p + 1];
        float e0 = g_asrc2[s0] + ad, e1 = g_asrc2[s1] + ad;
        e0 = e0 > 0.f ? e0 : 0.2f * e0;
        e1 = e1 > 0.f ? e1 : 0.2f * e1;
        float w0 = __expf(e0), w1 = __expf(e1);
        float4 v0 = H[s0 * 16 + u];
        float4 v1 = H[s1 * 16 + u];
        acc.x += w0 * v0.x + w1 * v1.x;
        acc.y += w0 * v0.y + w1 * v1.y;
        acc.z += w0 * v0.z + w1 * v1.z;
        acc.w += w0 * v0.w + w1 * v1.w;
        wsum += w0 + w1;
    }
    if (p < r1) {
        int s0 = g_ssrc[p];
        float e0 = g_asrc2[s0] + ad;
        e0 = e0 > 0.f ? e0 : 0.2f * e0;
        float w0 = __expf(e0);
        float4 v0 = H[s0 * 16 + u];
        acc.x += w0 * v0.x; acc.y += w0 * v0.y;
        acc.z += w0 * v0.z; acc.w += w0 * v0.w;
        wsum += w0;
    }
    float sinv = 1.f / (wsum + 1e-16f);
    float4 b = ((const float4*)bias2)[u];
    float4 o;
    o.x = acc.x * sinv + b.x;
    o.y = acc.y * sinv + b.y;
    o.z = acc.z * sinv + b.z;
    o.w = acc.w * sinv + b.w;
    ((float4*)out)[d * 16 + u] = o;
}

// ------------------------------------------------------------------------------
extern "C" void kernel_launch(void* const* d_in, const int* in_sizes, int n_in,
                              void* d_out, int out_size)
{
    const float* x   = (const float*)d_in[0];
    const void*  ei  = d_in[1];
    const float* W1  = (const float*)d_in[3];
    const float* as1 = (const float*)d_in[4];
    const float* ad1 = (const float*)d_in[5];
    const float* b1  = (const float*)d_in[6];
    const float* W2  = (const float*)d_in[7];
    const float* as2 = (const float*)d_in[8];
    const float* ad2 = (const float*)d_in[9];
    const float* b2  = (const float*)d_in[10];
    float* out = (float*)d_out;

    const int n  = in_sizes[0] / 128;   // 50000
    const int e  = in_sizes[1] / 2;     // 800000
    const int et = e + n;
    const int nb = (n + SCAN_B - 1) / SCAN_B;   // 196

    float *h2, *asrc1, *adst1;
    unsigned short *h1h, *xhi, *xlo, *b1catT, *h2hi, *h2lo, *b2catT;
    cudaGetSymbolAddress((void**)&h2,     g_h2);
    cudaGetSymbolAddress((void**)&asrc1,  g_asrc1);
    cudaGetSymbolAddress((void**)&adst1,  g_adst1);
    cudaGetSymbolAddress((void**)&h1h,    g_h1h);
    cudaGetSymbolAddress((void**)&xhi,    g_xhi);
    cudaGetSymbolAddress((void**)&xlo,    g_xlo);
    cudaGetSymbolAddress((void**)&b1catT, g_b1catT);
    cudaGetSymbolAddress((void**)&h2hi,   g_h2hi);
    cudaGetSymbolAddress((void**)&h2lo,   g_h2lo);
    cudaGetSymbolAddress((void**)&b2catT, g_b2catT);

    int nf4 = n * 32;
    k_prep<<<(nf4 + 255) / 256, 256>>>((const int*)ei, x, W1, W2, n, nf4);

    // layer1 GEMM + fused att1 logits (fp16 h1 output only)
    k_gemm_bf16<<<dim3(4, (n + 127) / 128), 256>>>(
        xhi, xlo, b1catT, (float*)nullptr, h1h, as1, ad1, asrc1, adst1, n, 256, 128);

    // CSR build (full-chip 3-phase scan)
    k_count<<<(et + 255) / 256, 256>>>(ei, e, n);
    k_scan_a<<<nb, SCAN_B>>>(n);
    k_scan_b<<<1, SCAN_B>>>(nb, n);
    k_scan_c<<<nb, SCAN_B>>>(n);
    k_scatter<<<(et + 255) / 256, 256>>>(ei, e, n);

    // layer1 aggregation (fused softmax)
    k_agg1<<<(n + 3) / 4, 256>>>(b1);

    // layer2 GEMM: h2 = elu_out @ W2 (fp32 output)
    k_gemm_bf16<<<dim3(1, (n + 127) / 128), 256>>>(
        h2hi, h2lo, b2catT, h2, (unsigned short*)nullptr,
        (const float*)nullptr, (const float*)nullptr, (float*)nullptr, (float*)nullptr,
        n, 64, 256);

    k_att2<<<(n * 32 + 255) / 256, 256>>>(as2, ad2, n);
    k_agg2<<<(n + 15) / 16, 256>>>(b2, out);
}

// round 13
// speedup vs baseline: 2.5423x; 1.0571x over previous
#include <cuda_runtime.h>
#include <cuda_bf16.h>
#include <cuda_fp16.h>
#include <cstdint>

#define NN 50000
#define NE 800000
#define NET (NN + NE)
#define SCAN_B 256

// ---------------- scratch (static device globals; no allocation) -------------
__device__ float g_asrc1[NN * 8];
__device__ float g_adst1[NN * 8];
__device__ float g_h2[NN * 64];
__device__ float g_asrc2[NN];
__device__ float g_adst2[NN];
__device__ int   g_deg[NN];
__device__ int   g_rowptr[NN + 1];
__device__ int   g_pos[NN];
__device__ int   g_ssrc[NET];
__device__ int   g_bsum[SCAN_B];
__device__ int   g_boff[SCAN_B];
__device__ int   g_is64;

// half/bf16 operands
__device__ unsigned short g_h1h[NN * 256];      // fp16 h1 (only h1 representation kept)
__device__ unsigned short g_xhi[NN * 128];
__device__ unsigned short g_xlo[NN * 128];
__device__ unsigned short g_b1catT[256 * 384];  // [n][3K]: hi|hi|lo, K=128
__device__ unsigned short g_h2hi[NN * 256];
__device__ unsigned short g_h2lo[NN * 256];
__device__ unsigned short g_b2catT[64 * 768];   // [n][3K], K=256

__device__ __forceinline__ unsigned short f2bf(float x) {
    __nv_bfloat16 b = __float2bfloat16_rn(x);
    return *(unsigned short*)&b;
}
__device__ __forceinline__ float bf2f(unsigned short u) {
    unsigned int v = ((unsigned int)u) << 16;
    return __uint_as_float(v);
}
__device__ __forceinline__ unsigned short f2h(float x) {
    __half h = __float2half_rn(x);
    return *(unsigned short*)&h;
}
__device__ __forceinline__ float h2f(unsigned short u) {
    __half h = *(__half*)&u;
    return __half2float(h);
}

__device__ __forceinline__ int load_idx(const void* ei, long long pos, int is64) {
    if (is64) return (int)((const long long*)ei)[pos];
    return ((const int*)ei)[pos];
}

// ---------------- fused prep: zero, detect, conv_x, conv_w --------------------
__global__ void k_prep(const int* __restrict__ w, const float* __restrict__ x,
                       const float* __restrict__ W1, const float* __restrict__ W2,
                       int n, int nf4)
{
    int i = blockIdx.x * blockDim.x + threadIdx.x;
    if (i == 0) {
        int all0 = 1;
        for (int j = 1; j < 200; j += 2)
            if (w[j] != 0) { all0 = 0; break; }
        g_is64 = all0;
    }
    if (i < n) g_deg[i] = 0;
    if (i < nf4) {
        float4 v = ((const float4*)x)[i];
        ushort4 hi, lo;
        hi.x = f2bf(v.x); lo.x = f2bf(v.x - bf2f(hi.x));
        hi.y = f2bf(v.y); lo.y = f2bf(v.y - bf2f(hi.y));
        hi.z = f2bf(v.z); lo.z = f2bf(v.z - bf2f(hi.z));
        hi.w = f2bf(v.w); lo.w = f2bf(v.w - bf2f(hi.w));
        ((ushort4*)g_xhi)[i] = hi;
        ((ushort4*)g_xlo)[i] = lo;
    }
    if (i < 32768) {
        int k = i >> 8, nn = i & 255;
        float wv = W1[i];
        unsigned short hi = f2bf(wv);
        unsigned short lo = f2bf(wv - bf2f(hi));
        unsigned short* r = &g_b1catT[nn * 384];
        r[k] = hi; r[128 + k] = hi; r[256 + k] = lo;
    } else if (i < 32768 + 16384) {
        int j = i - 32768;
        int k = j >> 6, nn = j & 63;
        float wv = W2[j];
        unsigned short hi = f2bf(wv);
        unsigned short lo = f2bf(wv - bf2f(hi));
        unsigned short* r = &g_b2catT[nn * 768];
        r[k] = hi; r[256 + k] = hi; r[512 + k] = lo;
    }
}

// ---------------- bf16 split tensor-core GEMM (cp.async, optional att epi) ----
__device__ __forceinline__ void mma16816(float* d, const uint32_t* a, const uint32_t* b) {
    asm volatile(
        "mma.sync.aligned.m16n8k16.row.col.f32.bf16.bf16.f32 "
        "{%0,%1,%2,%3}, {%4,%5,%6,%7}, {%8,%9}, {%0,%1,%2,%3};"
        : "+f"(d[0]), "+f"(d[1]), "+f"(d[2]), "+f"(d[3])
        : "r"(a[0]), "r"(a[1]), "r"(a[2]), "r"(a[3]), "r"(b[0]), "r"(b[1]));
}

__device__ __forceinline__ void ldsm_x4(uint32_t& r0, uint32_t& r1, uint32_t& r2, uint32_t& r3, uint32_t addr) {
    asm volatile("ldmatrix.sync.aligned.m8n8.x4.shared.b16 {%0,%1,%2,%3}, [%4];"
                 : "=r"(r0), "=r"(r1), "=r"(r2), "=r"(r3) : "r"(addr));
}

__device__ __forceinline__ void cpa16(uint32_t dst, const void* src, int srcsz) {
    asm volatile("cp.async.cg.shared.global [%0], [%1], 16, %2;"
                 :: "r"(dst), "l"(src), "r"(srcsz));
}

// If att_src != nullptr (layer 1): skip fp32 C store, store fp16 Ch, and compute
// per-(row,head) attention logits into asrc_o/adst_o. Each warp owns one head.
__global__ void __launch_bounds__(256) k_gemm_bf16(
    const unsigned short* __restrict__ Ahi, const unsigned short* __restrict__ Alo,
    const unsigned short* __restrict__ BcatT, float* __restrict__ C,
    unsigned short* __restrict__ Ch,
    const float* __restrict__ att_src, const float* __restrict__ att_dst,
    float* __restrict__ asrc_o, float* __restrict__ adst_o,
    int M, int Nc, int Kp)
{
    __shared__ unsigned short As[2][128][40];
    __shared__ unsigned short Bs[2][64][40];
    const int t = threadIdx.x;
    const int wid = t >> 5, lane = t & 31;
    const int gid = lane >> 2, tig = lane & 3;
    const int wm = wid & 3, wn = wid >> 2;
    const int m0 = blockIdx.y * 128, n0 = blockIdx.x * 64;
    const int cpp = Kp >> 5;
    const int nch = 3 * cpp;
    const int K3 = 3 * Kp;

    const int lr = lane & 7, lg = lane >> 3;
    const int segA = t & 3, rowA = t >> 2;
    const int nB = t >> 2, ksegB = t & 3;

    float acc[2][4][4];
#pragma unroll
    for (int a = 0; a < 2; a++)
#pragma unroll
        for (int b = 0; b < 4; b++)
#pragma unroll
            for (int c = 0; c < 4; c++) acc[a][b][c] = 0.f;

    auto issue = [&](int cc, int st) {
        int phase = cc / cpp;
        int kloc = (cc - phase * cpp) * 32;
        const unsigned short* Ap = (phase == 1) ? Alo : Ahi;
#pragma unroll
        for (int half = 0; half < 2; half++) {
            int r = rowA + half * 64;
            int m = m0 + r;
            uint32_t d = (uint32_t)__cvta_generic_to_shared(&As[st][r][segA * 8]);
            cpa16(d, Ap + (size_t)m * Kp + kloc + segA * 8, (m < M) ? 16 : 0);
        }
        {
            uint32_t d = (uint32_t)__cvta_generic_to_shared(&Bs[st][nB][ksegB * 8]);
            cpa16(d, BcatT + (size_t)(n0 + nB) * K3 + cc * 32 + ksegB * 8, 16);
        }
        asm volatile("cp.async.commit_group;");
    };

    issue(0, 0);
    for (int cc = 0; cc < nch; cc++) {
        int st = cc & 1;
        if (cc + 1 < nch) {
            issue(cc + 1, st ^ 1);
            asm volatile("cp.async.wait_group 1;");
        } else {
            asm volatile("cp.async.wait_group 0;");
        }
        __syncthreads();
        const uint32_t sA = (uint32_t)__cvta_generic_to_shared(&As[st][0][0]);
        const uint32_t sB = (uint32_t)__cvta_generic_to_shared(&Bs[st][0][0]);
#pragma unroll
        for (int ks = 0; ks < 32; ks += 16) {
            uint32_t af[2][4];
#pragma unroll
            for (int mt = 0; mt < 2; mt++) {
                int row = wm * 32 + mt * 16 + (lg & 1) * 8 + lr;
                int col = ks + (lg >> 1) * 8;
                ldsm_x4(af[mt][0], af[mt][1], af[mt][2], af[mt][3],
                        sA + (uint32_t)(row * 40 + col) * 2u);
            }
            uint32_t bfr[4][2];
#pragma unroll
            for (int p2 = 0; p2 < 2; p2++) {
                int row = wn * 32 + p2 * 16 + (lg >> 1) * 8 + lr;
                int col = ks + (lg & 1) * 8;
                ldsm_x4(bfr[p2 * 2][0], bfr[p2 * 2][1], bfr[p2 * 2 + 1][0], bfr[p2 * 2 + 1][1],
                        sB + (uint32_t)(row * 40 + col) * 2u);
            }
#pragma unroll
            for (int mt = 0; mt < 2; mt++)
#pragma unroll
                for (int nt = 0; nt < 4; nt++)
                    mma16816(acc[mt][nt], af[mt], bfr[nt]);
        }
        __syncthreads();
    }

    if (att_src) {
        // layer1 epilogue: fp16 store + fused attention logits (warp = 1 head)
        const int h = blockIdx.x * 2 + wn;
        float wsv[4][2], wdv[4][2];
#pragma unroll
        for (int nt = 0; nt < 4; nt++) {
            int c = nt * 8 + tig * 2;
            wsv[nt][0] = att_src[h * 32 + c];     wsv[nt][1] = att_src[h * 32 + c + 1];
            wdv[nt][0] = att_dst[h * 32 + c];     wdv[nt][1] = att_dst[h * 32 + c + 1];
        }
#pragma unroll
        for (int mt = 0; mt < 2; mt++) {
            float ps_lo = 0.f, ps_hi = 0.f, pd_lo = 0.f, pd_hi = 0.f;
#pragma unroll
            for (int nt = 0; nt < 4; nt++) {
                ps_lo += acc[mt][nt][0] * wsv[nt][0] + acc[mt][nt][1] * wsv[nt][1];
                ps_hi += acc[mt][nt][2] * wsv[nt][0] + acc[mt][nt][3] * wsv[nt][1];
                pd_lo += acc[mt][nt][0] * wdv[nt][0] + acc[mt][nt][1] * wdv[nt][1];
                pd_hi += acc[mt][nt][2] * wdv[nt][0] + acc[mt][nt][3] * wdv[nt][1];
            }
#pragma unroll
            for (int o = 1; o <= 2; o <<= 1) {
                ps_lo += __shfl_xor_sync(0xffffffffu, ps_lo, o);
                ps_hi += __shfl_xor_sync(0xffffffffu, ps_hi, o);
                pd_lo += __shfl_xor_sync(0xffffffffu, pd_lo, o);
                pd_hi += __shfl_xor_sync(0xffffffffu, pd_hi, o);
            }
            int row = m0 + wm * 32 + mt * 16 + gid;
            if (tig == 0) {
                if (row < M)     { asrc_o[row * 8 + h] = ps_lo; adst_o[row * 8 + h] = pd_lo; }
                if (row + 8 < M) { asrc_o[(row + 8) * 8 + h] = ps_hi; adst_o[(row + 8) * 8 + h] = pd_hi; }
            }
#pragma unroll
            for (int nt = 0; nt < 4; nt++) {
                int col = n0 + wn * 32 + nt * 8 + tig * 2;
                if (row < M) {
                    uint32_t pk = ((uint32_t)f2h(acc[mt][nt][1]) << 16) | f2h(acc[mt][nt][0]);
                    *(uint32_t*)&Ch[(size_t)row * Nc + col] = pk;
                }
                if (row + 8 < M) {
                    uint32_t pk = ((uint32_t)f2h(acc[mt][nt][3]) << 16) | f2h(acc[mt][nt][2]);
                    *(uint32_t*)&Ch[(size_t)(row + 8) * Nc + col] = pk;
                }
            }
        }
    } else {
#pragma unroll
        for (int mt = 0; mt < 2; mt++) {
#pragma unroll
            for (int nt = 0; nt < 4; nt++) {
                int row = m0 + wm * 32 + mt * 16 + gid;
                int col = n0 + wn * 32 + nt * 8 + tig * 2;
                if (row < M)
                    *(float2*)&C[(size_t)row * Nc + col] = make_float2(acc[mt][nt][0], acc[mt][nt][1]);
                if (row + 8 < M)
                    *(float2*)&C[(size_t)(row + 8) * Nc + col] = make_float2(acc[mt][nt][2], acc[mt][nt][3]);
            }
        }
    }
}

// ---------------- CSR build ---------------------------------------------------
__global__ void k_count(const void* __restrict__ ei, int e, int n) {
    int i = blockIdx.x * blockDim.x + threadIdx.x;
    if (i >= e + n) return;
    int is64 = g_is64;
    int d = (i < e) ? load_idx(ei, (long long)e + i, is64) : (i - e);
    atomicAdd(&g_deg[d], 1);
}

// full-chip 3-phase exclusive scan of g_deg -> g_rowptr/g_pos
__device__ __forceinline__ int block_incl_scan(int v, int t) {
    __shared__ int ws[8];
    int lane = t & 31, wid = t >> 5;
    int incl = v;
#pragma unroll
    for (int o = 1; o < 32; o <<= 1) {
        int u = __shfl_up_sync(0xffffffffu, incl, o);
        if (lane >= o) incl += u;
    }
    if (lane == 31) ws[wid] = incl;
    __syncthreads();
    if (wid == 0) {
        int w = (lane < 8) ? ws[lane] : 0;
#pragma unroll
        for (int o = 1; o < 8; o <<= 1) {
            int u = __shfl_up_sync(0xffffffffu, w, o);
            if (lane >= o) w += u;
        }
        if (lane < 8) ws[lane] = w;
    }
    __syncthreads();
    return incl + (wid > 0 ? ws[wid - 1] : 0);
}

__global__ void __launch_bounds__(SCAN_B) k_scan_a(int n) {
    int t = threadIdx.x;
    int i = blockIdx.x * SCAN_B + t;
    int v = (i < n) ? g_deg[i] : 0;
    int incl = block_incl_scan(v, t);
    if (i < n) g_rowptr[i] = incl - v;      // block-local exclusive
    if (t == SCAN_B - 1) g_bsum[blockIdx.x] = incl;
}

__global__ void __launch_bounds__(SCAN_B) k_scan_b(int nb, int n) {
    int t = threadIdx.x;
    int v = (t < nb) ? g_bsum[t] : 0;
    int incl = block_incl_scan(v, t);
    if (t < nb) g_boff[t] = incl - v;       // exclusive block offsets
    if (t == SCAN_B - 1) g_rowptr[n] = incl;
}

__global__ void __launch_bounds__(SCAN_B) k_scan_c(int n) {
    int i = blockIdx.x * SCAN_B + threadIdx.x;
    if (i < n) {
        int r = g_rowptr[i] + g_boff[blockIdx.x];
        g_rowptr[i] = r;
        g_pos[i] = r;
    }
}

__global__ void k_scatter(const void* __restrict__ ei, int e, int n) {
    int i = blockIdx.x * blockDim.x + threadIdx.x;
    if (i >= e + n) return;
    int is64 = g_is64;
    int s, d;
    if (i < e) { s = load_idx(ei, i, is64); d = load_idx(ei, (long long)e + i, is64); }
    else       { s = i - e;                 d = i - e; }
    int p = atomicAdd(&g_pos[d], 1);
    g_ssrc[p] = s;
}

// ---------------- layer1 agg: fused exp + gather + bias + ELU -> bf16 split ---
__global__ void __launch_bounds__(256) k_agg1(const float* __restrict__ bias1) {
    int t = threadIdx.x;
    int u = t & 63;
    int d = blockIdx.x * 4 + (t >> 6);
    int h = u >> 3;
    int r0 = g_rowptr[d], r1 = g_rowptr[d + 1];
    float ad = g_adst1[d * 8 + h];
    const ushort4* Hh = (const ushort4*)g_h1h;
    float4 acc = make_float4(0.f, 0.f, 0.f, 0.f);
    float wsum = 0.f;
    int p = r0;
    for (; p + 2 <= r1; p += 2) {
        int s0 = g_ssrc[p], s1 = g_ssrc[p + 1];
        float e0 = g_asrc1[s0 * 8 + h] + ad;
        float e1 = g_asrc1[s1 * 8 + h] + ad;
        e0 = e0 > 0.f ? e0 : 0.2f * e0;
        e1 = e1 > 0.f ? e1 : 0.2f * e1;
        float w0 = __expf(e0), w1 = __expf(e1);
        ushort4 v0 = Hh[s0 * 64 + u];
        ushort4 v1 = Hh[s1 * 64 + u];
        acc.x += w0 * h2f(v0.x) + w1 * h2f(v1.x);
        acc.y += w0 * h2f(v0.y) + w1 * h2f(v1.y);
        acc.z += w0 * h2f(v0.z) + w1 * h2f(v1.z);
        acc.w += w0 * h2f(v0.w) + w1 * h2f(v1.w);
        wsum += w0 + w1;
    }
    if (p < r1) {
        int s0 = g_ssrc[p];
        float e0 = g_asrc1[s0 * 8 + h] + ad;
        e0 = e0 > 0.f ? e0 : 0.2f * e0;
        float w0 = __expf(e0);
        ushort4 v0 = Hh[s0 * 64 + u];
        acc.x += w0 * h2f(v0.x); acc.y += w0 * h2f(v0.y);
        acc.z += w0 * h2f(v0.z); acc.w += w0 * h2f(v0.w);
        wsum += w0;
    }
    float sinv = 1.f / (wsum + 1e-16f);
    float4 b = ((const float4*)bias1)[u];
    float4 o;
    o.x = acc.x * sinv + b.x; o.x = o.x > 0.f ? o.x : expm1f(o.x);
    o.y = acc.y * sinv + b.y; o.y = o.y > 0.f ? o.y : expm1f(o.y);
    o.z = acc.z * sinv + b.z; o.z = o.z > 0.f ? o.z : expm1f(o.z);
    o.w = acc.w * sinv + b.w; o.w = o.w > 0.f ? o.w : expm1f(o.w);
    ushort4 hi, lo;
    hi.x = f2bf(o.x); lo.x = f2bf(o.x - bf2f(hi.x));
    hi.y = f2bf(o.y); lo.y = f2bf(o.y - bf2f(hi.y));
    hi.z = f2bf(o.z); lo.z = f2bf(o.z - bf2f(hi.z));
    hi.w = f2bf(o.w); lo.w = f2bf(o.w - bf2f(hi.w));
    ((ushort4*)g_h2hi)[d * 64 + u] = hi;
    ((ushort4*)g_h2lo)[d * 64 + u] = lo;
}

// ---------------- layer2 attention logits (warp per node) ---------------------
__global__ void k_att2(const float* __restrict__ as2,
                       const float* __restrict__ ad2, int n)
{
    int w = (blockIdx.x * blockDim.x + threadIdx.x) >> 5;
    int lane = threadIdx.x & 31;
    if (w >= n) return;
    float v0 = g_h2[w * 64 + lane], v1 = g_h2[w * 64 + 32 + lane];
    float sa = v0 * as2[lane] + v1 * as2[32 + lane];
    float sd = v0 * ad2[lane] + v1 * ad2[32 + lane];
#pragma unroll
    for (int o = 16; o; o >>= 1) {
        sa += __shfl_xor_sync(0xffffffffu, sa, o);
        sd += __shfl_xor_sync(0xffffffffu, sd, o);
    }
    if (lane == 0) { g_asrc2[w] = sa; g_adst2[w] = sd; }
}

// ---------------- layer2 agg: fused exp + gather + bias -> output -------------
__global__ void __launch_bounds__(256) k_agg2(const float* __restrict__ bias2,
                                              float* __restrict__ out)
{
    int t = threadIdx.x;
    int u = t & 15;
    int d = blockIdx.x * 16 + (t >> 4);
    int r0 = g_rowptr[d], r1 = g_rowptr[d + 1];
    float ad = g_adst2[d];
    const float4* H = (const float4*)g_h2;
    float4 acc = make_float4(0.f, 0.f, 0.f, 0.f);
    float wsum = 0.f;
    int p = r0;
    for (; p + 2 <= r1; p += 2) {
        int s0 = g_ssrc[p], s1 = g_ssrc[p + 1];
        float e0 = g_asrc2[s0] + ad, e1 = g_asrc2[s1] + ad;
        e0 = e0 > 0.f ? e0 : 0.2f * e0;
        e1 = e1 > 0.f ? e1 : 0.2f * e1;
        float w0 = __expf(e0), w1 = __expf(e1);
        float4 v0 = H[s0 * 16 + u];
        float4 v1 = H[s1 * 16 + u];
        acc.x += w0 * v0.x + w1 * v1.x;
        acc.y += w0 * v0.y + w1 * v1.y;
        acc.z += w0 * v0.z + w1 * v1.z;
        acc.w += w0 * v0.w + w1 * v1.w;
        wsum += w0 + w1;
    }
    if (p < r1) {
        int s0 = g_ssrc[p];
        float e0 = g_asrc2[s0] + ad;
        e0 = e0 > 0.f ? e0 : 0.2f * e0;
        float w0 = __expf(e0);
        float4 v0 = H[s0 * 16 + u];
        acc.x += w0 * v0.x; acc.y += w0 * v0.y;
        acc.z += w0 * v0.z; acc.w += w0 * v0.w;
        wsum += w0;
    }
    float sinv = 1.f / (wsum + 1e-16f);
    float4 b = ((const float4*)bias2)[u];
    float4 o;
    o.x = acc.x * sinv + b.x;
    o.y = acc.y * sinv + b.y;
    o.z = acc.z * sinv + b.z;
    o.w = acc.w * sinv + b.w;
    ((float4*)out)[d * 16 + u] = o;
}

// ------------------------------------------------------------------------------
extern "C" void kernel_launch(void* const* d_in, const int* in_sizes, int n_in,
                              void* d_out, int out_size)
{
    const float* x   = (const float*)d_in[0];
    const void*  ei  = d_in[1];
    const float* W1  = (const float*)d_in[3];
    const float* as1 = (const float*)d_in[4];
    const float* ad1 = (const float*)d_in[5];
    const float* b1  = (const float*)d_in[6];
    const float* W2  = (const float*)d_in[7];
    const float* as2 = (const float*)d_in[8];
    const float* ad2 = (const float*)d_in[9];
    const float* b2  = (const float*)d_in[10];
    float* out = (float*)d_out;

    const int n  = in_sizes[0] / 128;   // 50000
    const int e  = in_sizes[1] / 2;     // 800000
    const int et = e + n;
    const int nb = (n + SCAN_B - 1) / SCAN_B;   // 196

    float *h2, *asrc1, *adst1;
    unsigned short *h1h, *xhi, *xlo, *b1catT, *h2hi, *h2lo, *b2catT;
    cudaGetSymbolAddress((void**)&h2,     g_h2);
    cudaGetSymbolAddress((void**)&asrc1,  g_asrc1);
    cudaGetSymbolAddress((void**)&adst1,  g_adst1);
    cudaGetSymbolAddress((void**)&h1h,    g_h1h);
    cudaGetSymbolAddress((void**)&xhi,    g_xhi);
    cudaGetSymbolAddress((void**)&xlo,    g_xlo);
    cudaGetSymbolAddress((void**)&b1catT, g_b1catT);
    cudaGetSymbolAddress((void**)&h2hi,   g_h2hi);
    cudaGetSymbolAddress((void**)&h2lo,   g_h2lo);
    cudaGetSymbolAddress((void**)&b2catT, g_b2catT);

    // one-time host-side stream/event setup (no device memory involved)
    static cudaStream_t s_side = nullptr;
    static cudaEvent_t s_evF = nullptr, s_evJ = nullptr;
    if (!s_side) {
        cudaStreamCreateWithFlags(&s_side, cudaStreamNonBlocking);
        cudaEventCreateWithFlags(&s_evF, cudaEventDisableTiming);
        cudaEventCreateWithFlags(&s_evJ, cudaEventDisableTiming);
    }

    int nf4 = n * 32;
    k_prep<<<(nf4 + 255) / 256, 256>>>((const int*)ei, x, W1, W2, n, nf4);

    // fork: CSR chain on side stream, GEMM1 on main stream (independent)
    cudaEventRecord(s_evF, 0);
    cudaStreamWaitEvent(s_side, s_evF, 0);

    k_count<<<(et + 255) / 256, 256, 0, s_side>>>(ei, e, n);
    k_scan_a<<<nb, SCAN_B, 0, s_side>>>(n);
    k_scan_b<<<1, SCAN_B, 0, s_side>>>(nb, n);
    k_scan_c<<<nb, SCAN_B, 0, s_side>>>(n);
    k_scatter<<<(et + 255) / 256, 256, 0, s_side>>>(ei, e, n);
    cudaEventRecord(s_evJ, s_side);

    // layer1 GEMM + fused att1 logits (fp16 h1 output only) — main stream
    k_gemm_bf16<<<dim3(4, (n + 127) / 128), 256>>>(
        xhi, xlo, b1catT, (float*)nullptr, h1h, as1, ad1, asrc1, adst1, n, 256, 128);

    // join: agg1 needs both CSR (side) and h1h/logits (main)
    cudaStreamWaitEvent(0, s_evJ, 0);

    // layer1 aggregation (fused softmax)
    k_agg1<<<(n + 3) / 4, 256>>>(b1);

    // layer2 GEMM: h2 = elu_out @ W2 (fp32 output)
    k_gemm_bf16<<<dim3(1, (n + 127) / 128), 256>>>(
        h2hi, h2lo, b2catT, h2, (unsigned short*)nullptr,
        (const float*)nullptr, (const float*)nullptr, (float*)nullptr, (float*)nullptr,
        n, 64, 256);

    k_att2<<<(n * 32 + 255) / 256, 256>>>(as2, ad2, n);
    k_agg2<<<(n + 15) / 16, 256>>>(b2, out);
}

// round 14
// speedup vs baseline: 2.6203x; 1.0307x over previous
#include <cuda_runtime.h>
#include <cuda_bf16.h>
#include <cuda_fp16.h>
#include <cstdint>

#define NN 50000
#define NE 800000
#define NET (NN + NE)
#define SCAN_B 256

// ---------------- scratch (static device globals; no allocation) -------------
__device__ float g_asrc1[NN * 8];
__device__ float g_adst1[NN * 8];
__device__ float g_asrc2[NN];
__device__ float g_adst2[NN];
__device__ int   g_deg[NN];
__device__ int   g_rowptr[NN + 1];
__device__ int   g_pos[NN];
__device__ int   g_ssrc[NET];
__device__ int   g_bsum[SCAN_B];
__device__ int   g_boff[SCAN_B];
__device__ int   g_is64;

// half/bf16 operands
__device__ unsigned short g_h1h[NN * 256];      // fp16 h1
__device__ unsigned short g_h2h[NN * 64];       // fp16 h2 (only h2 representation)
__device__ unsigned short g_xhi[NN * 128];
__device__ unsigned short g_xlo[NN * 128];
__device__ unsigned short g_b1catT[256 * 384];  // [n][3K]: hi|hi|lo, K=128
__device__ unsigned short g_h2hi[NN * 256];
__device__ unsigned short g_h2lo[NN * 256];
__device__ unsigned short g_b2catT[64 * 768];   // [n][3K], K=256

__device__ __forceinline__ unsigned short f2bf(float x) {
    __nv_bfloat16 b = __float2bfloat16_rn(x);
    return *(unsigned short*)&b;
}
__device__ __forceinline__ float bf2f(unsigned short u) {
    unsigned int v = ((unsigned int)u) << 16;
    return __uint_as_float(v);
}
__device__ __forceinline__ unsigned short f2h(float x) {
    __half h = __float2half_rn(x);
    return *(unsigned short*)&h;
}
__device__ __forceinline__ float h2f(unsigned short u) {
    __half h = *(__half*)&u;
    return __half2float(h);
}

__device__ __forceinline__ int load_idx(const void* ei, long long pos, int is64) {
    if (is64) return (int)((const long long*)ei)[pos];
    return ((const int*)ei)[pos];
}

// ---------------- prep0: zero + detect (tiny, unblocks CSR side chain) --------
__global__ void k_prep0(const int* __restrict__ w, int n) {
    int i = blockIdx.x * blockDim.x + threadIdx.x;
    if (i < n) { g_deg[i] = 0; g_asrc2[i] = 0.f; g_adst2[i] = 0.f; }
    if (i == 0) {
        int all0 = 1;
        for (int j = 1; j < 200; j += 2)
            if (w[j] != 0) { all0 = 0; break; }
        g_is64 = all0;
    }
}

// ---------------- conversions: x hi/lo + W1/W2 transposed cat -----------------
__global__ void k_conv(const float* __restrict__ x,
                       const float* __restrict__ W1, const float* __restrict__ W2,
                       int nf4)
{
    int i = blockIdx.x * blockDim.x + threadIdx.x;
    if (i < nf4) {
        float4 v = ((const float4*)x)[i];
        ushort4 hi, lo;
        hi.x = f2bf(v.x); lo.x = f2bf(v.x - bf2f(hi.x));
        hi.y = f2bf(v.y); lo.y = f2bf(v.y - bf2f(hi.y));
        hi.z = f2bf(v.z); lo.z = f2bf(v.z - bf2f(hi.z));
        hi.w = f2bf(v.w); lo.w = f2bf(v.w - bf2f(hi.w));
        ((ushort4*)g_xhi)[i] = hi;
        ((ushort4*)g_xlo)[i] = lo;
    }
    if (i < 32768) {
        int k = i >> 8, nn = i & 255;
        float wv = W1[i];
        unsigned short hi = f2bf(wv);
        unsigned short lo = f2bf(wv - bf2f(hi));
        unsigned short* r = &g_b1catT[nn * 384];
        r[k] = hi; r[128 + k] = hi; r[256 + k] = lo;
    } else if (i < 32768 + 16384) {
        int j = i - 32768;
        int k = j >> 6, nn = j & 63;
        float wv = W2[j];
        unsigned short hi = f2bf(wv);
        unsigned short lo = f2bf(wv - bf2f(hi));
        unsigned short* r = &g_b2catT[nn * 768];
        r[k] = hi; r[256 + k] = hi; r[512 + k] = lo;
    }
}

// ---------------- bf16 split tensor-core GEMM (cp.async) ----------------------
// att_mode: 0 = none (fp32 C store); 1 = layer1 (fp16 Ch + per-warp-head logits);
//           2 = layer2 (fp16 Ch + single-head logits via atomics)
__device__ __forceinline__ void mma16816(float* d, const uint32_t* a, const uint32_t* b) {
    asm volatile(
        "mma.sync.aligned.m16n8k16.row.col.f32.bf16.bf16.f32 "
        "{%0,%1,%2,%3}, {%4,%5,%6,%7}, {%8,%9}, {%0,%1,%2,%3};"
        : "+f"(d[0]), "+f"(d[1]), "+f"(d[2]), "+f"(d[3])
        : "r"(a[0]), "r"(a[1]), "r"(a[2]), "r"(a[3]), "r"(b[0]), "r"(b[1]));
}

__device__ __forceinline__ void ldsm_x4(uint32_t& r0, uint32_t& r1, uint32_t& r2, uint32_t& r3, uint32_t addr) {
    asm volatile("ldmatrix.sync.aligned.m8n8.x4.shared.b16 {%0,%1,%2,%3}, [%4];"
                 : "=r"(r0), "=r"(r1), "=r"(r2), "=r"(r3) : "r"(addr));
}

__device__ __forceinline__ void cpa16(uint32_t dst, const void* src, int srcsz) {
    asm volatile("cp.async.cg.shared.global [%0], [%1], 16, %2;"
                 :: "r"(dst), "l"(src), "r"(srcsz));
}

__global__ void __launch_bounds__(256) k_gemm_bf16(
    const unsigned short* __restrict__ Ahi, const unsigned short* __restrict__ Alo,
    const unsigned short* __restrict__ BcatT, float* __restrict__ C,
    unsigned short* __restrict__ Ch,
    const float* __restrict__ att_src, const float* __restrict__ att_dst,
    float* __restrict__ asrc_o, float* __restrict__ adst_o,
    int att_mode, int M, int Nc, int Kp)
{
    __shared__ unsigned short As[2][128][40];
    __shared__ unsigned short Bs[2][64][40];
    const int t = threadIdx.x;
    const int wid = t >> 5, lane = t & 31;
    const int gid = lane >> 2, tig = lane & 3;
    const int wm = wid & 3, wn = wid >> 2;
    const int m0 = blockIdx.y * 128, n0 = blockIdx.x * 64;
    const int cpp = Kp >> 5;
    const int nch = 3 * cpp;
    const int K3 = 3 * Kp;

    const int lr = lane & 7, lg = lane >> 3;
    const int segA = t & 3, rowA = t >> 2;
    const int nB = t >> 2, ksegB = t & 3;

    float acc[2][4][4];
#pragma unroll
    for (int a = 0; a < 2; a++)
#pragma unroll
        for (int b = 0; b < 4; b++)
#pragma unroll
            for (int c = 0; c < 4; c++) acc[a][b][c] = 0.f;

    auto issue = [&](int cc, int st) {
        int phase = cc / cpp;
        int kloc = (cc - phase * cpp) * 32;
        const unsigned short* Ap = (phase == 1) ? Alo : Ahi;
#pragma unroll
        for (int half = 0; half < 2; half++) {
            int r = rowA + half * 64;
            int m = m0 + r;
            uint32_t d = (uint32_t)__cvta_generic_to_shared(&As[st][r][segA * 8]);
            cpa16(d, Ap + (size_t)m * Kp + kloc + segA * 8, (m < M) ? 16 : 0);
        }
        {
            uint32_t d = (uint32_t)__cvta_generic_to_shared(&Bs[st][nB][ksegB * 8]);
            cpa16(d, BcatT + (size_t)(n0 + nB) * K3 + cc * 32 + ksegB * 8, 16);
        }
        asm volatile("cp.async.commit_group;");
    };

    issue(0, 0);
    for (int cc = 0; cc < nch; cc++) {
        int st = cc & 1;
        if (cc + 1 < nch) {
            issue(cc + 1, st ^ 1);
            asm volatile("cp.async.wait_group 1;");
        } else {
            asm volatile("cp.async.wait_group 0;");
        }
        __syncthreads();
        const uint32_t sA = (uint32_t)__cvta_generic_to_shared(&As[st][0][0]);
        const uint32_t sB = (uint32_t)__cvta_generic_to_shared(&Bs[st][0][0]);
#pragma unroll
        for (int ks = 0; ks < 32; ks += 16) {
            uint32_t af[2][4];
#pragma unroll
            for (int mt = 0; mt < 2; mt++) {
                int row = wm * 32 + mt * 16 + (lg & 1) * 8 + lr;
                int col = ks + (lg >> 1) * 8;
                ldsm_x4(af[mt][0], af[mt][1], af[mt][2], af[mt][3],
                        sA + (uint32_t)(row * 40 + col) * 2u);
            }
            uint32_t bfr[4][2];
#pragma unroll
            for (int p2 = 0; p2 < 2; p2++) {
                int row = wn * 32 + p2 * 16 + (lg >> 1) * 8 + lr;
                int col = ks + (lg & 1) * 8;
                ldsm_x4(bfr[p2 * 2][0], bfr[p2 * 2][1], bfr[p2 * 2 + 1][0], bfr[p2 * 2 + 1][1],
                        sB + (uint32_t)(row * 40 + col) * 2u);
            }
#pragma unroll
            for (int mt = 0; mt < 2; mt++)
#pragma unroll
                for (int nt = 0; nt < 4; nt++)
                    mma16816(acc[mt][nt], af[mt], bfr[nt]);
        }
        __syncthreads();
    }

    if (att_mode) {
        // att weights for this warp's 32-column span
        const int cb = (att_mode == 1) ? ((blockIdx.x * 2 + wn) * 32) : (wn * 32);
        float wsv[4][2], wdv[4][2];
#pragma unroll
        for (int nt = 0; nt < 4; nt++) {
            int c = cb + nt * 8 + tig * 2;
            wsv[nt][0] = att_src[c]; wsv[nt][1] = att_src[c + 1];
            wdv[nt][0] = att_dst[c]; wdv[nt][1] = att_dst[c + 1];
        }
#pragma unroll
        for (int mt = 0; mt < 2; mt++) {
            float ps_lo = 0.f, ps_hi = 0.f, pd_lo = 0.f, pd_hi = 0.f;
#pragma unroll
            for (int nt = 0; nt < 4; nt++) {
                ps_lo += acc[mt][nt][0] * wsv[nt][0] + acc[mt][nt][1] * wsv[nt][1];
                ps_hi += acc[mt][nt][2] * wsv[nt][0] + acc[mt][nt][3] * wsv[nt][1];
                pd_lo += acc[mt][nt][0] * wdv[nt][0] + acc[mt][nt][1] * wdv[nt][1];
                pd_hi += acc[mt][nt][2] * wdv[nt][0] + acc[mt][nt][3] * wdv[nt][1];
            }
#pragma unroll
            for (int o = 1; o <= 2; o <<= 1) {
                ps_lo += __shfl_xor_sync(0xffffffffu, ps_lo, o);
                ps_hi += __shfl_xor_sync(0xffffffffu, ps_hi, o);
                pd_lo += __shfl_xor_sync(0xffffffffu, pd_lo, o);
                pd_hi += __shfl_xor_sync(0xffffffffu, pd_hi, o);
            }
            int row = m0 + wm * 32 + mt * 16 + gid;
            if (tig == 0) {
                if (att_mode == 1) {
                    int h = blockIdx.x * 2 + wn;
                    if (row < M)     { asrc_o[row * 8 + h] = ps_lo; adst_o[row * 8 + h] = pd_lo; }
                    if (row + 8 < M) { asrc_o[(row + 8) * 8 + h] = ps_hi; adst_o[(row + 8) * 8 + h] = pd_hi; }
                } else {
                    if (row < M)     { atomicAdd(&asrc_o[row], ps_lo); atomicAdd(&adst_o[row], pd_lo); }
                    if (row + 8 < M) { atomicAdd(&asrc_o[row + 8], ps_hi); atomicAdd(&adst_o[row + 8], pd_hi); }
                }
            }
#pragma unroll
            for (int nt = 0; nt < 4; nt++) {
                int col = n0 + wn * 32 + nt * 8 + tig * 2;
                if (row < M) {
                    uint32_t pk = ((uint32_t)f2h(acc[mt][nt][1]) << 16) | f2h(acc[mt][nt][0]);
                    *(uint32_t*)&Ch[(size_t)row * Nc + col] = pk;
                }
                if (row + 8 < M) {
                    uint32_t pk = ((uint32_t)f2h(acc[mt][nt][3]) << 16) | f2h(acc[mt][nt][2]);
                    *(uint32_t*)&Ch[(size_t)(row + 8) * Nc + col] = pk;
                }
            }
        }
    } else {
#pragma unroll
        for (int mt = 0; mt < 2; mt++) {
#pragma unroll
            for (int nt = 0; nt < 4; nt++) {
                int row = m0 + wm * 32 + mt * 16 + gid;
                int col = n0 + wn * 32 + nt * 8 + tig * 2;
                if (row < M)
                    *(float2*)&C[(size_t)row * Nc + col] = make_float2(acc[mt][nt][0], acc[mt][nt][1]);
                if (row + 8 < M)
                    *(float2*)&C[(size_t)(row + 8) * Nc + col] = make_float2(acc[mt][nt][2], acc[mt][nt][3]);
            }
        }
    }
}

// ---------------- CSR build ---------------------------------------------------
__global__ void k_count(const void* __restrict__ ei, int e, int n) {
    int i = blockIdx.x * blockDim.x + threadIdx.x;
    if (i >= e + n) return;
    int is64 = g_is64;
    int d = (i < e) ? load_idx(ei, (long long)e + i, is64) : (i - e);
    atomicAdd(&g_deg[d], 1);
}

__device__ __forceinline__ int block_incl_scan(int v, int t) {
    __shared__ int ws[8];
    int lane = t & 31, wid = t >> 5;
    int incl = v;
#pragma unroll
    for (int o = 1; o < 32; o <<= 1) {
        int u = __shfl_up_sync(0xffffffffu, incl, o);
        if (lane >= o) incl += u;
    }
    if (lane == 31) ws[wid] = incl;
    __syncthreads();
    if (wid == 0) {
        int w = (lane < 8) ? ws[lane] : 0;
#pragma unroll
        for (int o = 1; o < 8; o <<= 1) {
            int u = __shfl_up_sync(0xffffffffu, w, o);
            if (lane >= o) w += u;
        }
        if (lane < 8) ws[lane] = w;
    }
    __syncthreads();
    return incl + (wid > 0 ? ws[wid - 1] : 0);
}

__global__ void __launch_bounds__(SCAN_B) k_scan_a(int n) {
    int t = threadIdx.x;
    int i = blockIdx.x * SCAN_B + t;
    int v = (i < n) ? g_deg[i] : 0;
    int incl = block_incl_scan(v, t);
    if (i < n) g_rowptr[i] = incl - v;
    if (t == SCAN_B - 1) g_bsum[blockIdx.x] = incl;
}

__global__ void __launch_bounds__(SCAN_B) k_scan_b(int nb, int n) {
    int t = threadIdx.x;
    int v = (t < nb) ? g_bsum[t] : 0;
    int incl = block_incl_scan(v, t);
    if (t < nb) g_boff[t] = incl - v;
    if (t == SCAN_B - 1) g_rowptr[n] = incl;
}

__global__ void __launch_bounds__(SCAN_B) k_scan_c(int n) {
    int i = blockIdx.x * SCAN_B + threadIdx.x;
    if (i < n) {
        int r = g_rowptr[i] + g_boff[blockIdx.x];
        g_rowptr[i] = r;
        g_pos[i] = r;
    }
}

__global__ void k_scatter(const void* __restrict__ ei, int e, int n) {
    int i = blockIdx.x * blockDim.x + threadIdx.x;
    if (i >= e + n) return;
    int is64 = g_is64;
    int s, d;
    if (i < e) { s = load_idx(ei, i, is64); d = load_idx(ei, (long long)e + i, is64); }
    else       { s = i - e;                 d = i - e; }
    int p = atomicAdd(&g_pos[d], 1);
    g_ssrc[p] = s;
}

// ---------------- layer1 agg: fused exp + gather + bias + ELU -> bf16 split ---
__global__ void __launch_bounds__(256) k_agg1(const float* __restrict__ bias1) {
    int t = threadIdx.x;
    int u = t & 63;
    int d = blockIdx.x * 4 + (t >> 6);
    int h = u >> 3;
    int r0 = g_rowptr[d], r1 = g_rowptr[d + 1];
    float ad = g_adst1[d * 8 + h];
    const ushort4* Hh = (const ushort4*)g_h1h;
    float4 acc = make_float4(0.f, 0.f, 0.f, 0.f);
    float wsum = 0.f;
    int p = r0;
    for (; p + 2 <= r1; p += 2) {
        int s0 = g_ssrc[p], s1 = g_ssrc[p + 1];
        float e0 = g_asrc1[s0 * 8 + h] + ad;
        float e1 = g_asrc1[s1 * 8 + h] + ad;
        e0 = e0 > 0.f ? e0 : 0.2f * e0;
        e1 = e1 > 0.f ? e1 : 0.2f * e1;
        float w0 = __expf(e0), w1 = __expf(e1);
        ushort4 v0 = Hh[s0 * 64 + u];
        ushort4 v1 = Hh[s1 * 64 + u];
        acc.x += w0 * h2f(v0.x) + w1 * h2f(v1.x);
        acc.y += w0 * h2f(v0.y) + w1 * h2f(v1.y);
        acc.z += w0 * h2f(v0.z) + w1 * h2f(v1.z);
        acc.w += w0 * h2f(v0.w) + w1 * h2f(v1.w);
        wsum += w0 + w1;
    }
    if (p < r1) {
        int s0 = g_ssrc[p];
        float e0 = g_asrc1[s0 * 8 + h] + ad;
        e0 = e0 > 0.f ? e0 : 0.2f * e0;
        float w0 = __expf(e0);
        ushort4 v0 = Hh[s0 * 64 + u];
        acc.x += w0 * h2f(v0.x); acc.y += w0 * h2f(v0.y);
        acc.z += w0 * h2f(v0.z); acc.w += w0 * h2f(v0.w);
        wsum += w0;
    }
    float sinv = 1.f / (wsum + 1e-16f);
    float4 b = ((const float4*)bias1)[u];
    float4 o;
    o.x = acc.x * sinv + b.x; o.x = o.x > 0.f ? o.x : expm1f(o.x);
    o.y = acc.y * sinv + b.y; o.y = o.y > 0.f ? o.y : expm1f(o.y);
    o.z = acc.z * sinv + b.z; o.z = o.z > 0.f ? o.z : expm1f(o.z);
    o.w = acc.w * sinv + b.w; o.w = o.w > 0.f ? o.w : expm1f(o.w);
    ushort4 hi, lo;
    hi.x = f2bf(o.x); lo.x = f2bf(o.x - bf2f(hi.x));
    hi.y = f2bf(o.y); lo.y = f2bf(o.y - bf2f(hi.y));
    hi.z = f2bf(o.z); lo.z = f2bf(o.z - bf2f(hi.z));
    hi.w = f2bf(o.w); lo.w = f2bf(o.w - bf2f(hi.w));
    ((ushort4*)g_h2hi)[d * 64 + u] = hi;
    ((ushort4*)g_h2lo)[d * 64 + u] = lo;
}

// ---------------- layer2 agg: fused exp + fp16 gather + bias -> output --------
__global__ void __launch_bounds__(256) k_agg2(const float* __restrict__ bias2,
                                              float* __restrict__ out)
{
    int t = threadIdx.x;
    int u = t & 15;
    int d = blockIdx.x * 16 + (t >> 4);
    int r0 = g_rowptr[d], r1 = g_rowptr[d + 1];
    float ad = g_adst2[d];
    const ushort4* Hh = (const ushort4*)g_h2h;
    float4 acc = make_float4(0.f, 0.f, 0.f, 0.f);
    float wsum = 0.f;
    int p = r0;
    for (; p + 2 <= r1; p += 2) {
        int s0 = g_ssrc[p], s1 = g_ssrc[p + 1];
        float e0 = g_asrc2[s0] + ad, e1 = g_asrc2[s1] + ad;
        e0 = e0 > 0.f ? e0 : 0.2f * e0;
        e1 = e1 > 0.f ? e1 : 0.2f * e1;
        float w0 = __expf(e0), w1 = __expf(e1);
        ushort4 v0 = Hh[s0 * 16 + u];
        ushort4 v1 = Hh[s1 * 16 + u];
        acc.x += w0 * h2f(v0.x) + w1 * h2f(v1.x);
        acc.y += w0 * h2f(v0.y) + w1 * h2f(v1.y);
        acc.z += w0 * h2f(v0.z) + w1 * h2f(v1.z);
        acc.w += w0 * h2f(v0.w) + w1 * h2f(v1.w);
        wsum += w0 + w1;
    }
    if (p < r1) {
        int s0 = g_ssrc[p];
        float e0 = g_asrc2[s0] + ad;
        e0 = e0 > 0.f ? e0 : 0.2f * e0;
        float w0 = __expf(e0);
        ushort4 v0 = Hh[s0 * 16 + u];
        acc.x += w0 * h2f(v0.x); acc.y += w0 * h2f(v0.y);
        acc.z += w0 * h2f(v0.z); acc.w += w0 * h2f(v0.w);
        wsum += w0;
    }
    float sinv = 1.f / (wsum + 1e-16f);
    float4 b = ((const float4*)bias2)[u];
    float4 o;
    o.x = acc.x * sinv + b.x;
    o.y = acc.y * sinv + b.y;
    o.z = acc.z * sinv + b.z;
    o.w = acc.w * sinv + b.w;
    ((float4*)out)[d * 16 + u] = o;
}

// ------------------------------------------------------------------------------
extern "C" void kernel_launch(void* const* d_in, const int* in_sizes, int n_in,
                              void* d_out, int out_size)
{
    const float* x   = (const float*)d_in[0];
    const void*  ei  = d_in[1];
    const float* W1  = (const float*)d_in[3];
    const float* as1 = (const float*)d_in[4];
    const float* ad1 = (const float*)d_in[5];
    const float* b1  = (const float*)d_in[6];
    const float* W2  = (const float*)d_in[7];
    const float* as2 = (const float*)d_in[8];
    const float* ad2 = (const float*)d_in[9];
    const float* b2  = (const float*)d_in[10];
    float* out = (float*)d_out;

    const int n  = in_sizes[0] / 128;   // 50000
    const int e  = in_sizes[1] / 2;     // 800000
    const int et = e + n;
    const int nb = (n + SCAN_B - 1) / SCAN_B;

    float *asrc1, *adst1, *asrc2, *adst2;
    unsigned short *h1h, *h2h, *xhi, *xlo, *b1catT, *h2hi, *h2lo, *b2catT;
    cudaGetSymbolAddress((void**)&asrc1,  g_asrc1);
    cudaGetSymbolAddress((void**)&adst1,  g_adst1);
    cudaGetSymbolAddress((void**)&asrc2,  g_asrc2);
    cudaGetSymbolAddress((void**)&adst2,  g_adst2);
    cudaGetSymbolAddress((void**)&h1h,    g_h1h);
    cudaGetSymbolAddress((void**)&h2h,    g_h2h);
    cudaGetSymbolAddress((void**)&xhi,    g_xhi);
    cudaGetSymbolAddress((void**)&xlo,    g_xlo);
    cudaGetSymbolAddress((void**)&b1catT, g_b1catT);
    cudaGetSymbolAddress((void**)&h2hi,   g_h2hi);
    cudaGetSymbolAddress((void**)&h2lo,   g_h2lo);
    cudaGetSymbolAddress((void**)&b2catT, g_b2catT);

    static cudaStream_t s_side = nullptr;
    static cudaEvent_t s_evF = nullptr, s_evJ = nullptr;
    if (!s_side) {
        cudaStreamCreateWithFlags(&s_side, cudaStreamNonBlocking);
        cudaEventCreateWithFlags(&s_evF, cudaEventDisableTiming);
        cudaEventCreateWithFlags(&s_evJ, cudaEventDisableTiming);
    }

    int nf4 = n * 32;

    // tiny prep (zero + detect) then fork CSR chain immediately
    k_prep0<<<(n + 255) / 256, 256>>>((const int*)ei, n);
    cudaEventRecord(s_evF, 0);
    cudaStreamWaitEvent(s_side, s_evF, 0);

    k_count<<<(et + 255) / 256, 256, 0, s_side>>>(ei, e, n);
    k_scan_a<<<nb, SCAN_B, 0, s_side>>>(n);
    k_scan_b<<<1, SCAN_B, 0, s_side>>>(nb, n);
    k_scan_c<<<nb, SCAN_B, 0, s_side>>>(n);
    k_scatter<<<(et + 255) / 256, 256, 0, s_side>>>(ei, e, n);
    cudaEventRecord(s_evJ, s_side);

    // main stream: conversions + layer1 GEMM (+fused att1)
    k_conv<<<(nf4 + 255) / 256, 256>>>(x, W1, W2, nf4);
    k_gemm_bf16<<<dim3(4, (n + 127) / 128), 256>>>(
        xhi, xlo, b1catT, (float*)nullptr, h1h, as1, ad1, asrc1, adst1, 1, n, 256, 128);

    // join: agg1 needs CSR + h1h/logits
    cudaStreamWaitEvent(0, s_evJ, 0);
    k_agg1<<<(n + 3) / 4, 256>>>(b1);

    // layer2 GEMM (+fused att2 via atomics, fp16 h2 only)
    k_gemm_bf16<<<dim3(1, (n + 127) / 128), 256>>>(
        h2hi, h2lo, b2catT, (float*)nullptr, h2h, as2, ad2, asrc2, adst2, 2, n, 64, 256);

    k_agg2<<<(n + 15) / 16, 256>>>(b2, out);
}

// round 15
// speedup vs baseline: 2.7020x; 1.0312x over previous
#include <cuda_runtime.h>
#include <cuda_bf16.h>
#include <cuda_fp16.h>
#include <cstdint>

#define NN 50000
#define NE 800000
#define NET (NN + NE)
#define SCAN_B 256

// ---------------- scratch (static device globals; no allocation) -------------
__device__ float g_asrc1[NN * 8];
__device__ float g_adst1[NN * 8];
__device__ float g_asrc2[NN];
__device__ float g_adst2[NN];
__device__ int   g_deg[NN];
__device__ int   g_rowptr[NN + 1];
__device__ int   g_pos[NN];
__device__ int   g_ssrc[NET];
__device__ int   g_bsum[SCAN_B];
__device__ int   g_boff[SCAN_B];
__device__ int   g_is64;

// half/bf16 operands
__device__ unsigned short g_h1h[NN * 256];      // fp16 h1
__device__ unsigned short g_h2h[NN * 64];       // fp16 h2
__device__ unsigned short g_xhi[NN * 128];
__device__ unsigned short g_xlo[NN * 128];
__device__ unsigned short g_b1catT[256 * 384];  // [n][3K]: hi|hi|lo, K=128
__device__ unsigned short g_h2hi[NN * 256];
__device__ unsigned short g_h2lo[NN * 256];
__device__ unsigned short g_b2catT[64 * 768];   // [n][3K], K=256

__device__ __forceinline__ unsigned short f2bf(float x) {
    __nv_bfloat16 b = __float2bfloat16_rn(x);
    return *(unsigned short*)&b;
}
__device__ __forceinline__ float bf2f(unsigned short u) {
    unsigned int v = ((unsigned int)u) << 16;
    return __uint_as_float(v);
}
__device__ __forceinline__ unsigned short f2h(float x) {
    __half h = __float2half_rn(x);
    return *(unsigned short*)&h;
}
__device__ __forceinline__ float h2f(unsigned short u) {
    __half h = *(__half*)&u;
    return __half2float(h);
}

__device__ __forceinline__ int load_idx(const void* ei, long long pos, int is64) {
    if (is64) return (int)((const long long*)ei)[pos];
    return ((const int*)ei)[pos];
}

// ---------------- prep0: zero + detect ----------------------------------------
__global__ void k_prep0(const int* __restrict__ w, int n) {
    int i = blockIdx.x * blockDim.x + threadIdx.x;
    if (i < n) { g_deg[i] = 0; g_asrc2[i] = 0.f; g_adst2[i] = 0.f; }
    if (i == 0) {
        int all0 = 1;
        for (int j = 1; j < 200; j += 2)
            if (w[j] != 0) { all0 = 0; break; }
        g_is64 = all0;
    }
}

// ---------------- conversions --------------------------------------------------
__global__ void k_conv(const float* __restrict__ x,
                       const float* __restrict__ W1, const float* __restrict__ W2,
                       int nf4)
{
    int i = blockIdx.x * blockDim.x + threadIdx.x;
    if (i < nf4) {
        float4 v = ((const float4*)x)[i];
        ushort4 hi, lo;
        hi.x = f2bf(v.x); lo.x = f2bf(v.x - bf2f(hi.x));
        hi.y = f2bf(v.y); lo.y = f2bf(v.y - bf2f(hi.y));
        hi.z = f2bf(v.z); lo.z = f2bf(v.z - bf2f(hi.z));
        hi.w = f2bf(v.w); lo.w = f2bf(v.w - bf2f(hi.w));
        ((ushort4*)g_xhi)[i] = hi;
        ((ushort4*)g_xlo)[i] = lo;
    }
    if (i < 32768) {
        int k = i >> 8, nn = i & 255;
        float wv = W1[i];
        unsigned short hi = f2bf(wv);
        unsigned short lo = f2bf(wv - bf2f(hi));
        unsigned short* r = &g_b1catT[nn * 384];
        r[k] = hi; r[128 + k] = hi; r[256 + k] = lo;
    } else if (i < 32768 + 16384) {
        int j = i - 32768;
        int k = j >> 6, nn = j & 63;
        float wv = W2[j];
        unsigned short hi = f2bf(wv);
        unsigned short lo = f2bf(wv - bf2f(hi));
        unsigned short* r = &g_b2catT[nn * 768];
        r[k] = hi; r[256 + k] = hi; r[512 + k] = lo;
    }
}

// ---------------- bf16 split tensor-core GEMM (cp.async) ----------------------
__device__ __forceinline__ void mma16816(float* d, const uint32_t* a, const uint32_t* b) {
    asm volatile(
        "mma.sync.aligned.m16n8k16.row.col.f32.bf16.bf16.f32 "
        "{%0,%1,%2,%3}, {%4,%5,%6,%7}, {%8,%9}, {%0,%1,%2,%3};"
        : "+f"(d[0]), "+f"(d[1]), "+f"(d[2]), "+f"(d[3])
        : "r"(a[0]), "r"(a[1]), "r"(a[2]), "r"(a[3]), "r"(b[0]), "r"(b[1]));
}

__device__ __forceinline__ void ldsm_x4(uint32_t& r0, uint32_t& r1, uint32_t& r2, uint32_t& r3, uint32_t addr) {
    asm volatile("ldmatrix.sync.aligned.m8n8.x4.shared.b16 {%0,%1,%2,%3}, [%4];"
                 : "=r"(r0), "=r"(r1), "=r"(r2), "=r"(r3) : "r"(addr));
}

__device__ __forceinline__ void cpa16(uint32_t dst, const void* src, int srcsz) {
    asm volatile("cp.async.cg.shared.global [%0], [%1], 16, %2;"
                 :: "r"(dst), "l"(src), "r"(srcsz));
}

__global__ void __launch_bounds__(256) k_gemm_bf16(
    const unsigned short* __restrict__ Ahi, const unsigned short* __restrict__ Alo,
    const unsigned short* __restrict__ BcatT, float* __restrict__ C,
    unsigned short* __restrict__ Ch,
    const float* __restrict__ att_src, const float* __restrict__ att_dst,
    float* __restrict__ asrc_o, float* __restrict__ adst_o,
    int att_mode, int M, int Nc, int Kp)
{
    __shared__ unsigned short As[2][128][40];
    __shared__ unsigned short Bs[2][64][40];
    const int t = threadIdx.x;
    const int wid = t >> 5, lane = t & 31;
    const int gid = lane >> 2, tig = lane & 3;
    const int wm = wid & 3, wn = wid >> 2;
    const int m0 = blockIdx.y * 128, n0 = blockIdx.x * 64;
    const int cpp = Kp >> 5;
    const int nch = 3 * cpp;
    const int K3 = 3 * Kp;

    const int lr = lane & 7, lg = lane >> 3;
    const int segA = t & 3, rowA = t >> 2;
    const int nB = t >> 2, ksegB = t & 3;

    float acc[2][4][4];
#pragma unroll
    for (int a = 0; a < 2; a++)
#pragma unroll
        for (int b = 0; b < 4; b++)
#pragma unroll
            for (int c = 0; c < 4; c++) acc[a][b][c] = 0.f;

    auto issue = [&](int cc, int st) {
        int phase = cc / cpp;
        int kloc = (cc - phase * cpp) * 32;
        const unsigned short* Ap = (phase == 1) ? Alo : Ahi;
#pragma unroll
        for (int half = 0; half < 2; half++) {
            int r = rowA + half * 64;
            int m = m0 + r;
            uint32_t d = (uint32_t)__cvta_generic_to_shared(&As[st][r][segA * 8]);
            cpa16(d, Ap + (size_t)m * Kp + kloc + segA * 8, (m < M) ? 16 : 0);
        }
        {
            uint32_t d = (uint32_t)__cvta_generic_to_shared(&Bs[st][nB][ksegB * 8]);
            cpa16(d, BcatT + (size_t)(n0 + nB) * K3 + cc * 32 + ksegB * 8, 16);
        }
        asm volatile("cp.async.commit_group;");
    };

    issue(0, 0);
    for (int cc = 0; cc < nch; cc++) {
        int st = cc & 1;
        if (cc + 1 < nch) {
            issue(cc + 1, st ^ 1);
            asm volatile("cp.async.wait_group 1;");
        } else {
            asm volatile("cp.async.wait_group 0;");
        }
        __syncthreads();
        const uint32_t sA = (uint32_t)__cvta_generic_to_shared(&As[st][0][0]);
        const uint32_t sB = (uint32_t)__cvta_generic_to_shared(&Bs[st][0][0]);
#pragma unroll
        for (int ks = 0; ks < 32; ks += 16) {
            uint32_t af[2][4];
#pragma unroll
            for (int mt = 0; mt < 2; mt++) {
                int row = wm * 32 + mt * 16 + (lg & 1) * 8 + lr;
                int col = ks + (lg >> 1) * 8;
                ldsm_x4(af[mt][0], af[mt][1], af[mt][2], af[mt][3],
                        sA + (uint32_t)(row * 40 + col) * 2u);
            }
            uint32_t bfr[4][2];
#pragma unroll
            for (int p2 = 0; p2 < 2; p2++) {
                int row = wn * 32 + p2 * 16 + (lg >> 1) * 8 + lr;
                int col = ks + (lg & 1) * 8;
                ldsm_x4(bfr[p2 * 2][0], bfr[p2 * 2][1], bfr[p2 * 2 + 1][0], bfr[p2 * 2 + 1][1],
                        sB + (uint32_t)(row * 40 + col) * 2u);
            }
#pragma unroll
            for (int mt = 0; mt < 2; mt++)
#pragma unroll
                for (int nt = 0; nt < 4; nt++)
                    mma16816(acc[mt][nt], af[mt], bfr[nt]);
        }
        __syncthreads();
    }

    if (att_mode) {
        const int cb = (att_mode == 1) ? ((blockIdx.x * 2 + wn) * 32) : (wn * 32);
        float wsv[4][2], wdv[4][2];
#pragma unroll
        for (int nt = 0; nt < 4; nt++) {
            int c = cb + nt * 8 + tig * 2;
            wsv[nt][0] = att_src[c]; wsv[nt][1] = att_src[c + 1];
            wdv[nt][0] = att_dst[c]; wdv[nt][1] = att_dst[c + 1];
        }
#pragma unroll
        for (int mt = 0; mt < 2; mt++) {
            float ps_lo = 0.f, ps_hi = 0.f, pd_lo = 0.f, pd_hi = 0.f;
#pragma unroll
            for (int nt = 0; nt < 4; nt++) {
                ps_lo += acc[mt][nt][0] * wsv[nt][0] + acc[mt][nt][1] * wsv[nt][1];
                ps_hi += acc[mt][nt][2] * wsv[nt][0] + acc[mt][nt][3] * wsv[nt][1];
                pd_lo += acc[mt][nt][0] * wdv[nt][0] + acc[mt][nt][1] * wdv[nt][1];
                pd_hi += acc[mt][nt][2] * wdv[nt][0] + acc[mt][nt][3] * wdv[nt][1];
            }
#pragma unroll
            for (int o = 1; o <= 2; o <<= 1) {
                ps_lo += __shfl_xor_sync(0xffffffffu, ps_lo, o);
                ps_hi += __shfl_xor_sync(0xffffffffu, ps_hi, o);
                pd_lo += __shfl_xor_sync(0xffffffffu, pd_lo, o);
                pd_hi += __shfl_xor_sync(0xffffffffu, pd_hi, o);
            }
            int row = m0 + wm * 32 + mt * 16 + gid;
            if (tig == 0) {
                if (att_mode == 1) {
                    int h = blockIdx.x * 2 + wn;
                    if (row < M)     { asrc_o[row * 8 + h] = ps_lo; adst_o[row * 8 + h] = pd_lo; }
                    if (row + 8 < M) { asrc_o[(row + 8) * 8 + h] = ps_hi; adst_o[(row + 8) * 8 + h] = pd_hi; }
                } else {
                    if (row < M)     { atomicAdd(&asrc_o[row], ps_lo); atomicAdd(&adst_o[row], pd_lo); }
                    if (row + 8 < M) { atomicAdd(&asrc_o[row + 8], ps_hi); atomicAdd(&adst_o[row + 8], pd_hi); }
                }
            }
#pragma unroll
            for (int nt = 0; nt < 4; nt++) {
                int col = n0 + wn * 32 + nt * 8 + tig * 2;
                if (row < M) {
                    uint32_t pk = ((uint32_t)f2h(acc[mt][nt][1]) << 16) | f2h(acc[mt][nt][0]);
                    *(uint32_t*)&Ch[(size_t)row * Nc + col] = pk;
                }
                if (row + 8 < M) {
                    uint32_t pk = ((uint32_t)f2h(acc[mt][nt][3]) << 16) | f2h(acc[mt][nt][2]);
                    *(uint32_t*)&Ch[(size_t)(row + 8) * Nc + col] = pk;
                }
            }
        }
    } else {
#pragma unroll
        for (int mt = 0; mt < 2; mt++) {
#pragma unroll
            for (int nt = 0; nt < 4; nt++) {
                int row = m0 + wm * 32 + mt * 16 + gid;
                int col = n0 + wn * 32 + nt * 8 + tig * 2;
                if (row < M)
                    *(float2*)&C[(size_t)row * Nc + col] = make_float2(acc[mt][nt][0], acc[mt][nt][1]);
                if (row + 8 < M)
                    *(float2*)&C[(size_t)(row + 8) * Nc + col] = make_float2(acc[mt][nt][2], acc[mt][nt][3]);
            }
        }
    }
}

// ---------------- CSR build ---------------------------------------------------
__global__ void k_count(const void* __restrict__ ei, int e, int n) {
    int i = blockIdx.x * blockDim.x + threadIdx.x;
    if (i >= e + n) return;
    int is64 = g_is64;
    int d = (i < e) ? load_idx(ei, (long long)e + i, is64) : (i - e);
    atomicAdd(&g_deg[d], 1);
}

__device__ __forceinline__ int block_incl_scan(int v, int t) {
    __shared__ int ws[8];
    int lane = t & 31, wid = t >> 5;
    int incl = v;
#pragma unroll
    for (int o = 1; o < 32; o <<= 1) {
        int u = __shfl_up_sync(0xffffffffu, incl, o);
        if (lane >= o) incl += u;
    }
    if (lane == 31) ws[wid] = incl;
    __syncthreads();
    if (wid == 0) {
        int w = (lane < 8) ? ws[lane] : 0;
#pragma unroll
        for (int o = 1; o < 8; o <<= 1) {
            int u = __shfl_up_sync(0xffffffffu, w, o);
            if (lane >= o) w += u;
        }
        if (lane < 8) ws[lane] = w;
    }
    __syncthreads();
    return incl + (wid > 0 ? ws[wid - 1] : 0);
}

__global__ void __launch_bounds__(SCAN_B) k_scan_a(int n) {
    int t = threadIdx.x;
    int i = blockIdx.x * SCAN_B + t;
    int v = (i < n) ? g_deg[i] : 0;
    int incl = block_incl_scan(v, t);
    if (i < n) g_rowptr[i] = incl - v;
    if (t == SCAN_B - 1) g_bsum[blockIdx.x] = incl;
}

__global__ void __launch_bounds__(SCAN_B) k_scan_b(int nb, int n) {
    int t = threadIdx.x;
    int v = (t < nb) ? g_bsum[t] : 0;
    int incl = block_incl_scan(v, t);
    if (t < nb) g_boff[t] = incl - v;
    if (t == SCAN_B - 1) g_rowptr[n] = incl;
}

__global__ void __launch_bounds__(SCAN_B) k_scan_c(int n) {
    int i = blockIdx.x * SCAN_B + threadIdx.x;
    if (i < n) {
        int r = g_rowptr[i] + g_boff[blockIdx.x];
        g_rowptr[i] = r;
        g_pos[i] = r;
    }
}

__global__ void k_scatter(const void* __restrict__ ei, int e, int n) {
    int i = blockIdx.x * blockDim.x + threadIdx.x;
    if (i >= e + n) return;
    int is64 = g_is64;
    int s, d;
    if (i < e) { s = load_idx(ei, i, is64); d = load_idx(ei, (long long)e + i, is64); }
    else       { s = i - e;                 d = i - e; }
    int p = atomicAdd(&g_pos[d], 1);
    g_ssrc[p] = s;
}

// ---------------- layer1 agg: unroll-4, fused exp + gather + bias + ELU -------
__global__ void __launch_bounds__(256) k_agg1(const float* __restrict__ bias1) {
    int t = threadIdx.x;
    int u = t & 63;
    int d = blockIdx.x * 4 + (t >> 6);
    int h = u >> 3;
    int r0 = g_rowptr[d], r1 = g_rowptr[d + 1];
    float ad = g_adst1[d * 8 + h];
    const ushort4* Hh = (const ushort4*)g_h1h;
    float4 acc = make_float4(0.f, 0.f, 0.f, 0.f);
    float wsum = 0.f;
    int p = r0;
    for (; p + 4 <= r1; p += 4) {
        int s0 = g_ssrc[p],     s1 = g_ssrc[p + 1];
        int s2 = g_ssrc[p + 2], s3 = g_ssrc[p + 3];
        float a0 = g_asrc1[s0 * 8 + h], a1 = g_asrc1[s1 * 8 + h];
        float a2 = g_asrc1[s2 * 8 + h], a3 = g_asrc1[s3 * 8 + h];
        ushort4 v0 = Hh[s0 * 64 + u];
        ushort4 v1 = Hh[s1 * 64 + u];
        ushort4 v2 = Hh[s2 * 64 + u];
        ushort4 v3 = Hh[s3 * 64 + u];
        float e0 = a0 + ad, e1 = a1 + ad, e2 = a2 + ad, e3 = a3 + ad;
        e0 = e0 > 0.f ? e0 : 0.2f * e0;
        e1 = e1 > 0.f ? e1 : 0.2f * e1;
        e2 = e2 > 0.f ? e2 : 0.2f * e2;
        e3 = e3 > 0.f ? e3 : 0.2f * e3;
        float w0 = __expf(e0), w1 = __expf(e1), w2 = __expf(e2), w3 = __expf(e3);
        acc.x += w0 * h2f(v0.x) + w1 * h2f(v1.x) + w2 * h2f(v2.x) + w3 * h2f(v3.x);
        acc.y += w0 * h2f(v0.y) + w1 * h2f(v1.y) + w2 * h2f(v2.y) + w3 * h2f(v3.y);
        acc.z += w0 * h2f(v0.z) + w1 * h2f(v1.z) + w2 * h2f(v2.z) + w3 * h2f(v3.z);
        acc.w += w0 * h2f(v0.w) + w1 * h2f(v1.w) + w2 * h2f(v2.w) + w3 * h2f(v3.w);
        wsum += (w0 + w1) + (w2 + w3);
    }
    if (p + 2 <= r1) {
        int s0 = g_ssrc[p], s1 = g_ssrc[p + 1];
        float a0 = g_asrc1[s0 * 8 + h], a1 = g_asrc1[s1 * 8 + h];
        ushort4 v0 = Hh[s0 * 64 + u];
        ushort4 v1 = Hh[s1 * 64 + u];
        float e0 = a0 + ad, e1 = a1 + ad;
        e0 = e0 > 0.f ? e0 : 0.2f * e0;
        e1 = e1 > 0.f ? e1 : 0.2f * e1;
        float w0 = __expf(e0), w1 = __expf(e1);
        acc.x += w0 * h2f(v0.x) + w1 * h2f(v1.x);
        acc.y += w0 * h2f(v0.y) + w1 * h2f(v1.y);
        acc.z += w0 * h2f(v0.z) + w1 * h2f(v1.z);
        acc.w += w0 * h2f(v0.w) + w1 * h2f(v1.w);
        wsum += w0 + w1;
        p += 2;
    }
    if (p < r1) {
        int s0 = g_ssrc[p];
        float e0 = g_asrc1[s0 * 8 + h] + ad;
        e0 = e0 > 0.f ? e0 : 0.2f * e0;
        float w0 = __expf(e0);
        ushort4 v0 = Hh[s0 * 64 + u];
        acc.x += w0 * h2f(v0.x); acc.y += w0 * h2f(v0.y);
        acc.z += w0 * h2f(v0.z); acc.w += w0 * h2f(v0.w);
        wsum += w0;
    }
    float sinv = 1.f / (wsum + 1e-16f);
    float4 b = ((const float4*)bias1)[u];
    float4 o;
    o.x = acc.x * sinv + b.x; o.x = o.x > 0.f ? o.x : expm1f(o.x);
    o.y = acc.y * sinv + b.y; o.y = o.y > 0.f ? o.y : expm1f(o.y);
    o.z = acc.z * sinv + b.z; o.z = o.z > 0.f ? o.z : expm1f(o.z);
    o.w = acc.w * sinv + b.w; o.w = o.w > 0.f ? o.w : expm1f(o.w);
    ushort4 hi, lo;
    hi.x = f2bf(o.x); lo.x = f2bf(o.x - bf2f(hi.x));
    hi.y = f2bf(o.y); lo.y = f2bf(o.y - bf2f(hi.y));
    hi.z = f2bf(o.z); lo.z = f2bf(o.z - bf2f(hi.z));
    hi.w = f2bf(o.w); lo.w = f2bf(o.w - bf2f(hi.w));
    ((ushort4*)g_h2hi)[d * 64 + u] = hi;
    ((ushort4*)g_h2lo)[d * 64 + u] = lo;
}

// ---------------- layer2 agg: unroll-4, fused exp + fp16 gather + bias --------
__global__ void __launch_bounds__(256) k_agg2(const float* __restrict__ bias2,
                                              float* __restrict__ out)
{
    int t = threadIdx.x;
    int u = t & 15;
    int d = blockIdx.x * 16 + (t >> 4);
    int r0 = g_rowptr[d], r1 = g_rowptr[d + 1];
    float ad = g_adst2[d];
    const ushort4* Hh = (const ushort4*)g_h2h;
    float4 acc = make_float4(0.f, 0.f, 0.f, 0.f);
    float wsum = 0.f;
    int p = r0;
    for (; p + 4 <= r1; p += 4) {
        int s0 = g_ssrc[p],     s1 = g_ssrc[p + 1];
        int s2 = g_ssrc[p + 2], s3 = g_ssrc[p + 3];
        float a0 = g_asrc2[s0], a1 = g_asrc2[s1];
        float a2 = g_asrc2[s2], a3 = g_asrc2[s3];
        ushort4 v0 = Hh[s0 * 16 + u];
        ushort4 v1 = Hh[s1 * 16 + u];
        ushort4 v2 = Hh[s2 * 16 + u];
        ushort4 v3 = Hh[s3 * 16 + u];
        float e0 = a0 + ad, e1 = a1 + ad, e2 = a2 + ad, e3 = a3 + ad;
        e0 = e0 > 0.f ? e0 : 0.2f * e0;
        e1 = e1 > 0.f ? e1 : 0.2f * e1;
        e2 = e2 > 0.f ? e2 : 0.2f * e2;
        e3 = e3 > 0.f ? e3 : 0.2f * e3;
        float w0 = __expf(e0), w1 = __expf(e1), w2 = __expf(e2), w3 = __expf(e3);
        acc.x += w0 * h2f(v0.x) + w1 * h2f(v1.x) + w2 * h2f(v2.x) + w3 * h2f(v3.x);
        acc.y += w0 * h2f(v0.y) + w1 * h2f(v1.y) + w2 * h2f(v2.y) + w3 * h2f(v3.y);
        acc.z += w0 * h2f(v0.z) + w1 * h2f(v1.z) + w2 * h2f(v2.z) + w3 * h2f(v3.z);
        acc.w += w0 * h2f(v0.w) + w1 * h2f(v1.w) + w2 * h2f(v2.w) + w3 * h2f(v3.w);
        wsum += (w0 + w1) + (w2 + w3);
    }
    if (p + 2 <= r1) {
        int s0 = g_ssrc[p], s1 = g_ssrc[p + 1];
        float a0 = g_asrc2[s0], a1 = g_asrc2[s1];
        ushort4 v0 = Hh[s0 * 16 + u];
        ushort4 v1 = Hh[s1 * 16 + u];
        float e0 = a0 + ad, e1 = a1 + ad;
        e0 = e0 > 0.f ? e0 : 0.2f * e0;
        e1 = e1 > 0.f ? e1 : 0.2f * e1;
        float w0 = __expf(e0), w1 = __expf(e1);
        acc.x += w0 * h2f(v0.x) + w1 * h2f(v1.x);
        acc.y += w0 * h2f(v0.y) + w1 * h2f(v1.y);
        acc.z += w0 * h2f(v0.z) + w1 * h2f(v1.z);
        acc.w += w0 * h2f(v0.w) + w1 * h2f(v1.w);
        wsum += w0 + w1;
        p += 2;
    }
    if (p < r1) {
        int s0 = g_ssrc[p];
        float e0 = g_asrc2[s0] + ad;
        e0 = e0 > 0.f ? e0 : 0.2f * e0;
        float w0 = __expf(e0);
        ushort4 v0 = Hh[s0 * 16 + u];
        acc.x += w0 * h2f(v0.x); acc.y += w0 * h2f(v0.y);
        acc.z += w0 * h2f(v0.z); acc.w += w0 * h2f(v0.w);
        wsum += w0;
    }
    float sinv = 1.f / (wsum + 1e-16f);
    float4 b = ((const float4*)bias2)[u];
    float4 o;
    o.x = acc.x * sinv + b.x;
    o.y = acc.y * sinv + b.y;
    o.z = acc.z * sinv + b.z;
    o.w = acc.w * sinv + b.w;
    ((float4*)out)[d * 16 + u] = o;
}

// ------------------------------------------------------------------------------
extern "C" void kernel_launch(void* const* d_in, const int* in_sizes, int n_in,
                              void* d_out, int out_size)
{
    const float* x   = (const float*)d_in[0];
    const void*  ei  = d_in[1];
    const float* W1  = (const float*)d_in[3];
    const float* as1 = (const float*)d_in[4];
    const float* ad1 = (const float*)d_in[5];
    const float* b1  = (const float*)d_in[6];
    const float* W2  = (const float*)d_in[7];
    const float* as2 = (const float*)d_in[8];
    const float* ad2 = (const float*)d_in[9];
    const float* b2  = (const float*)d_in[10];
    float* out = (float*)d_out;

    const int n  = in_sizes[0] / 128;   // 50000
    const int e  = in_sizes[1] / 2;     // 800000
    const int et = e + n;
    const int nb = (n + SCAN_B - 1) / SCAN_B;

    float *asrc1, *adst1, *asrc2, *adst2;
    unsigned short *h1h, *h2h, *xhi, *xlo, *b1catT, *h2hi, *h2lo, *b2catT;
    cudaGetSymbolAddress((void**)&asrc1,  g_asrc1);
    cudaGetSymbolAddress((void**)&adst1,  g_adst1);
    cudaGetSymbolAddress((void**)&asrc2,  g_asrc2);
    cudaGetSymbolAddress((void**)&adst2,  g_adst2);
    cudaGetSymbolAddress((void**)&h1h,    g_h1h);
    cudaGetSymbolAddress((void**)&h2h,    g_h2h);
    cudaGetSymbolAddress((void**)&xhi,    g_xhi);
    cudaGetSymbolAddress((void**)&xlo,    g_xlo);
    cudaGetSymbolAddress((void**)&b1catT, g_b1catT);
    cudaGetSymbolAddress((void**)&h2hi,   g_h2hi);
    cudaGetSymbolAddress((void**)&h2lo,   g_h2lo);
    cudaGetSymbolAddress((void**)&b2catT, g_b2catT);

    static cudaStream_t s_side = nullptr;
    static cudaEvent_t s_evF = nullptr, s_evJ = nullptr;
    if (!s_side) {
        cudaStreamCreateWithFlags(&s_side, cudaStreamNonBlocking);
        cudaEventCreateWithFlags(&s_evF, cudaEventDisableTiming);
        cudaEventCreateWithFlags(&s_evJ, cudaEventDisableTiming);
    }

    int nf4 = n * 32;

    // tiny prep (zero + detect) then fork CSR chain immediately
    k_prep0<<<(n + 255) / 256, 256>>>((const int*)ei, n);
    cudaEventRecord(s_evF, 0);
    cudaStreamWaitEvent(s_side, s_evF, 0);

    k_count<<<(et + 255) / 256, 256, 0, s_side>>>(ei, e, n);
    k_scan_a<<<nb, SCAN_B, 0, s_side>>>(n);
    k_scan_b<<<1, SCAN_B, 0, s_side>>>(nb, n);
    k_scan_c<<<nb, SCAN_B, 0, s_side>>>(n);
    k_scatter<<<(et + 255) / 256, 256, 0, s_side>>>(ei, e, n);
    cudaEventRecord(s_evJ, s_side);

    // main stream: conversions + layer1 GEMM (+fused att1)
    k_conv<<<(nf4 + 255) / 256, 256>>>(x, W1, W2, nf4);
    k_gemm_bf16<<<dim3(4, (n + 127) / 128), 256>>>(
        xhi, xlo, b1catT, (float*)nullptr, h1h, as1, ad1, asrc1, adst1, 1, n, 256, 128);

    // join: agg1 needs CSR + h1h/logits
    cudaStreamWaitEvent(0, s_evJ, 0);
    k_agg1<<<(n + 3) / 4, 256>>>(b1);

    // layer2 GEMM (+fused att2 via atomics, fp16 h2 only)
    k_gemm_bf16<<<dim3(1, (n + 127) / 128), 256>>>(
        h2hi, h2lo, b2catT, (float*)nullptr, h2h, as2, ad2, asrc2, adst2, 2, n, 64, 256);

    k_agg2<<<(n + 15) / 16, 256>>>(b2, out);
}

// round 16
// speedup vs baseline: 2.7325x; 1.0113x over previous
#include <cuda_runtime.h>
#include <cuda_bf16.h>
#include <cuda_fp16.h>
#include <cstdint>

#define NN 50000
#define NE 800000
#define NET (NN + NE)
#define SCAN_B 256

// ---------------- scratch (static device globals; no allocation) -------------
__device__ float g_asrc1[NN * 8];
__device__ float g_adst1[NN * 8];
__device__ float g_asrc2[NN];
__device__ float g_adst2[NN];
__device__ int   g_deg[NN];
__device__ int   g_rowptr[NN + 1];
__device__ int   g_pos[NN];
__device__ int   g_ssrc[NET];
__device__ int   g_bsum[SCAN_B];
__device__ int   g_boff[SCAN_B];
__device__ int   g_is64;

// half/bf16 operands
__device__ unsigned short g_h1h[NN * 256];      // fp16 h1
__device__ unsigned short g_h2h[NN * 64];       // fp16 h2
__device__ unsigned short g_xhi[NN * 128];
__device__ unsigned short g_xlo[NN * 128];
__device__ unsigned short g_b1catT[256 * 256];  // [n][2K]: hi|lo, K=128
__device__ unsigned short g_h2hi[NN * 256];
__device__ unsigned short g_h2lo[NN * 256];
__device__ unsigned short g_b2catT[64 * 512];   // [n][2K], K=256

__device__ __forceinline__ unsigned short f2bf(float x) {
    __nv_bfloat16 b = __float2bfloat16_rn(x);
    return *(unsigned short*)&b;
}
__device__ __forceinline__ float bf2f(unsigned short u) {
    unsigned int v = ((unsigned int)u) << 16;
    return __uint_as_float(v);
}
__device__ __forceinline__ unsigned short f2h(float x) {
    __half h = __float2half_rn(x);
    return *(unsigned short*)&h;
}
__device__ __forceinline__ float h2f(unsigned short u) {
    __half h = *(__half*)&u;
    return __half2float(h);
}

__device__ __forceinline__ int load_idx(const void* ei, long long pos, int is64) {
    if (is64) return (int)((const long long*)ei)[pos];
    return ((const int*)ei)[pos];
}

// ---------------- prep0: zero + detect (covers n*8 for logit accumulators) ----
__global__ void k_prep0(const int* __restrict__ w, int n) {
    int i = blockIdx.x * blockDim.x + threadIdx.x;
    if (i < n) { g_deg[i] = 0; g_asrc2[i] = 0.f; g_adst2[i] = 0.f; }
    if (i < n * 8) { g_asrc1[i] = 0.f; g_adst1[i] = 0.f; }
    if (i == 0) {
        int all0 = 1;
        for (int j = 1; j < 200; j += 2)
            if (w[j] != 0) { all0 = 0; break; }
        g_is64 = all0;
    }
}

// ---------------- conversions --------------------------------------------------
__global__ void k_conv(const float* __restrict__ x,
                       const float* __restrict__ W1, const float* __restrict__ W2,
                       int nf4)
{
    int i = blockIdx.x * blockDim.x + threadIdx.x;
    if (i < nf4) {
        float4 v = ((const float4*)x)[i];
        ushort4 hi, lo;
        hi.x = f2bf(v.x); lo.x = f2bf(v.x - bf2f(hi.x));
        hi.y = f2bf(v.y); lo.y = f2bf(v.y - bf2f(hi.y));
        hi.z = f2bf(v.z); lo.z = f2bf(v.z - bf2f(hi.z));
        hi.w = f2bf(v.w); lo.w = f2bf(v.w - bf2f(hi.w));
        ((ushort4*)g_xhi)[i] = hi;
        ((ushort4*)g_xlo)[i] = lo;
    }
    if (i < 32768) {
        int k = i >> 8, nn = i & 255;
        float wv = W1[i];
        unsigned short hi = f2bf(wv);
        unsigned short lo = f2bf(wv - bf2f(hi));
        unsigned short* r = &g_b1catT[nn * 256];
        r[k] = hi; r[128 + k] = lo;
    } else if (i < 32768 + 16384) {
        int j = i - 32768;
        int k = j >> 6, nn = j & 63;
        float wv = W2[j];
        unsigned short hi = f2bf(wv);
        unsigned short lo = f2bf(wv - bf2f(hi));
        unsigned short* r = &g_b2catT[nn * 512];
        r[k] = hi; r[256 + k] = lo;
    }
}

// ---------------- bf16 split tensor-core GEMM, k-major (hi/lo resident) -------
// Block 64(M) x 64(N), 8 warps (2x4), warp tile 32x16. Per k-chunk: load
// Ahi/Alo/Bhi/Blo once, run 3 MMA groups (hh, lh, hl). Epilogue: fp16 store +
// attention logits via atomicAdd (att_mode 1: 8 heads of 32 cols; 2: 1 head).
__device__ __forceinline__ void mma16816(float* d, const uint32_t* a, const uint32_t* b) {
    asm volatile(
        "mma.sync.aligned.m16n8k16.row.col.f32.bf16.bf16.f32 "
        "{%0,%1,%2,%3}, {%4,%5,%6,%7}, {%8,%9}, {%0,%1,%2,%3};"
        : "+f"(d[0]), "+f"(d[1]), "+f"(d[2]), "+f"(d[3])
        : "r"(a[0]), "r"(a[1]), "r"(a[2]), "r"(a[3]), "r"(b[0]), "r"(b[1]));
}

__device__ __forceinline__ void ldsm_x4(uint32_t& r0, uint32_t& r1, uint32_t& r2, uint32_t& r3, uint32_t addr) {
    asm volatile("ldmatrix.sync.aligned.m8n8.x4.shared.b16 {%0,%1,%2,%3}, [%4];"
                 : "=r"(r0), "=r"(r1), "=r"(r2), "=r"(r3) : "r"(addr));
}

__device__ __forceinline__ void cpa16(uint32_t dst, const void* src, int srcsz) {
    asm volatile("cp.async.cg.shared.global [%0], [%1], 16, %2;"
                 :: "r"(dst), "l"(src), "r"(srcsz));
}

__global__ void __launch_bounds__(256) k_gemm_bf16(
    const unsigned short* __restrict__ Ahi, const unsigned short* __restrict__ Alo,
    const unsigned short* __restrict__ Bcat2,
    unsigned short* __restrict__ Ch,
    const float* __restrict__ att_src, const float* __restrict__ att_dst,
    float* __restrict__ asrc_o, float* __restrict__ adst_o,
    int att_mode, int M, int Nc, int Kp)
{
    __shared__ unsigned short AsH[2][64][40], AsL[2][64][40];
    __shared__ unsigned short BsH[2][64][40], BsL[2][64][40];
    const int t = threadIdx.x;
    const int wid = t >> 5, lane = t & 31;
    const int gid = lane >> 2, tig = lane & 3;
    const int wm = wid & 1, wn = wid >> 1;      // 2 x 4 warp grid
    const int m0 = blockIdx.y * 64, n0 = blockIdx.x * 64;
    const int nch = Kp >> 5;
    const int K2 = 2 * Kp;

    const int lr = lane & 7, lg = lane >> 3;
    const int rowA = t >> 2, segA = t & 3;
    const int nB = t >> 2, ksegB = t & 3;

    float acc[2][2][4];
#pragma unroll
    for (int a = 0; a < 2; a++)
#pragma unroll
        for (int b = 0; b < 2; b++)
#pragma unroll
            for (int c = 0; c < 4; c++) acc[a][b][c] = 0.f;

    auto issue = [&](int cc, int st) {
        int kloc = cc * 32;
        int m = m0 + rowA;
        int ok = (m < M) ? 16 : 0;
        cpa16((uint32_t)__cvta_generic_to_shared(&AsH[st][rowA][segA * 8]),
              Ahi + (size_t)m * Kp + kloc + segA * 8, ok);
        cpa16((uint32_t)__cvta_generic_to_shared(&AsL[st][rowA][segA * 8]),
              Alo + (size_t)m * Kp + kloc + segA * 8, ok);
        const unsigned short* br = Bcat2 + (size_t)(n0 + nB) * K2;
        cpa16((uint32_t)__cvta_generic_to_shared(&BsH[st][nB][ksegB * 8]),
              br + kloc + ksegB * 8, 16);
        cpa16((uint32_t)__cvta_generic_to_shared(&BsL[st][nB][ksegB * 8]),
              br + Kp + kloc + ksegB * 8, 16);
        asm volatile("cp.async.commit_group;");
    };

    issue(0, 0);
    for (int cc = 0; cc < nch; cc++) {
        int st = cc & 1;
        if (cc + 1 < nch) {
            issue(cc + 1, st ^ 1);
            asm volatile("cp.async.wait_group 1;");
        } else {
            asm volatile("cp.async.wait_group 0;");
        }
        __syncthreads();
        const uint32_t sAH = (uint32_t)__cvta_generic_to_shared(&AsH[st][0][0]);
        const uint32_t sAL = (uint32_t)__cvta_generic_to_shared(&AsL[st][0][0]);
        const uint32_t sBH = (uint32_t)__cvta_generic_to_shared(&BsH[st][0][0]);
        const uint32_t sBL = (uint32_t)__cvta_generic_to_shared(&BsL[st][0][0]);
#pragma unroll
        for (int ks = 0; ks < 32; ks += 16) {
            uint32_t ah[2][4], al[2][4];
#pragma unroll
            for (int mt = 0; mt < 2; mt++) {
                uint32_t off = (uint32_t)((wm * 32 + mt * 16 + (lg & 1) * 8 + lr) * 40
                                          + ks + (lg >> 1) * 8) * 2u;
                ldsm_x4(ah[mt][0], ah[mt][1], ah[mt][2], ah[mt][3], sAH + off);
                ldsm_x4(al[mt][0], al[mt][1], al[mt][2], al[mt][3], sAL + off);
            }
            uint32_t bh[2][2], bl[2][2];
            {
                uint32_t off = (uint32_t)((wn * 16 + (lg >> 1) * 8 + lr) * 40
                                          + ks + (lg & 1) * 8) * 2u;
                ldsm_x4(bh[0][0], bh[0][1], bh[1][0], bh[1][1], sBH + off);
                ldsm_x4(bl[0][0], bl[0][1], bl[1][0], bl[1][1], sBL + off);
            }
#pragma unroll
            for (int mt = 0; mt < 2; mt++)
#pragma unroll
                for (int nt = 0; nt < 2; nt++) {
                    mma16816(acc[mt][nt], ah[mt], bh[nt]);
                    mma16816(acc[mt][nt], al[mt], bh[nt]);
                    mma16816(acc[mt][nt], ah[mt], bl[nt]);
                }
        }
        __syncthreads();
    }

    // epilogue: fp16 store + fused attention logits (atomicAdd)
    float wsv[2][2], wdv[2][2];
#pragma unroll
    for (int nt = 0; nt < 2; nt++) {
        int c = n0 + wn * 16 + nt * 8 + tig * 2;
        wsv[nt][0] = att_src[c]; wsv[nt][1] = att_src[c + 1];
        wdv[nt][0] = att_dst[c]; wdv[nt][1] = att_dst[c + 1];
    }
    const int hidx = (att_mode == 1) ? ((n0 + wn * 16) >> 5) : 0;
#pragma unroll
    for (int mt = 0; mt < 2; mt++) {
        float ps_lo = 0.f, ps_hi = 0.f, pd_lo = 0.f, pd_hi = 0.f;
#pragma unroll
        for (int nt = 0; nt < 2; nt++) {
            ps_lo += acc[mt][nt][0] * wsv[nt][0] + acc[mt][nt][1] * wsv[nt][1];
            ps_hi += acc[mt][nt][2] * wsv[nt][0] + acc[mt][nt][3] * wsv[nt][1];
            pd_lo += acc[mt][nt][0] * wdv[nt][0] + acc[mt][nt][1] * wdv[nt][1];
            pd_hi += acc[mt][nt][2] * wdv[nt][0] + acc[mt][nt][3] * wdv[nt][1];
        }
#pragma unroll
        for (int o = 1; o <= 2; o <<= 1) {
            ps_lo += __shfl_xor_sync(0xffffffffu, ps_lo, o);
            ps_hi += __shfl_xor_sync(0xffffffffu, ps_hi, o);
            pd_lo += __shfl_xor_sync(0xffffffffu, pd_lo, o);
            pd_hi += __shfl_xor_sync(0xffffffffu, pd_hi, o);
        }
        int row = m0 + wm * 32 + mt * 16 + gid;
        if (tig == 0) {
            if (att_mode == 1) {
                if (row < M)     { atomicAdd(&asrc_o[row * 8 + hidx], ps_lo); atomicAdd(&adst_o[row * 8 + hidx], pd_lo); }
                if (row + 8 < M) { atomicAdd(&asrc_o[(row + 8) * 8 + hidx], ps_hi); atomicAdd(&adst_o[(row + 8) * 8 + hidx], pd_hi); }
            } else {
                if (row < M)     { atomicAdd(&asrc_o[row], ps_lo); atomicAdd(&adst_o[row], pd_lo); }
                if (row + 8 < M) { atomicAdd(&asrc_o[row + 8], ps_hi); atomicAdd(&adst_o[row + 8], pd_hi); }
            }
        }
#pragma unroll
        for (int nt = 0; nt < 2; nt++) {
            int col = n0 + wn * 16 + nt * 8 + tig * 2;
            if (row < M) {
                uint32_t pk = ((uint32_t)f2h(acc[mt][nt][1]) << 16) | f2h(acc[mt][nt][0]);
                *(uint32_t*)&Ch[(size_t)row * Nc + col] = pk;
            }
            if (row + 8 < M) {
                uint32_t pk = ((uint32_t)f2h(acc[mt][nt][3]) << 16) | f2h(acc[mt][nt][2]);
                *(uint32_t*)&Ch[(size_t)(row + 8) * Nc + col] = pk;
            }
        }
    }
}

// ---------------- CSR build ---------------------------------------------------
__global__ void k_count(const void* __restrict__ ei, int e, int n) {
    int i = blockIdx.x * blockDim.x + threadIdx.x;
    if (i >= e + n) return;
    int is64 = g_is64;
    int d = (i < e) ? load_idx(ei, (long long)e + i, is64) : (i - e);
    atomicAdd(&g_deg[d], 1);
}

__device__ __forceinline__ int block_incl_scan(int v, int t) {
    __shared__ int ws[8];
    int lane = t & 31, wid = t >> 5;
    int incl = v;
#pragma unroll
    for (int o = 1; o < 32; o <<= 1) {
        int u = __shfl_up_sync(0xffffffffu, incl, o);
        if (lane >= o) incl += u;
    }
    if (lane == 31) ws[wid] = incl;
    __syncthreads();
    if (wid == 0) {
        int w = (lane < 8) ? ws[lane] : 0;
#pragma unroll
        for (int o = 1; o < 8; o <<= 1) {
            int u = __shfl_up_sync(0xffffffffu, w, o);
            if (lane >= o) w += u;
        }
        if (lane < 8) ws[lane] = w;
    }
    __syncthreads();
    return incl + (wid > 0 ? ws[wid - 1] : 0);
}

__global__ void __launch_bounds__(SCAN_B) k_scan_a(int n) {
    int t = threadIdx.x;
    int i = blockIdx.x * SCAN_B + t;
    int v = (i < n) ? g_deg[i] : 0;
    int incl = block_incl_scan(v, t);
    if (i < n) g_rowptr[i] = incl - v;
    if (t == SCAN_B - 1) g_bsum[blockIdx.x] = incl;
}

__global__ void __launch_bounds__(SCAN_B) k_scan_b(int nb, int n) {
    int t = threadIdx.x;
    int v = (t < nb) ? g_bsum[t] : 0;
    int incl = block_incl_scan(v, t);
    if (t < nb) g_boff[t] = incl - v;
    if (t == SCAN_B - 1) g_rowptr[n] = incl;
}

__global__ void __launch_bounds__(SCAN_B) k_scan_c(int n) {
    int i = blockIdx.x * SCAN_B + threadIdx.x;
    if (i < n) {
        int r = g_rowptr[i] + g_boff[blockIdx.x];
        g_rowptr[i] = r;
        g_pos[i] = r;
    }
}

__global__ void k_scatter(const void* __restrict__ ei, int e, int n) {
    int i = blockIdx.x * blockDim.x + threadIdx.x;
    if (i >= e + n) return;
    int is64 = g_is64;
    int s, d;
    if (i < e) { s = load_idx(ei, i, is64); d = load_idx(ei, (long long)e + i, is64); }
    else       { s = i - e;                 d = i - e; }
    int p = atomicAdd(&g_pos[d], 1);
    g_ssrc[p] = s;
}

// ---------------- layer1 agg: unroll-4, fused exp + gather + bias + ELU -------
__global__ void __launch_bounds__(256) k_agg1(const float* __restrict__ bias1) {
    int t = threadIdx.x;
    int u = t & 63;
    int d = blockIdx.x * 4 + (t >> 6);
    int h = u >> 3;
    int r0 = g_rowptr[d], r1 = g_rowptr[d + 1];
    float ad = g_adst1[d * 8 + h];
    const ushort4* Hh = (const ushort4*)g_h1h;
    float4 acc = make_float4(0.f, 0.f, 0.f, 0.f);
    float wsum = 0.f;
    int p = r0;
    for (; p + 4 <= r1; p += 4) {
        int s0 = g_ssrc[p],     s1 = g_ssrc[p + 1];
        int s2 = g_ssrc[p + 2], s3 = g_ssrc[p + 3];
        float a0 = g_asrc1[s0 * 8 + h], a1 = g_asrc1[s1 * 8 + h];
        float a2 = g_asrc1[s2 * 8 + h], a3 = g_asrc1[s3 * 8 + h];
        ushort4 v0 = Hh[s0 * 64 + u];
        ushort4 v1 = Hh[s1 * 64 + u];
        ushort4 v2 = Hh[s2 * 64 + u];
        ushort4 v3 = Hh[s3 * 64 + u];
        float e0 = a0 + ad, e1 = a1 + ad, e2 = a2 + ad, e3 = a3 + ad;
        e0 = e0 > 0.f ? e0 : 0.2f * e0;
        e1 = e1 > 0.f ? e1 : 0.2f * e1;
        e2 = e2 > 0.f ? e2 : 0.2f * e2;
        e3 = e3 > 0.f ? e3 : 0.2f * e3;
        float w0 = __expf(e0), w1 = __expf(e1), w2 = __expf(e2), w3 = __expf(e3);
        acc.x += w0 * h2f(v0.x) + w1 * h2f(v1.x) + w2 * h2f(v2.x) + w3 * h2f(v3.x);
        acc.y += w0 * h2f(v0.y) + w1 * h2f(v1.y) + w2 * h2f(v2.y) + w3 * h2f(v3.y);
        acc.z += w0 * h2f(v0.z) + w1 * h2f(v1.z) + w2 * h2f(v2.z) + w3 * h2f(v3.z);
        acc.w += w0 * h2f(v0.w) + w1 * h2f(v1.w) + w2 * h2f(v2.w) + w3 * h2f(v3.w);
        wsum += (w0 + w1) + (w2 + w3);
    }
    if (p + 2 <= r1) {
        int s0 = g_ssrc[p], s1 = g_ssrc[p + 1];
        float a0 = g_asrc1[s0 * 8 + h], a1 = g_asrc1[s1 * 8 + h];
        ushort4 v0 = Hh[s0 * 64 + u];
        ushort4 v1 = Hh[s1 * 64 + u];
        float e0 = a0 + ad, e1 = a1 + ad;
        e0 = e0 > 0.f ? e0 : 0.2f * e0;
        e1 = e1 > 0.f ? e1 : 0.2f * e1;
        float w0 = __expf(e0), w1 = __expf(e1);
        acc.x += w0 * h2f(v0.x) + w1 * h2f(v1.x);
        acc.y += w0 * h2f(v0.y) + w1 * h2f(v1.y);
        acc.z += w0 * h2f(v0.z) + w1 * h2f(v1.z);
        acc.w += w0 * h2f(v0.w) + w1 * h2f(v1.w);
        wsum += w0 + w1;
        p += 2;
    }
    if (p < r1) {
        int s0 = g_ssrc[p];
        float e0 = g_asrc1[s0 * 8 + h] + ad;
        e0 = e0 > 0.f ? e0 : 0.2f * e0;
        float w0 = __expf(e0);
        ushort4 v0 = Hh[s0 * 64 + u];
        acc.x += w0 * h2f(v0.x); acc.y += w0 * h2f(v0.y);
        acc.z += w0 * h2f(v0.z); acc.w += w0 * h2f(v0.w);
        wsum += w0;
    }
    float sinv = 1.f / (wsum + 1e-16f);
    float4 b = ((const float4*)bias1)[u];
    float4 o;
    o.x = acc.x * sinv + b.x; o.x = o.x > 0.f ? o.x : expm1f(o.x);
    o.y = acc.y * sinv + b.y; o.y = o.y > 0.f ? o.y : expm1f(o.y);
    o.z = acc.z * sinv + b.z; o.z = o.z > 0.f ? o.z : expm1f(o.z);
    o.w = acc.w * sinv + b.w; o.w = o.w > 0.f ? o.w : expm1f(o.w);
    ushort4 hi, lo;
    hi.x = f2bf(o.x); lo.x = f2bf(o.x - bf2f(hi.x));
    hi.y = f2bf(o.y); lo.y = f2bf(o.y - bf2f(hi.y));
    hi.z = f2bf(o.z); lo.z = f2bf(o.z - bf2f(hi.z));
    hi.w = f2bf(o.w); lo.w = f2bf(o.w - bf2f(hi.w));
    ((ushort4*)g_h2hi)[d * 64 + u] = hi;
    ((ushort4*)g_h2lo)[d * 64 + u] = lo;
}

// ---------------- layer2 agg: unroll-4, fused exp + fp16 gather + bias --------
__global__ void __launch_bounds__(256) k_agg2(const float* __restrict__ bias2,
                                              float* __restrict__ out)
{
    int t = threadIdx.x;
    int u = t & 15;
    int d = blockIdx.x * 16 + (t >> 4);
    int r0 = g_rowptr[d], r1 = g_rowptr[d + 1];
    float ad = g_adst2[d];
    const ushort4* Hh = (const ushort4*)g_h2h;
    float4 acc = make_float4(0.f, 0.f, 0.f, 0.f);
    float wsum = 0.f;
    int p = r0;
    for (; p + 4 <= r1; p += 4) {
        int s0 = g_ssrc[p],     s1 = g_ssrc[p + 1];
        int s2 = g_ssrc[p + 2], s3 = g_ssrc[p + 3];
        float a0 = g_asrc2[s0], a1 = g_asrc2[s1];
        float a2 = g_asrc2[s2], a3 = g_asrc2[s3];
        ushort4 v0 = Hh[s0 * 16 + u];
        ushort4 v1 = Hh[s1 * 16 + u];
        ushort4 v2 = Hh[s2 * 16 + u];
        ushort4 v3 = Hh[s3 * 16 + u];
        float e0 = a0 + ad, e1 = a1 + ad, e2 = a2 + ad, e3 = a3 + ad;
        e0 = e0 > 0.f ? e0 : 0.2f * e0;
        e1 = e1 > 0.f ? e1 : 0.2f * e1;
        e2 = e2 > 0.f ? e2 : 0.2f * e2;
        e3 = e3 > 0.f ? e3 : 0.2f * e3;
        float w0 = __expf(e0), w1 = __expf(e1), w2 = __expf(e2), w3 = __expf(e3);
        acc.x += w0 * h2f(v0.x) + w1 * h2f(v1.x) + w2 * h2f(v2.x) + w3 * h2f(v3.x);
        acc.y += w0 * h2f(v0.y) + w1 * h2f(v1.y) + w2 * h2f(v2.y) + w3 * h2f(v3.y);
        acc.z += w0 * h2f(v0.z) + w1 * h2f(v1.z) + w2 * h2f(v2.z) + w3 * h2f(v3.z);
        acc.w += w0 * h2f(v0.w) + w1 * h2f(v1.w) + w2 * h2f(v2.w) + w3 * h2f(v3.w);
        wsum += (w0 + w1) + (w2 + w3);
    }
    if (p + 2 <= r1) {
        int s0 = g_ssrc[p], s1 = g_ssrc[p + 1];
        float a0 = g_asrc2[s0], a1 = g_asrc2[s1];
        ushort4 v0 = Hh[s0 * 16 + u];
        ushort4 v1 = Hh[s1 * 16 + u];
        float e0 = a0 + ad, e1 = a1 + ad;
        e0 = e0 > 0.f ? e0 : 0.2f * e0;
        e1 = e1 > 0.f ? e1 : 0.2f * e1;
        float w0 = __expf(e0), w1 = __expf(e1);
        acc.x += w0 * h2f(v0.x) + w1 * h2f(v1.x);
        acc.y += w0 * h2f(v0.y) + w1 * h2f(v1.y);
        acc.z += w0 * h2f(v0.z) + w1 * h2f(v1.z);
        acc.w += w0 * h2f(v0.w) + w1 * h2f(v1.w);
        wsum += w0 + w1;
        p += 2;
    }
    if (p < r1) {
        int s0 = g_ssrc[p];
        float e0 = g_asrc2[s0] + ad;
        e0 = e0 > 0.f ? e0 : 0.2f * e0;
        float w0 = __expf(e0);
        ushort4 v0 = Hh[s0 * 16 + u];
        acc.x += w0 * h2f(v0.x); acc.y += w0 * h2f(v0.y);
        acc.z += w0 * h2f(v0.z); acc.w += w0 * h2f(v0.w);
        wsum += w0;
    }
    float sinv = 1.f / (wsum + 1e-16f);
    float4 b = ((const float4*)bias2)[u];
    float4 o;
    o.x = acc.x * sinv + b.x;
    o.y = acc.y * sinv + b.y;
    o.z = acc.z * sinv + b.z;
    o.w = acc.w * sinv + b.w;
    ((float4*)out)[d * 16 + u] = o;
}

// ------------------------------------------------------------------------------
extern "C" void kernel_launch(void* const* d_in, const int* in_sizes, int n_in,
                              void* d_out, int out_size)
{
    const float* x   = (const float*)d_in[0];
    const void*  ei  = d_in[1];
    const float* W1  = (const float*)d_in[3];
    const float* as1 = (const float*)d_in[4];
    const float* ad1 = (const float*)d_in[5];
    const float* b1  = (const float*)d_in[6];
    const float* W2  = (const float*)d_in[7];
    const float* as2 = (const float*)d_in[8];
    const float* ad2 = (const float*)d_in[9];
    const float* b2  = (const float*)d_in[10];
    float* out = (float*)d_out;

    const int n  = in_sizes[0] / 128;   // 50000
    const int e  = in_sizes[1] / 2;     // 800000
    const int et = e + n;
    const int nb = (n + SCAN_B - 1) / SCAN_B;

    float *asrc1, *adst1, *asrc2, *adst2;
    unsigned short *h1h, *h2h, *xhi, *xlo, *b1catT, *h2hi, *h2lo, *b2catT;
    cudaGetSymbolAddress((void**)&asrc1,  g_asrc1);
    cudaGetSymbolAddress((void**)&adst1,  g_adst1);
    cudaGetSymbolAddress((void**)&asrc2,  g_asrc2);
    cudaGetSymbolAddress((void**)&adst2,  g_adst2);
    cudaGetSymbolAddress((void**)&h1h,    g_h1h);
    cudaGetSymbolAddress((void**)&h2h,    g_h2h);
    cudaGetSymbolAddress((void**)&xhi,    g_xhi);
    cudaGetSymbolAddress((void**)&xlo,    g_xlo);
    cudaGetSymbolAddress((void**)&b1catT, g_b1catT);
    cudaGetSymbolAddress((void**)&h2hi,   g_h2hi);
    cudaGetSymbolAddress((void**)&h2lo,   g_h2lo);
    cudaGetSymbolAddress((void**)&b2catT, g_b2catT);

    static cudaStream_t s_side = nullptr;
    static cudaEvent_t s_evF = nullptr, s_evJ = nullptr;
    if (!s_side) {
        cudaStreamCreateWithFlags(&s_side, cudaStreamNonBlocking);
        cudaEventCreateWithFlags(&s_evF, cudaEventDisableTiming);
        cudaEventCreateWithFlags(&s_evJ, cudaEventDisableTiming);
    }

    int nf4 = n * 32;

    // tiny prep (zero + detect) then fork CSR chain immediately
    k_prep0<<<(n * 8 + 255) / 256, 256>>>((const int*)ei, n);
    cudaEventRecord(s_evF, 0);
    cudaStreamWaitEvent(s_side, s_evF, 0);

    k_count<<<(et + 255) / 256, 256, 0, s_side>>>(ei, e, n);
    k_scan_a<<<nb, SCAN_B, 0, s_side>>>(n);
    k_scan_b<<<1, SCAN_B, 0, s_side>>>(nb, n);
    k_scan_c<<<nb, SCAN_B, 0, s_side>>>(n);
    k_scatter<<<(et + 255) / 256, 256, 0, s_side>>>(ei, e, n);
    cudaEventRecord(s_evJ, s_side);

    // main stream: conversions + layer1 GEMM (+fused att1)
    k_conv<<<(nf4 + 255) / 256, 256>>>(x, W1, W2, nf4);
    k_gemm_bf16<<<dim3(4, (n + 63) / 64), 256>>>(
        xhi, xlo, b1catT, h1h, as1, ad1, asrc1, adst1, 1, n, 256, 128);

    // join: agg1 needs CSR + h1h/logits
    cudaStreamWaitEvent(0, s_evJ, 0);
    k_agg1<<<(n + 3) / 4, 256>>>(b1);

    // layer2 GEMM (+fused att2 via atomics, fp16 h2 only)
    k_gemm_bf16<<<dim3(1, (n + 63) / 64), 256>>>(
        h2hi, h2lo, b2catT, h2h, as2, ad2, asrc2, adst2, 2, n, 64, 256);

    k_agg2<<<(n + 15) / 16, 256>>>(b2, out);
}